// round 12
// baseline (speedup 1.0000x reference)
#include <cuda_runtime.h>
#include <math.h>
#include <stdint.h>

#define BATCH   2
#define SEQ     4096
#define DMODEL  512
#define NH      8
#define HD      64
#define NC      128
#define NS      64
#define TOPK    16
#define NROWS   (BATCH*SEQ)

// ---------------- scratch ----------------
__device__ float d_Q[NROWS*DMODEL];
__device__ float d_K[NROWS*DMODEL];
__device__ float d_V[NROWS*DMODEL];
__device__ float d_O[NROWS*DMODEL];
__device__ float d_KC[BATCH*NH*NC*HD];
__device__ float d_VC[BATCH*NH*NC*HD];
__device__ float d_G[NROWS*3];
__device__ int   d_SEL[BATCH*NH*NS*TOPK];

// ---------------- tf32 helpers ----------------
__device__ __forceinline__ float ftf(float x) {
    uint32_t u;
    asm("cvt.rna.tf32.f32 %0, %1;" : "=r"(u) : "f"(x));
    return __uint_as_float(u);
}
__device__ __forceinline__ float4 ftf4(float4 v) {
    return make_float4(ftf(v.x), ftf(v.y), ftf(v.z), ftf(v.w));
}
__device__ __forceinline__ float ex2(float x) {
    float r;
    asm("ex2.approx.ftz.f32 %0, %1;" : "=f"(r) : "f"(x));
    return r;
}
__device__ __forceinline__ void mma_tf32(float* c, const uint32_t* a, const uint32_t* b) {
    asm volatile(
        "mma.sync.aligned.m16n8k8.row.col.f32.tf32.tf32.f32 "
        "{%0,%1,%2,%3},{%4,%5,%6,%7},{%8,%9},{%0,%1,%2,%3};\n"
        : "+f"(c[0]), "+f"(c[1]), "+f"(c[2]), "+f"(c[3])
        : "r"(a[0]), "r"(a[1]), "r"(a[2]), "r"(a[3]), "r"(b[0]), "r"(b[1]));
}
__device__ __forceinline__ void split_tf32(float x, uint32_t& hi, uint32_t& lo) {
    float h = ftf(x);
    hi = __float_as_uint(h);
    lo = __float_as_uint(ftf(x - h));
}
#define U(x) __float_as_uint(x)
#define QSCALE 0.18033688011112042f   /* 0.125 * log2(e) */

// ---------------- tf32 GEMM: 128x128 tile, k-slab 32, smem double buffer --
#define GPA 36
#define GPB 136
__global__ __launch_bounds__(256) void gemm512_tc(const float* __restrict__ Aext,
    const float* __restrict__ B0, const float* __restrict__ B1,
    const float* __restrict__ B2, float* __restrict__ Cext, int modeBase)
{
    extern __shared__ float smg[];
    float* As = smg;
    float* Bs = smg + 2 * 128 * GPA;

    int mode = modeBase + blockIdx.z;
    const float* A  = (mode == 3) ? d_O : Aext;
    const float* Bm = (mode == 1) ? B1 : (mode == 2) ? B2 : B0;
    float* C = (mode == 0) ? d_Q : (mode == 1) ? d_K : (mode == 2) ? d_V : Cext;

    int tid = threadIdx.x, lane = tid & 31, w = tid >> 5;
    int grp = lane >> 2, t4 = lane & 3;
    int wm = w & 3, wn = w >> 2;
    int m0 = blockIdx.y * 128, n0 = blockIdx.x * 128;

    int arr[4], arc[4], brr[4], brc[4];
#pragma unroll
    for (int ii = 0; ii < 4; ii++) {
        int i = tid + ii * 256;
        arr[ii] = i >> 3;  arc[ii] = (i & 7) * 4;
        brr[ii] = i >> 5;  brc[ii] = (i & 31) * 4;
    }

    float acc[2][8][4];
#pragma unroll
    for (int mt = 0; mt < 2; mt++)
#pragma unroll
        for (int nt = 0; nt < 8; nt++)
#pragma unroll
            for (int r = 0; r < 4; r++) acc[mt][nt][r] = 0.f;

    float4 areg[4], breg[4];
#pragma unroll
    for (int ii = 0; ii < 4; ii++) {
        areg[ii] = *(const float4*)(A + (size_t)(m0 + arr[ii]) * 512 + arc[ii]);
        breg[ii] = *(const float4*)(Bm + (size_t)brr[ii] * 512 + n0 + brc[ii]);
    }
#pragma unroll
    for (int ii = 0; ii < 4; ii++) {
        *(float4*)(&As[arr[ii] * GPA + arc[ii]]) = ftf4(areg[ii]);
        *(float4*)(&Bs[brr[ii] * GPB + brc[ii]]) = ftf4(breg[ii]);
    }
    __syncthreads();

    for (int s = 0; s < 16; s++) {
        float* Ab = As + (s & 1) * 128 * GPA;
        float* Bb = Bs + (s & 1) * 32 * GPB;
        if (s < 15) {
            int k0 = (s + 1) * 32;
#pragma unroll
            for (int ii = 0; ii < 4; ii++) {
                areg[ii] = *(const float4*)(A + (size_t)(m0 + arr[ii]) * 512 + k0 + arc[ii]);
                breg[ii] = *(const float4*)(Bm + (size_t)(k0 + brr[ii]) * 512 + n0 + brc[ii]);
            }
        }
#pragma unroll
        for (int ks = 0; ks < 4; ks++) {
            int kb = ks * 8;
            uint32_t af[2][4], bf[8][2];
#pragma unroll
            for (int mt = 0; mt < 2; mt++) {
                int row = wm * 32 + mt * 16 + grp;
                af[mt][0] = U(Ab[row * GPA + kb + t4]);
                af[mt][1] = U(Ab[(row + 8) * GPA + kb + t4]);
                af[mt][2] = U(Ab[row * GPA + kb + t4 + 4]);
                af[mt][3] = U(Ab[(row + 8) * GPA + kb + t4 + 4]);
            }
#pragma unroll
            for (int nt = 0; nt < 8; nt++) {
                int col = wn * 64 + nt * 8 + grp;
                bf[nt][0] = U(Bb[(kb + t4) * GPB + col]);
                bf[nt][1] = U(Bb[(kb + t4 + 4) * GPB + col]);
            }
#pragma unroll
            for (int mt = 0; mt < 2; mt++)
#pragma unroll
                for (int nt = 0; nt < 8; nt++)
                    mma_tf32(acc[mt][nt], af[mt], bf[nt]);
        }
        if (s < 15) {
            float* An = As + ((s + 1) & 1) * 128 * GPA;
            float* Bn = Bs + ((s + 1) & 1) * 32 * GPB;
#pragma unroll
            for (int ii = 0; ii < 4; ii++) {
                *(float4*)(&An[arr[ii] * GPA + arc[ii]]) = ftf4(areg[ii]);
                *(float4*)(&Bn[brr[ii] * GPB + brc[ii]]) = ftf4(breg[ii]);
            }
        }
        __syncthreads();
    }
#pragma unroll
    for (int mt = 0; mt < 2; mt++)
#pragma unroll
        for (int nt = 0; nt < 8; nt++) {
            int row = m0 + wm * 32 + mt * 16 + grp;
            int col = n0 + wn * 64 + nt * 8 + 2 * t4;
            *(float2*)(C + (size_t)row * 512 + col) =
                make_float2(acc[mt][nt][0], acc[mt][nt][1]);
            *(float2*)(C + (size_t)(row + 8) * 512 + col) =
                make_float2(acc[mt][nt][2], acc[mt][nt][3]);
        }
}

// ---------------- fused gate + compress (one launch) ----------------
__global__ __launch_bounds__(256) void gate_compress(const float* __restrict__ x,
                                                     const float* __restrict__ Wg)
{
    int blk = blockIdx.x;
    if (blk < 1024) {
        // gate: warp per row
        int w = threadIdx.x >> 5, lane = threadIdx.x & 31;
        int row = blk * 8 + w;
        float p0 = 0, p1 = 0, p2 = 0;
#pragma unroll
        for (int c = 0; c < 4; c++) {
            int d = c * 128 + lane * 4;
            float4 xv = *(const float4*)(x + (size_t)row * 512 + d);
            p0 += xv.x * Wg[d * 3]     + xv.y * Wg[d * 3 + 3] +
                  xv.z * Wg[d * 3 + 6] + xv.w * Wg[d * 3 + 9];
            p1 += xv.x * Wg[d * 3 + 1] + xv.y * Wg[d * 3 + 4] +
                  xv.z * Wg[d * 3 + 7] + xv.w * Wg[d * 3 + 10];
            p2 += xv.x * Wg[d * 3 + 2] + xv.y * Wg[d * 3 + 5] +
                  xv.z * Wg[d * 3 + 8] + xv.w * Wg[d * 3 + 11];
        }
#pragma unroll
        for (int o = 16; o; o >>= 1) {
            p0 += __shfl_xor_sync(0xffffffffu, p0, o);
            p1 += __shfl_xor_sync(0xffffffffu, p1, o);
            p2 += __shfl_xor_sync(0xffffffffu, p2, o);
        }
        if (lane == 0) {
            d_G[row * 3 + 0] = 1.f / (1.f + expf(-p0));
            d_G[row * 3 + 1] = 1.f / (1.f + expf(-p1));
            d_G[row * 3 + 2] = 1.f / (1.f + expf(-p2));
        }
    } else {
        // compress
        int idx = (blk - 1024) * 256 + threadIdx.x;
        int d = idx & 63, n = (idx >> 6) & 127, h = (idx >> 13) & 7, b = idx >> 16;
        const float* kp = d_K + (size_t)(b * SEQ + n * 32) * 512 + h * 64 + d;
        const float* vp = d_V + (size_t)(b * SEQ + n * 32) * 512 + h * 64 + d;
        float ks = 0, vs = 0;
#pragma unroll
        for (int r = 0; r < 32; r++) { ks += kp[r * 512]; vs += vp[r * 512]; }
        d_KC[idx] = ks * (1.f / 32.f);
        d_VC[idx] = vs * (1.f / 32.f);
    }
}

// ---------------- compressed attention + top-k (R7 proven: 3xTF32 QK) -----
#define CQ 68
#define CK 72
#define CS 132
__global__ __launch_bounds__(256) void cmp_attn_mma()
{
    extern __shared__ float sm[];
    float* qs   = sm;
    float* kv   = qs + 64 * CQ;
    float* ps   = kv + 128 * CK;
    float* redm = ps + 64 * CS;
    float* reds = redm + 256;
    float* impb = reds + 256;

    int g = blockIdx.x, h = blockIdx.y, b = blockIdx.z;
    int tid = threadIdx.x, lane = tid & 31, w = tid >> 5;
    int grp = lane >> 2, t4 = lane & 3;
    int wm = w & 1, wn = w >> 1;
    int qbase = g * 64;

    for (int i = tid; i < 1024; i += 256) {
        int r = i >> 4, d4 = (i & 15) * 4;
        float4 v = *(const float4*)(d_Q + (size_t)(b * SEQ + qbase + r) * 512 + h * 64 + d4);
        *(float4*)(&qs[r * CQ + d4]) = v;
    }
    int cbase = ((b * NH + h) * NC) * HD;
    for (int i = tid; i < 2048; i += 256) {
        int r = i >> 4, d4 = (i & 15) * 4;
        float4 v = *(const float4*)(d_KC + cbase + r * 64 + d4);
        *(float4*)(&kv[r * CK + d4]) = v;
    }
    __syncthreads();

    float s[2][4][4];
#pragma unroll
    for (int mt = 0; mt < 2; mt++)
#pragma unroll
        for (int nt = 0; nt < 4; nt++)
#pragma unroll
            for (int r = 0; r < 4; r++) s[mt][nt][r] = 0.f;
#pragma unroll
    for (int ks = 0; ks < 8; ks++) {
        int kk = ks * 8;
        uint32_t ah[2][4], al[2][4], bh[4][2], bl[4][2];
#pragma unroll
        for (int mt = 0; mt < 2; mt++) {
            int row = wm * 32 + mt * 16 + grp;
            split_tf32(qs[row * CQ + kk + t4],           ah[mt][0], al[mt][0]);
            split_tf32(qs[(row + 8) * CQ + kk + t4],     ah[mt][1], al[mt][1]);
            split_tf32(qs[row * CQ + kk + t4 + 4],       ah[mt][2], al[mt][2]);
            split_tf32(qs[(row + 8) * CQ + kk + t4 + 4], ah[mt][3], al[mt][3]);
        }
#pragma unroll
        for (int nt = 0; nt < 4; nt++) {
            int key = wn * 32 + nt * 8 + grp;
            split_tf32(kv[key * CK + kk + t4],     bh[nt][0], bl[nt][0]);
            split_tf32(kv[key * CK + kk + t4 + 4], bh[nt][1], bl[nt][1]);
        }
#pragma unroll
        for (int mt = 0; mt < 2; mt++)
#pragma unroll
            for (int nt = 0; nt < 4; nt++) {
                mma_tf32(s[mt][nt], ah[mt], bl[nt]);
                mma_tf32(s[mt][nt], al[mt], bh[nt]);
                mma_tf32(s[mt][nt], ah[mt], bh[nt]);
            }
    }

    int nval[2][2];
#pragma unroll
    for (int mt = 0; mt < 2; mt++)
#pragma unroll
        for (int hf = 0; hf < 2; hf++) {
            int pos = qbase + wm * 32 + mt * 16 + grp + hf * 8;
            nval[mt][hf] = (pos >= 31) ? ((pos - 31) >> 5) + 1 : 0;
        }
#pragma unroll
    for (int mt = 0; mt < 2; mt++)
#pragma unroll
        for (int nt = 0; nt < 4; nt++)
#pragma unroll
            for (int r = 0; r < 4; r++) {
                int c = wn * 32 + nt * 8 + 2 * t4 + (r & 1);
                bool valid = c < nval[mt][r >> 1];
                s[mt][nt][r] = valid ? s[mt][nt][r] * 0.125f : -1e30f;
            }

#pragma unroll
    for (int mt = 0; mt < 2; mt++)
#pragma unroll
        for (int hf = 0; hf < 2; hf++) {
            float rm = -1e30f;
#pragma unroll
            for (int nt = 0; nt < 4; nt++)
                rm = fmaxf(rm, fmaxf(s[mt][nt][2 * hf], s[mt][nt][2 * hf + 1]));
            rm = fmaxf(rm, __shfl_xor_sync(0xffffffffu, rm, 1));
            rm = fmaxf(rm, __shfl_xor_sync(0xffffffffu, rm, 2));
            if (t4 == 0)
                redm[(wm * 32 + mt * 16 + grp + hf * 8) * 4 + wn] = rm;
        }
    __syncthreads();

    for (int i = tid; i < 2048; i += 256) {
        int r = i >> 4, d4 = (i & 15) * 4;
        float4 v = *(const float4*)(d_VC + cbase + r * 64 + d4);
        *(float4*)(&kv[r * CK + d4]) = v;
    }
#pragma unroll
    for (int mt = 0; mt < 2; mt++)
#pragma unroll
        for (int hf = 0; hf < 2; hf++) {
            int row = wm * 32 + mt * 16 + grp + hf * 8;
            float4 rmv = *(float4*)(&redm[row * 4]);
            float gmax = fmaxf(fmaxf(rmv.x, rmv.y), fmaxf(rmv.z, rmv.w));
            float rs = 0.f;
#pragma unroll
            for (int nt = 0; nt < 4; nt++) {
                float e0 = __expf(s[mt][nt][2 * hf]     - gmax);
                float e1 = __expf(s[mt][nt][2 * hf + 1] - gmax);
                s[mt][nt][2 * hf] = e0;
                s[mt][nt][2 * hf + 1] = e1;
                rs += e0 + e1;
            }
            rs += __shfl_xor_sync(0xffffffffu, rs, 1);
            rs += __shfl_xor_sync(0xffffffffu, rs, 2);
            if (t4 == 0) reds[row * 4 + wn] = rs;
        }
    __syncthreads();

#pragma unroll
    for (int mt = 0; mt < 2; mt++)
#pragma unroll
        for (int hf = 0; hf < 2; hf++) {
            int row = wm * 32 + mt * 16 + grp + hf * 8;
            float4 rsv = *(float4*)(&reds[row * 4]);
            float tot = rsv.x + rsv.y + rsv.z + rsv.w;
            float inv = (nval[mt][hf] > 0) ? 1.f / tot : 0.f;
#pragma unroll
            for (int nt = 0; nt < 4; nt++) {
                int col = wn * 32 + nt * 8 + 2 * t4;
                ps[row * CS + col]     = s[mt][nt][2 * hf]     * inv;
                ps[row * CS + col + 1] = s[mt][nt][2 * hf + 1] * inv;
            }
        }
    __syncthreads();

    float o[2][2][4];
#pragma unroll
    for (int mt = 0; mt < 2; mt++)
#pragma unroll
        for (int nt = 0; nt < 2; nt++)
#pragma unroll
            for (int r = 0; r < 4; r++) o[mt][nt][r] = 0.f;
#pragma unroll
    for (int ks = 0; ks < 16; ks++) {
        int kk = ks * 8;
        uint32_t af[2][4], bf[2][2];
#pragma unroll
        for (int mt = 0; mt < 2; mt++) {
            int row = wm * 32 + mt * 16 + grp;
            af[mt][0] = U(ftf(ps[row * CS + kk + t4]));
            af[mt][1] = U(ftf(ps[(row + 8) * CS + kk + t4]));
            af[mt][2] = U(ftf(ps[row * CS + kk + t4 + 4]));
            af[mt][3] = U(ftf(ps[(row + 8) * CS + kk + t4 + 4]));
        }
#pragma unroll
        for (int nt = 0; nt < 2; nt++) {
            int dcol = wn * 16 + nt * 8 + grp;
            bf[nt][0] = U(ftf(kv[(kk + t4) * CK + dcol]));
            bf[nt][1] = U(ftf(kv[(kk + t4 + 4) * CK + dcol]));
        }
#pragma unroll
        for (int mt = 0; mt < 2; mt++)
#pragma unroll
            for (int nt = 0; nt < 2; nt++)
                mma_tf32(o[mt][nt], af[mt], bf[nt]);
    }

#pragma unroll
    for (int mt = 0; mt < 2; mt++)
#pragma unroll
        for (int hf = 0; hf < 2; hf++) {
            int qp = qbase + wm * 32 + mt * 16 + grp + hf * 8;
            float g0 = d_G[(b * SEQ + qp) * 3 + 0];
#pragma unroll
            for (int nt = 0; nt < 2; nt++) {
                int dcol = wn * 16 + nt * 8 + 2 * t4;
                size_t ob = (size_t)(b * SEQ + qp) * 512 + h * 64 + dcol;
                *(float2*)(d_O + ob) = make_float2(o[mt][nt][2 * hf] * g0,
                                                   o[mt][nt][2 * hf + 1] * g0);
            }
        }
    __syncthreads();

    if (tid < 64) {
        float v = 0.f;
        for (int q = 0; q < 64; q++)
            v += ps[q * CS + 2 * tid] + ps[q * CS + 2 * tid + 1];
        impb[tid] = v;
    }
    __syncthreads();
    if (w == 0) {
        int j0 = lane, j1 = lane + 32;
        float v0 = (j0 <= g) ? impb[j0] + (j0 == g ? 1e9f : 0.f) : -1e30f;
        float v1 = (j1 <= g) ? impb[j1] + (j1 == g ? 1e9f : 0.f) : -1e30f;
        int selbase = ((b * NH + h) * NS + g) * TOPK;
        for (int r = 0; r < TOPK; r++) {
            float bv; int bi;
            if (v0 >= v1) { bv = v0; bi = j0; } else { bv = v1; bi = j1; }
#pragma unroll
            for (int o2 = 16; o2; o2 >>= 1) {
                float ov = __shfl_xor_sync(0xffffffffu, bv, o2);
                int   oi = __shfl_xor_sync(0xffffffffu, bi, o2);
                if (ov > bv || (ov == bv && oi < bi)) { bv = ov; bi = oi; }
            }
            if (lane == 0) d_SEL[selbase + r] = bi;
            if (bi == j0) v0 = -3e30f;
            if (bi == j1) v1 = -3e30f;
        }
    }
}

// ---------------- fused sel+win flash attention -----------------------------
// exp2-domain softmax (0.125*log2e folded into Q), no out_acc (direct RMW at
// phase boundary), 3 CTAs/SM target.
#define QP 72
#define KP 68
#define VP 72
#define PP 72
__global__ void __launch_bounds__(256, 3) selwin_fused()
{
    extern __shared__ float sm[];
    float* qs   = sm;                 // 64*72 paired (pre-scaled by QSCALE)
    float* Ks   = qs + 64 * QP;       // 64*68
    float* Vs   = Ks + 64 * KP;       // 64*72
    float* ps   = Vs + 64 * VP;       // 64*72 paired
    float* redm = ps + 64 * PP;       // 64*4
    float* reds = redm + 256;         // 64*4

    int g = blockIdx.x, hh = blockIdx.y, b = blockIdx.z;
    int tid = threadIdx.x, lane = tid & 31, w = tid >> 5;
    int grp = lane >> 2, t4 = lane & 3;
    int wm = w & 1, wn = w >> 1;
    int qbase = g * 64;

#pragma unroll
    for (int ii = 0; ii < 2; ii++) {
        int i = tid + ii * 256;
        int r = i >> 3, g8 = (i & 7) * 8;
        const float* src = d_Q + (size_t)(b * SEQ + qbase + r) * 512 + hh * 64 + g8;
        float4 lo = *(const float4*)src;
        float4 hi = *(const float4*)(src + 4);
        float2* dst = (float2*)(&qs[r * QP + g8]);
        dst[0] = make_float2(ftf(lo.x * QSCALE), ftf(hi.x * QSCALE));
        dst[1] = make_float2(ftf(lo.y * QSCALE), ftf(hi.y * QSCALE));
        dst[2] = make_float2(ftf(lo.z * QSCALE), ftf(hi.z * QSCALE));
        dst[3] = make_float2(ftf(lo.w * QSCALE), ftf(hi.w * QSCALE));
    }

    int selbase = ((b * NH + hh) * NS + g) * TOPK;
    int kblist[25];
    int nsel = 0;
#pragma unroll
    for (int it = 0; it < TOPK; it++) {
        int kb = d_SEL[selbase + it];
        if (kb <= g) kblist[nsel++] = kb;
    }
    int ntot = nsel;
    {
        int st = (g > 8) ? g - 8 : 0;
        for (int kb = st; kb <= g; kb++) kblist[ntot++] = kb;
    }

    float gv1[2][2], gv2[2][2];
#pragma unroll
    for (int mt = 0; mt < 2; mt++)
#pragma unroll
        for (int hf = 0; hf < 2; hf++) {
            int qp = qbase + wm * 32 + mt * 16 + grp + hf * 8;
            gv1[mt][hf] = d_G[(b * SEQ + qp) * 3 + 1];
            gv2[mt][hf] = d_G[(b * SEQ + qp) * 3 + 2];
        }

    float o[2][2][4];
#pragma unroll
    for (int mt = 0; mt < 2; mt++)
#pragma unroll
        for (int nt = 0; nt < 2; nt++)
#pragma unroll
            for (int r = 0; r < 4; r++) o[mt][nt][r] = 0.f;
    float mst[2][2], lst[2][2];
#pragma unroll
    for (int mt = 0; mt < 2; mt++)
#pragma unroll
        for (int hf = 0; hf < 2; hf++) { mst[mt][hf] = -1e30f; lst[mt][hf] = 0.f; }

    float4 kreg[4], vreg[4];
    int pr = tid >> 4, pd4 = (tid & 15) * 4;
    {
        size_t kbase = (size_t)(b * SEQ + kblist[0] * 64) * 512 + hh * 64;
#pragma unroll
        for (int j = 0; j < 4; j++) {
            kreg[j] = *(const float4*)(d_K + kbase + (size_t)(pr + j * 16) * 512 + pd4);
            vreg[j] = *(const float4*)(d_V + kbase + (size_t)(pr + j * 16) * 512 + pd4);
        }
#pragma unroll
        for (int j = 0; j < 4; j++) {
            int r = pr + j * 16;
            *(float4*)(&Ks[r * KP + pd4]) = ftf4(kreg[j]);
            *(float4*)(&Vs[r * VP + pd4]) = ftf4(vreg[j]);
        }
        int nb = (ntot > 1) ? 1 : 0;
        size_t kbase1 = (size_t)(b * SEQ + kblist[nb] * 64) * 512 + hh * 64;
#pragma unroll
        for (int j = 0; j < 4; j++) {
            kreg[j] = *(const float4*)(d_K + kbase1 + (size_t)(pr + j * 16) * 512 + pd4);
            vreg[j] = *(const float4*)(d_V + kbase1 + (size_t)(pr + j * 16) * 512 + pd4);
        }
    }
    __syncthreads();

    int posA = ((t4 & 1) << 2) + (t4 >> 1);

    for (int t = 0; t < ntot; t++) {
        if (t == nsel) {
            // finalize sel phase -> d_O, reset state
#pragma unroll
            for (int mt = 0; mt < 2; mt++)
#pragma unroll
                for (int hf = 0; hf < 2; hf++) {
                    int qp = qbase + wm * 32 + mt * 16 + grp + hf * 8;
                    float inv = gv1[mt][hf] / lst[mt][hf];
#pragma unroll
                    for (int nt = 0; nt < 2; nt++) {
                        int dcol = wn * 16 + nt * 8 + 2 * t4;
                        size_t ob = (size_t)(b * SEQ + qp) * 512 + hh * 64 + dcol;
                        float2 cur = *(float2*)(d_O + ob);
                        cur.x += o[mt][nt][2 * hf]     * inv;
                        cur.y += o[mt][nt][2 * hf + 1] * inv;
                        *(float2*)(d_O + ob) = cur;
                        o[mt][nt][2 * hf] = 0.f; o[mt][nt][2 * hf + 1] = 0.f;
                    }
                    mst[mt][hf] = -1e30f; lst[mt][hf] = 0.f;
                }
        }
        int kb = kblist[t];
        bool winph = (t >= nsel);
        bool more = (t + 1 < ntot);
        int nidx = (t + 2 < ntot) ? t + 2 : ntot - 1;
        size_t nbase = (size_t)(b * SEQ + kblist[nidx] * 64) * 512 + hh * 64;

        float s[2][2][4];
#pragma unroll
        for (int mt = 0; mt < 2; mt++)
#pragma unroll
            for (int nt = 0; nt < 2; nt++)
#pragma unroll
                for (int r = 0; r < 4; r++) s[mt][nt][r] = 0.f;
#pragma unroll
        for (int ks = 0; ks < 8; ks++) {
            int kk = ks * 8;
            uint32_t af[2][4], bf[2][2];
#pragma unroll
            for (int mt = 0; mt < 2; mt++) {
                int row = wm * 32 + mt * 16 + grp;
                float2 a0 = *(float2*)(&qs[row * QP + kk + 2 * t4]);
                float2 a1 = *(float2*)(&qs[(row + 8) * QP + kk + 2 * t4]);
                af[mt][0] = U(a0.x); af[mt][2] = U(a0.y);
                af[mt][1] = U(a1.x); af[mt][3] = U(a1.y);
            }
#pragma unroll
            for (int nt = 0; nt < 2; nt++) {
                int key = wn * 16 + nt * 8 + grp;
                bf[nt][0] = U(Ks[key * KP + kk + t4]);
                bf[nt][1] = U(Ks[key * KP + kk + t4 + 4]);
            }
#pragma unroll
            for (int mt = 0; mt < 2; mt++)
#pragma unroll
                for (int nt = 0; nt < 2; nt++)
                    mma_tf32(s[mt][nt], af[mt], bf[nt]);
        }

        // mask only (scale already folded into Q)
#pragma unroll
        for (int mt = 0; mt < 2; mt++)
#pragma unroll
            for (int nt = 0; nt < 2; nt++)
#pragma unroll
                for (int r = 0; r < 4; r++) {
                    int qp = qbase + wm * 32 + mt * 16 + grp + (r >> 1) * 8;
                    int kp = kb * 64 + wn * 16 + nt * 8 + 2 * t4 + (r & 1);
                    bool valid = (kp <= qp) && (!winph || (kp + 512 > qp));
                    s[mt][nt][r] = valid ? s[mt][nt][r] : -1e30f;
                }

#pragma unroll
        for (int mt = 0; mt < 2; mt++)
#pragma unroll
            for (int hf = 0; hf < 2; hf++) {
                float rm = fmaxf(fmaxf(s[mt][0][2 * hf], s[mt][0][2 * hf + 1]),
                                 fmaxf(s[mt][1][2 * hf], s[mt][1][2 * hf + 1]));
                rm = fmaxf(rm, __shfl_xor_sync(0xffffffffu, rm, 1));
                rm = fmaxf(rm, __shfl_xor_sync(0xffffffffu, rm, 2));
                if (t4 == 0)
                    redm[(wm * 32 + mt * 16 + grp + hf * 8) * 4 + wn] = rm;
            }
        __syncthreads();

        if (more) {
#pragma unroll
            for (int j = 0; j < 4; j++)
                *(float4*)(&Ks[(pr + j * 16) * KP + pd4]) = ftf4(kreg[j]);
#pragma unroll
            for (int j = 0; j < 4; j++)
                kreg[j] = *(const float4*)(d_K + nbase + (size_t)(pr + j * 16) * 512 + pd4);
        }

        float corr[2][2], mnew[2][2];
#pragma unroll
        for (int mt = 0; mt < 2; mt++)
#pragma unroll
            for (int hf = 0; hf < 2; hf++) {
                int row = wm * 32 + mt * 16 + grp + hf * 8;
                float4 rmv = *(float4*)(&redm[row * 4]);
                float gmax = fmaxf(fmaxf(rmv.x, rmv.y), fmaxf(rmv.z, rmv.w));
                float mn = fmaxf(mst[mt][hf], gmax);
                mnew[mt][hf] = mn;
                corr[mt][hf] = ex2(mst[mt][hf] - mn);
            }

#pragma unroll
        for (int mt = 0; mt < 2; mt++)
#pragma unroll
            for (int hf = 0; hf < 2; hf++) {
                int rowl = wm * 32 + mt * 16 + grp + hf * 8;
                float mn = mnew[mt][hf];
                float rs = 0.f;
#pragma unroll
                for (int nt = 0; nt < 2; nt++) {
                    float p0 = ex2(s[mt][nt][2 * hf]     - mn);
                    float p1 = ex2(s[mt][nt][2 * hf + 1] - mn);
                    rs += p0 + p1;
                    int gb = wn * 16 + nt * 8;
                    ps[rowl * PP + gb + posA]     = ftf(p0);
                    ps[rowl * PP + gb + posA + 2] = ftf(p1);
                }
                rs += __shfl_xor_sync(0xffffffffu, rs, 1);
                rs += __shfl_xor_sync(0xffffffffu, rs, 2);
                if (t4 == 0) reds[rowl * 4 + wn] = rs;
            }
        __syncthreads();

#pragma unroll
        for (int mt = 0; mt < 2; mt++)
#pragma unroll
            for (int hf = 0; hf < 2; hf++) {
                int row = wm * 32 + mt * 16 + grp + hf * 8;
                float4 rsv = *(float4*)(&reds[row * 4]);
                float ls = rsv.x + rsv.y + rsv.z + rsv.w;
                float cr = corr[mt][hf];
                lst[mt][hf] = lst[mt][hf] * cr + ls;
                mst[mt][hf] = mnew[mt][hf];
#pragma unroll
                for (int nt = 0; nt < 2; nt++) {
                    o[mt][nt][2 * hf]     *= cr;
                    o[mt][nt][2 * hf + 1] *= cr;
                }
            }

#pragma unroll
        for (int ks = 0; ks < 8; ks++) {
            int kk = ks * 8;
            uint32_t af[2][4], bf[2][2];
#pragma unroll
            for (int mt = 0; mt < 2; mt++) {
                int row = wm * 32 + mt * 16 + grp;
                float2 p0 = *(float2*)(&ps[row * PP + kk + 2 * t4]);
                float2 p1 = *(float2*)(&ps[(row + 8) * PP + kk + 2 * t4]);
                af[mt][0] = U(p0.x); af[mt][2] = U(p0.y);
                af[mt][1] = U(p1.x); af[mt][3] = U(p1.y);
            }
#pragma unroll
            for (int nt = 0; nt < 2; nt++) {
                int dcol = wn * 16 + nt * 8 + grp;
                bf[nt][0] = U(Vs[(kk + t4) * VP + dcol]);
                bf[nt][1] = U(Vs[(kk + t4 + 4) * VP + dcol]);
            }
#pragma unroll
            for (int mt = 0; mt < 2; mt++)
#pragma unroll
                for (int nt = 0; nt < 2; nt++)
                    mma_tf32(o[mt][nt], af[mt], bf[nt]);
        }
        __syncthreads();

        if (more) {
#pragma unroll
            for (int j = 0; j < 4; j++)
                *(float4*)(&Vs[(pr + j * 16) * VP + pd4]) = ftf4(vreg[j]);
#pragma unroll
            for (int j = 0; j < 4; j++)
                vreg[j] = *(const float4*)(d_V + nbase + (size_t)(pr + j * 16) * 512 + pd4);
        }
    }

    // finalize win phase
#pragma unroll
    for (int mt = 0; mt < 2; mt++)
#pragma unroll
        for (int hf = 0; hf < 2; hf++) {
            int qp = qbase + wm * 32 + mt * 16 + grp + hf * 8;
            float inv = gv2[mt][hf] / lst[mt][hf];
#pragma unroll
            for (int nt = 0; nt < 2; nt++) {
                int dcol = wn * 16 + nt * 8 + 2 * t4;
                size_t ob = (size_t)(b * SEQ + qp) * 512 + hh * 64 + dcol;
                float2 cur = *(float2*)(d_O + ob);
                cur.x += o[mt][nt][2 * hf]     * inv;
                cur.y += o[mt][nt][2 * hf + 1] * inv;
                *(float2*)(d_O + ob) = cur;
            }
        }
}

// ---------------------------------------------------------------------------
extern "C" void kernel_launch(void* const* d_in, const int* in_sizes, int n_in,
                              void* d_out, int out_size)
{
    const float* x  = (const float*)d_in[0];
    const float* Wq = (const float*)d_in[1];
    const float* Wk = (const float*)d_in[2];
    const float* Wv = (const float*)d_in[3];
    const float* Wo = (const float*)d_in[4];
    const float* Wg = (const float*)d_in[5];
    float* y = (float*)d_out;

    cudaFuncSetAttribute(gemm512_tc,
                         cudaFuncAttributeMaxDynamicSharedMemorySize, 71680);
    cudaFuncSetAttribute(cmp_attn_mma,
                         cudaFuncAttributeMaxDynamicSharedMemorySize, 90368);
    cudaFuncSetAttribute(selwin_fused,
                         cudaFuncAttributeMaxDynamicSharedMemorySize, 74752);

    gemm512_tc<<<dim3(4, 64, 3), 256, 71680>>>(x, Wq, Wk, Wv, nullptr, 0);
    gate_compress<<<1024 + 512, 256>>>(x, Wg);
    cmp_attn_mma<<<dim3(64, 8, 2), 256, 90368>>>();
    selwin_fused<<<dim3(64, 8, 2), 256, 74752>>>();
    gemm512_tc<<<dim3(4, 64, 1), 256, 71680>>>(nullptr, Wo, nullptr, nullptr, y, 3);
}

// round 13
// speedup vs baseline: 1.1250x; 1.1250x over previous
#include <cuda_runtime.h>
#include <math.h>
#include <stdint.h>

#define BATCH   2
#define SEQ     4096
#define DMODEL  512
#define NH      8
#define HD      64
#define NC      128
#define NS      64
#define TOPK    16
#define NROWS   (BATCH*SEQ)

// ---------------- scratch ----------------
__device__ float d_Q[NROWS*DMODEL];
__device__ float d_K[NROWS*DMODEL];
__device__ float d_V[NROWS*DMODEL];
__device__ float d_O[NROWS*DMODEL];
__device__ float d_KC[BATCH*NH*NC*HD];
__device__ float d_VC[BATCH*NH*NC*HD];
__device__ float d_G[NROWS*3];
__device__ int   d_SEL[BATCH*NH*NS*TOPK];

// ---------------- tf32 helpers ----------------
__device__ __forceinline__ float ftf(float x) {
    uint32_t u;
    asm("cvt.rna.tf32.f32 %0, %1;" : "=r"(u) : "f"(x));
    return __uint_as_float(u);
}
__device__ __forceinline__ float4 ftf4(float4 v) {
    return make_float4(ftf(v.x), ftf(v.y), ftf(v.z), ftf(v.w));
}
__device__ __forceinline__ float ex2(float x) {
    float r;
    asm("ex2.approx.ftz.f32 %0, %1;" : "=f"(r) : "f"(x));
    return r;
}
__device__ __forceinline__ void mma_tf32(float* c, const uint32_t* a, const uint32_t* b) {
    asm volatile(
        "mma.sync.aligned.m16n8k8.row.col.f32.tf32.tf32.f32 "
        "{%0,%1,%2,%3},{%4,%5,%6,%7},{%8,%9},{%0,%1,%2,%3};\n"
        : "+f"(c[0]), "+f"(c[1]), "+f"(c[2]), "+f"(c[3])
        : "r"(a[0]), "r"(a[1]), "r"(a[2]), "r"(a[3]), "r"(b[0]), "r"(b[1]));
}
__device__ __forceinline__ void split_tf32(float x, uint32_t& hi, uint32_t& lo) {
    float h = ftf(x);
    hi = __float_as_uint(h);
    lo = __float_as_uint(ftf(x - h));
}
#define U(x) __float_as_uint(x)
#define QSCALE 0.18033688011112042f   /* 0.125 * log2(e) */

// ---------------- tf32 GEMM: 128x128 tile, k-slab 32, smem double buffer --
#define GPA 36
#define GPB 136
__global__ __launch_bounds__(256) void gemm512_tc(const float* __restrict__ Aext,
    const float* __restrict__ B0, const float* __restrict__ B1,
    const float* __restrict__ B2, float* __restrict__ Cext, int modeBase)
{
    extern __shared__ float smg[];
    float* As = smg;
    float* Bs = smg + 2 * 128 * GPA;

    int mode = modeBase + blockIdx.z;
    const float* A  = (mode == 3) ? d_O : Aext;
    const float* Bm = (mode == 1) ? B1 : (mode == 2) ? B2 : B0;
    float* C = (mode == 0) ? d_Q : (mode == 1) ? d_K : (mode == 2) ? d_V : Cext;

    int tid = threadIdx.x, lane = tid & 31, w = tid >> 5;
    int grp = lane >> 2, t4 = lane & 3;
    int wm = w & 3, wn = w >> 2;
    int m0 = blockIdx.y * 128, n0 = blockIdx.x * 128;

    int arr[4], arc[4], brr[4], brc[4];
#pragma unroll
    for (int ii = 0; ii < 4; ii++) {
        int i = tid + ii * 256;
        arr[ii] = i >> 3;  arc[ii] = (i & 7) * 4;
        brr[ii] = i >> 5;  brc[ii] = (i & 31) * 4;
    }

    float acc[2][8][4];
#pragma unroll
    for (int mt = 0; mt < 2; mt++)
#pragma unroll
        for (int nt = 0; nt < 8; nt++)
#pragma unroll
            for (int r = 0; r < 4; r++) acc[mt][nt][r] = 0.f;

    float4 areg[4], breg[4];
#pragma unroll
    for (int ii = 0; ii < 4; ii++) {
        areg[ii] = *(const float4*)(A + (size_t)(m0 + arr[ii]) * 512 + arc[ii]);
        breg[ii] = *(const float4*)(Bm + (size_t)brr[ii] * 512 + n0 + brc[ii]);
    }
#pragma unroll
    for (int ii = 0; ii < 4; ii++) {
        *(float4*)(&As[arr[ii] * GPA + arc[ii]]) = ftf4(areg[ii]);
        *(float4*)(&Bs[brr[ii] * GPB + brc[ii]]) = ftf4(breg[ii]);
    }
    __syncthreads();

    for (int s = 0; s < 16; s++) {
        float* Ab = As + (s & 1) * 128 * GPA;
        float* Bb = Bs + (s & 1) * 32 * GPB;
        if (s < 15) {
            int k0 = (s + 1) * 32;
#pragma unroll
            for (int ii = 0; ii < 4; ii++) {
                areg[ii] = *(const float4*)(A + (size_t)(m0 + arr[ii]) * 512 + k0 + arc[ii]);
                breg[ii] = *(const float4*)(Bm + (size_t)(k0 + brr[ii]) * 512 + n0 + brc[ii]);
            }
        }
#pragma unroll
        for (int ks = 0; ks < 4; ks++) {
            int kb = ks * 8;
            uint32_t af[2][4], bf[8][2];
#pragma unroll
            for (int mt = 0; mt < 2; mt++) {
                int row = wm * 32 + mt * 16 + grp;
                af[mt][0] = U(Ab[row * GPA + kb + t4]);
                af[mt][1] = U(Ab[(row + 8) * GPA + kb + t4]);
                af[mt][2] = U(Ab[row * GPA + kb + t4 + 4]);
                af[mt][3] = U(Ab[(row + 8) * GPA + kb + t4 + 4]);
            }
#pragma unroll
            for (int nt = 0; nt < 8; nt++) {
                int col = wn * 64 + nt * 8 + grp;
                bf[nt][0] = U(Bb[(kb + t4) * GPB + col]);
                bf[nt][1] = U(Bb[(kb + t4 + 4) * GPB + col]);
            }
#pragma unroll
            for (int mt = 0; mt < 2; mt++)
#pragma unroll
                for (int nt = 0; nt < 8; nt++)
                    mma_tf32(acc[mt][nt], af[mt], bf[nt]);
        }
        if (s < 15) {
            float* An = As + ((s + 1) & 1) * 128 * GPA;
            float* Bn = Bs + ((s + 1) & 1) * 32 * GPB;
#pragma unroll
            for (int ii = 0; ii < 4; ii++) {
                *(float4*)(&An[arr[ii] * GPA + arc[ii]]) = ftf4(areg[ii]);
                *(float4*)(&Bn[brr[ii] * GPB + brc[ii]]) = ftf4(breg[ii]);
            }
        }
        __syncthreads();
    }
#pragma unroll
    for (int mt = 0; mt < 2; mt++)
#pragma unroll
        for (int nt = 0; nt < 8; nt++) {
            int row = m0 + wm * 32 + mt * 16 + grp;
            int col = n0 + wn * 64 + nt * 8 + 2 * t4;
            *(float2*)(C + (size_t)row * 512 + col) =
                make_float2(acc[mt][nt][0], acc[mt][nt][1]);
            *(float2*)(C + (size_t)(row + 8) * 512 + col) =
                make_float2(acc[mt][nt][2], acc[mt][nt][3]);
        }
}

// ---------------- fused gate + compress (one launch) ----------------
__global__ __launch_bounds__(256) void gate_compress(const float* __restrict__ x,
                                                     const float* __restrict__ Wg)
{
    int blk = blockIdx.x;
    if (blk < 1024) {
        int w = threadIdx.x >> 5, lane = threadIdx.x & 31;
        int row = blk * 8 + w;
        float p0 = 0, p1 = 0, p2 = 0;
#pragma unroll
        for (int c = 0; c < 4; c++) {
            int d = c * 128 + lane * 4;
            float4 xv = *(const float4*)(x + (size_t)row * 512 + d);
            p0 += xv.x * Wg[d * 3]     + xv.y * Wg[d * 3 + 3] +
                  xv.z * Wg[d * 3 + 6] + xv.w * Wg[d * 3 + 9];
            p1 += xv.x * Wg[d * 3 + 1] + xv.y * Wg[d * 3 + 4] +
                  xv.z * Wg[d * 3 + 7] + xv.w * Wg[d * 3 + 10];
            p2 += xv.x * Wg[d * 3 + 2] + xv.y * Wg[d * 3 + 5] +
                  xv.z * Wg[d * 3 + 8] + xv.w * Wg[d * 3 + 11];
        }
#pragma unroll
        for (int o = 16; o; o >>= 1) {
            p0 += __shfl_xor_sync(0xffffffffu, p0, o);
            p1 += __shfl_xor_sync(0xffffffffu, p1, o);
            p2 += __shfl_xor_sync(0xffffffffu, p2, o);
        }
        if (lane == 0) {
            d_G[row * 3 + 0] = 1.f / (1.f + expf(-p0));
            d_G[row * 3 + 1] = 1.f / (1.f + expf(-p1));
            d_G[row * 3 + 2] = 1.f / (1.f + expf(-p2));
        }
    } else {
        int idx = (blk - 1024) * 256 + threadIdx.x;
        int d = idx & 63, n = (idx >> 6) & 127, h = (idx >> 13) & 7, b = idx >> 16;
        const float* kp = d_K + (size_t)(b * SEQ + n * 32) * 512 + h * 64 + d;
        const float* vp = d_V + (size_t)(b * SEQ + n * 32) * 512 + h * 64 + d;
        float ks = 0, vs = 0;
#pragma unroll
        for (int r = 0; r < 32; r++) { ks += kp[r * 512]; vs += vp[r * 512]; }
        d_KC[idx] = ks * (1.f / 32.f);
        d_VC[idx] = vs * (1.f / 32.f);
    }
}

// ---------------- compressed attention + top-k (R7 proven: 3xTF32 QK) -----
#define CQ 68
#define CK 72
#define CS 132
__global__ __launch_bounds__(256) void cmp_attn_mma()
{
    extern __shared__ float sm[];
    float* qs   = sm;
    float* kv   = qs + 64 * CQ;
    float* ps   = kv + 128 * CK;
    float* redm = ps + 64 * CS;
    float* reds = redm + 256;
    float* impb = reds + 256;

    int g = blockIdx.x, h = blockIdx.y, b = blockIdx.z;
    int tid = threadIdx.x, lane = tid & 31, w = tid >> 5;
    int grp = lane >> 2, t4 = lane & 3;
    int wm = w & 1, wn = w >> 1;
    int qbase = g * 64;

    for (int i = tid; i < 1024; i += 256) {
        int r = i >> 4, d4 = (i & 15) * 4;
        float4 v = *(const float4*)(d_Q + (size_t)(b * SEQ + qbase + r) * 512 + h * 64 + d4);
        *(float4*)(&qs[r * CQ + d4]) = v;
    }
    int cbase = ((b * NH + h) * NC) * HD;
    for (int i = tid; i < 2048; i += 256) {
        int r = i >> 4, d4 = (i & 15) * 4;
        float4 v = *(const float4*)(d_KC + cbase + r * 64 + d4);
        *(float4*)(&kv[r * CK + d4]) = v;
    }
    __syncthreads();

    float s[2][4][4];
#pragma unroll
    for (int mt = 0; mt < 2; mt++)
#pragma unroll
        for (int nt = 0; nt < 4; nt++)
#pragma unroll
            for (int r = 0; r < 4; r++) s[mt][nt][r] = 0.f;
#pragma unroll
    for (int ks = 0; ks < 8; ks++) {
        int kk = ks * 8;
        uint32_t ah[2][4], al[2][4], bh[4][2], bl[4][2];
#pragma unroll
        for (int mt = 0; mt < 2; mt++) {
            int row = wm * 32 + mt * 16 + grp;
            split_tf32(qs[row * CQ + kk + t4],           ah[mt][0], al[mt][0]);
            split_tf32(qs[(row + 8) * CQ + kk + t4],     ah[mt][1], al[mt][1]);
            split_tf32(qs[row * CQ + kk + t4 + 4],       ah[mt][2], al[mt][2]);
            split_tf32(qs[(row + 8) * CQ + kk + t4 + 4], ah[mt][3], al[mt][3]);
        }
#pragma unroll
        for (int nt = 0; nt < 4; nt++) {
            int key = wn * 32 + nt * 8 + grp;
            split_tf32(kv[key * CK + kk + t4],     bh[nt][0], bl[nt][0]);
            split_tf32(kv[key * CK + kk + t4 + 4], bh[nt][1], bl[nt][1]);
        }
#pragma unroll
        for (int mt = 0; mt < 2; mt++)
#pragma unroll
            for (int nt = 0; nt < 4; nt++) {
                mma_tf32(s[mt][nt], ah[mt], bl[nt]);
                mma_tf32(s[mt][nt], al[mt], bh[nt]);
                mma_tf32(s[mt][nt], ah[mt], bh[nt]);
            }
    }

    int nval[2][2];
#pragma unroll
    for (int mt = 0; mt < 2; mt++)
#pragma unroll
        for (int hf = 0; hf < 2; hf++) {
            int pos = qbase + wm * 32 + mt * 16 + grp + hf * 8;
            nval[mt][hf] = (pos >= 31) ? ((pos - 31) >> 5) + 1 : 0;
        }
#pragma unroll
    for (int mt = 0; mt < 2; mt++)
#pragma unroll
        for (int nt = 0; nt < 4; nt++)
#pragma unroll
            for (int r = 0; r < 4; r++) {
                int c = wn * 32 + nt * 8 + 2 * t4 + (r & 1);
                bool valid = c < nval[mt][r >> 1];
                s[mt][nt][r] = valid ? s[mt][nt][r] * 0.125f : -1e30f;
            }

#pragma unroll
    for (int mt = 0; mt < 2; mt++)
#pragma unroll
        for (int hf = 0; hf < 2; hf++) {
            float rm = -1e30f;
#pragma unroll
            for (int nt = 0; nt < 4; nt++)
                rm = fmaxf(rm, fmaxf(s[mt][nt][2 * hf], s[mt][nt][2 * hf + 1]));
            rm = fmaxf(rm, __shfl_xor_sync(0xffffffffu, rm, 1));
            rm = fmaxf(rm, __shfl_xor_sync(0xffffffffu, rm, 2));
            if (t4 == 0)
                redm[(wm * 32 + mt * 16 + grp + hf * 8) * 4 + wn] = rm;
        }
    __syncthreads();

    for (int i = tid; i < 2048; i += 256) {
        int r = i >> 4, d4 = (i & 15) * 4;
        float4 v = *(const float4*)(d_VC + cbase + r * 64 + d4);
        *(float4*)(&kv[r * CK + d4]) = v;
    }
#pragma unroll
    for (int mt = 0; mt < 2; mt++)
#pragma unroll
        for (int hf = 0; hf < 2; hf++) {
            int row = wm * 32 + mt * 16 + grp + hf * 8;
            float4 rmv = *(float4*)(&redm[row * 4]);
            float gmax = fmaxf(fmaxf(rmv.x, rmv.y), fmaxf(rmv.z, rmv.w));
            float rs = 0.f;
#pragma unroll
            for (int nt = 0; nt < 4; nt++) {
                float e0 = __expf(s[mt][nt][2 * hf]     - gmax);
                float e1 = __expf(s[mt][nt][2 * hf + 1] - gmax);
                s[mt][nt][2 * hf] = e0;
                s[mt][nt][2 * hf + 1] = e1;
                rs += e0 + e1;
            }
            rs += __shfl_xor_sync(0xffffffffu, rs, 1);
            rs += __shfl_xor_sync(0xffffffffu, rs, 2);
            if (t4 == 0) reds[row * 4 + wn] = rs;
        }
    __syncthreads();

#pragma unroll
    for (int mt = 0; mt < 2; mt++)
#pragma unroll
        for (int hf = 0; hf < 2; hf++) {
            int row = wm * 32 + mt * 16 + grp + hf * 8;
            float4 rsv = *(float4*)(&reds[row * 4]);
            float tot = rsv.x + rsv.y + rsv.z + rsv.w;
            float inv = (nval[mt][hf] > 0) ? 1.f / tot : 0.f;
#pragma unroll
            for (int nt = 0; nt < 4; nt++) {
                int col = wn * 32 + nt * 8 + 2 * t4;
                ps[row * CS + col]     = s[mt][nt][2 * hf]     * inv;
                ps[row * CS + col + 1] = s[mt][nt][2 * hf + 1] * inv;
            }
        }
    __syncthreads();

    float o[2][2][4];
#pragma unroll
    for (int mt = 0; mt < 2; mt++)
#pragma unroll
        for (int nt = 0; nt < 2; nt++)
#pragma unroll
            for (int r = 0; r < 4; r++) o[mt][nt][r] = 0.f;
#pragma unroll
    for (int ks = 0; ks < 16; ks++) {
        int kk = ks * 8;
        uint32_t af[2][4], bf[2][2];
#pragma unroll
        for (int mt = 0; mt < 2; mt++) {
            int row = wm * 32 + mt * 16 + grp;
            af[mt][0] = U(ftf(ps[row * CS + kk + t4]));
            af[mt][1] = U(ftf(ps[(row + 8) * CS + kk + t4]));
            af[mt][2] = U(ftf(ps[row * CS + kk + t4 + 4]));
            af[mt][3] = U(ftf(ps[(row + 8) * CS + kk + t4 + 4]));
        }
#pragma unroll
        for (int nt = 0; nt < 2; nt++) {
            int dcol = wn * 16 + nt * 8 + grp;
            bf[nt][0] = U(ftf(kv[(kk + t4) * CK + dcol]));
            bf[nt][1] = U(ftf(kv[(kk + t4 + 4) * CK + dcol]));
        }
#pragma unroll
        for (int mt = 0; mt < 2; mt++)
#pragma unroll
            for (int nt = 0; nt < 2; nt++)
                mma_tf32(o[mt][nt], af[mt], bf[nt]);
    }

#pragma unroll
    for (int mt = 0; mt < 2; mt++)
#pragma unroll
        for (int hf = 0; hf < 2; hf++) {
            int qp = qbase + wm * 32 + mt * 16 + grp + hf * 8;
            float g0 = d_G[(b * SEQ + qp) * 3 + 0];
#pragma unroll
            for (int nt = 0; nt < 2; nt++) {
                int dcol = wn * 16 + nt * 8 + 2 * t4;
                size_t ob = (size_t)(b * SEQ + qp) * 512 + h * 64 + dcol;
                *(float2*)(d_O + ob) = make_float2(o[mt][nt][2 * hf] * g0,
                                                   o[mt][nt][2 * hf + 1] * g0);
            }
        }
    __syncthreads();

    if (tid < 64) {
        float v = 0.f;
        for (int q = 0; q < 64; q++)
            v += ps[q * CS + 2 * tid] + ps[q * CS + 2 * tid + 1];
        impb[tid] = v;
    }
    __syncthreads();
    if (w == 0) {
        int j0 = lane, j1 = lane + 32;
        float v0 = (j0 <= g) ? impb[j0] + (j0 == g ? 1e9f : 0.f) : -1e30f;
        float v1 = (j1 <= g) ? impb[j1] + (j1 == g ? 1e9f : 0.f) : -1e30f;
        int selbase = ((b * NH + h) * NS + g) * TOPK;
        for (int r = 0; r < TOPK; r++) {
            float bv; int bi;
            if (v0 >= v1) { bv = v0; bi = j0; } else { bv = v1; bi = j1; }
#pragma unroll
            for (int o2 = 16; o2; o2 >>= 1) {
                float ov = __shfl_xor_sync(0xffffffffu, bv, o2);
                int   oi = __shfl_xor_sync(0xffffffffu, bi, o2);
                if (ov > bv || (ov == bv && oi < bi)) { bv = ov; bi = oi; }
            }
            if (lane == 0) d_SEL[selbase + r] = bi;
            if (bi == j0) v0 = -3e30f;
            if (bi == j1) v1 = -3e30f;
        }
    }
}

// ---------------- fused sel+win flash attention -----------------------------
// exp2-domain softmax, direct phase-boundary RMW (no out_acc), NO forced
// min-blocks (R12's ,3 caused register spills: L1 71%, L2 22%).
#define QP 72
#define KP 68
#define VP 72
#define PP 72
__global__ void __launch_bounds__(256) selwin_fused()
{
    extern __shared__ float sm[];
    float* qs   = sm;                 // 64*72 paired (pre-scaled by QSCALE)
    float* Ks   = qs + 64 * QP;       // 64*68
    float* Vs   = Ks + 64 * KP;       // 64*72
    float* ps   = Vs + 64 * VP;       // 64*72 paired
    float* redm = ps + 64 * PP;       // 64*4
    float* reds = redm + 256;         // 64*4

    int g = blockIdx.x, hh = blockIdx.y, b = blockIdx.z;
    int tid = threadIdx.x, lane = tid & 31, w = tid >> 5;
    int grp = lane >> 2, t4 = lane & 3;
    int wm = w & 1, wn = w >> 1;
    int qbase = g * 64;

#pragma unroll
    for (int ii = 0; ii < 2; ii++) {
        int i = tid + ii * 256;
        int r = i >> 3, g8 = (i & 7) * 8;
        const float* src = d_Q + (size_t)(b * SEQ + qbase + r) * 512 + hh * 64 + g8;
        float4 lo = *(const float4*)src;
        float4 hi = *(const float4*)(src + 4);
        float2* dst = (float2*)(&qs[r * QP + g8]);
        dst[0] = make_float2(ftf(lo.x * QSCALE), ftf(hi.x * QSCALE));
        dst[1] = make_float2(ftf(lo.y * QSCALE), ftf(hi.y * QSCALE));
        dst[2] = make_float2(ftf(lo.z * QSCALE), ftf(hi.z * QSCALE));
        dst[3] = make_float2(ftf(lo.w * QSCALE), ftf(hi.w * QSCALE));
    }

    int selbase = ((b * NH + hh) * NS + g) * TOPK;
    int kblist[25];
    int nsel = 0;
#pragma unroll
    for (int it = 0; it < TOPK; it++) {
        int kb = d_SEL[selbase + it];
        if (kb <= g) kblist[nsel++] = kb;
    }
    int ntot = nsel;
    {
        int st = (g > 8) ? g - 8 : 0;
        for (int kb = st; kb <= g; kb++) kblist[ntot++] = kb;
    }

    float gv1[2][2], gv2[2][2];
#pragma unroll
    for (int mt = 0; mt < 2; mt++)
#pragma unroll
        for (int hf = 0; hf < 2; hf++) {
            int qp = qbase + wm * 32 + mt * 16 + grp + hf * 8;
            gv1[mt][hf] = d_G[(b * SEQ + qp) * 3 + 1];
            gv2[mt][hf] = d_G[(b * SEQ + qp) * 3 + 2];
        }

    float o[2][2][4];
#pragma unroll
    for (int mt = 0; mt < 2; mt++)
#pragma unroll
        for (int nt = 0; nt < 2; nt++)
#pragma unroll
            for (int r = 0; r < 4; r++) o[mt][nt][r] = 0.f;
    float mst[2][2], lst[2][2];
#pragma unroll
    for (int mt = 0; mt < 2; mt++)
#pragma unroll
        for (int hf = 0; hf < 2; hf++) { mst[mt][hf] = -1e30f; lst[mt][hf] = 0.f; }

    float4 kreg[4], vreg[4];
    int pr = tid >> 4, pd4 = (tid & 15) * 4;
    {
        size_t kbase = (size_t)(b * SEQ + kblist[0] * 64) * 512 + hh * 64;
#pragma unroll
        for (int j = 0; j < 4; j++) {
            kreg[j] = *(const float4*)(d_K + kbase + (size_t)(pr + j * 16) * 512 + pd4);
            vreg[j] = *(const float4*)(d_V + kbase + (size_t)(pr + j * 16) * 512 + pd4);
        }
#pragma unroll
        for (int j = 0; j < 4; j++) {
            int r = pr + j * 16;
            *(float4*)(&Ks[r * KP + pd4]) = ftf4(kreg[j]);
            *(float4*)(&Vs[r * VP + pd4]) = ftf4(vreg[j]);
        }
        int nb = (ntot > 1) ? 1 : 0;
        size_t kbase1 = (size_t)(b * SEQ + kblist[nb] * 64) * 512 + hh * 64;
#pragma unroll
        for (int j = 0; j < 4; j++) {
            kreg[j] = *(const float4*)(d_K + kbase1 + (size_t)(pr + j * 16) * 512 + pd4);
            vreg[j] = *(const float4*)(d_V + kbase1 + (size_t)(pr + j * 16) * 512 + pd4);
        }
    }
    __syncthreads();

    int posA = ((t4 & 1) << 2) + (t4 >> 1);

    for (int t = 0; t < ntot; t++) {
        if (t == nsel) {
#pragma unroll
            for (int mt = 0; mt < 2; mt++)
#pragma unroll
                for (int hf = 0; hf < 2; hf++) {
                    int qp = qbase + wm * 32 + mt * 16 + grp + hf * 8;
                    float inv = gv1[mt][hf] / lst[mt][hf];
#pragma unroll
                    for (int nt = 0; nt < 2; nt++) {
                        int dcol = wn * 16 + nt * 8 + 2 * t4;
                        size_t ob = (size_t)(b * SEQ + qp) * 512 + hh * 64 + dcol;
                        float2 cur = *(float2*)(d_O + ob);
                        cur.x += o[mt][nt][2 * hf]     * inv;
                        cur.y += o[mt][nt][2 * hf + 1] * inv;
                        *(float2*)(d_O + ob) = cur;
                        o[mt][nt][2 * hf] = 0.f; o[mt][nt][2 * hf + 1] = 0.f;
                    }
                    mst[mt][hf] = -1e30f; lst[mt][hf] = 0.f;
                }
        }
        int kb = kblist[t];
        bool winph = (t >= nsel);
        bool more = (t + 1 < ntot);
        int nidx = (t + 2 < ntot) ? t + 2 : ntot - 1;
        size_t nbase = (size_t)(b * SEQ + kblist[nidx] * 64) * 512 + hh * 64;

        float s[2][2][4];
#pragma unroll
        for (int mt = 0; mt < 2; mt++)
#pragma unroll
            for (int nt = 0; nt < 2; nt++)
#pragma unroll
                for (int r = 0; r < 4; r++) s[mt][nt][r] = 0.f;
#pragma unroll
        for (int ks = 0; ks < 8; ks++) {
            int kk = ks * 8;
            uint32_t af[2][4], bf[2][2];
#pragma unroll
            for (int mt = 0; mt < 2; mt++) {
                int row = wm * 32 + mt * 16 + grp;
                float2 a0 = *(float2*)(&qs[row * QP + kk + 2 * t4]);
                float2 a1 = *(float2*)(&qs[(row + 8) * QP + kk + 2 * t4]);
                af[mt][0] = U(a0.x); af[mt][2] = U(a0.y);
                af[mt][1] = U(a1.x); af[mt][3] = U(a1.y);
            }
#pragma unroll
            for (int nt = 0; nt < 2; nt++) {
                int key = wn * 16 + nt * 8 + grp;
                bf[nt][0] = U(Ks[key * KP + kk + t4]);
                bf[nt][1] = U(Ks[key * KP + kk + t4 + 4]);
            }
#pragma unroll
            for (int mt = 0; mt < 2; mt++)
#pragma unroll
                for (int nt = 0; nt < 2; nt++)
                    mma_tf32(s[mt][nt], af[mt], bf[nt]);
        }

#pragma unroll
        for (int mt = 0; mt < 2; mt++)
#pragma unroll
            for (int nt = 0; nt < 2; nt++)
#pragma unroll
                for (int r = 0; r < 4; r++) {
                    int qp = qbase + wm * 32 + mt * 16 + grp + (r >> 1) * 8;
                    int kp = kb * 64 + wn * 16 + nt * 8 + 2 * t4 + (r & 1);
                    bool valid = (kp <= qp) && (!winph || (kp + 512 > qp));
                    s[mt][nt][r] = valid ? s[mt][nt][r] : -1e30f;
                }

#pragma unroll
        for (int mt = 0; mt < 2; mt++)
#pragma unroll
            for (int hf = 0; hf < 2; hf++) {
                float rm = fmaxf(fmaxf(s[mt][0][2 * hf], s[mt][0][2 * hf + 1]),
                                 fmaxf(s[mt][1][2 * hf], s[mt][1][2 * hf + 1]));
                rm = fmaxf(rm, __shfl_xor_sync(0xffffffffu, rm, 1));
                rm = fmaxf(rm, __shfl_xor_sync(0xffffffffu, rm, 2));
                if (t4 == 0)
                    redm[(wm * 32 + mt * 16 + grp + hf * 8) * 4 + wn] = rm;
            }
        __syncthreads();

        if (more) {
#pragma unroll
            for (int j = 0; j < 4; j++)
                *(float4*)(&Ks[(pr + j * 16) * KP + pd4]) = ftf4(kreg[j]);
#pragma unroll
            for (int j = 0; j < 4; j++)
                kreg[j] = *(const float4*)(d_K + nbase + (size_t)(pr + j * 16) * 512 + pd4);
        }

        float corr[2][2], mnew[2][2];
#pragma unroll
        for (int mt = 0; mt < 2; mt++)
#pragma unroll
            for (int hf = 0; hf < 2; hf++) {
                int row = wm * 32 + mt * 16 + grp + hf * 8;
                float4 rmv = *(float4*)(&redm[row * 4]);
                float gmax = fmaxf(fmaxf(rmv.x, rmv.y), fmaxf(rmv.z, rmv.w));
                float mn = fmaxf(mst[mt][hf], gmax);
                mnew[mt][hf] = mn;
                corr[mt][hf] = ex2(mst[mt][hf] - mn);
            }

#pragma unroll
        for (int mt = 0; mt < 2; mt++)
#pragma unroll
            for (int hf = 0; hf < 2; hf++) {
                int rowl = wm * 32 + mt * 16 + grp + hf * 8;
                float mn = mnew[mt][hf];
                float rs = 0.f;
#pragma unroll
                for (int nt = 0; nt < 2; nt++) {
                    float p0 = ex2(s[mt][nt][2 * hf]     - mn);
                    float p1 = ex2(s[mt][nt][2 * hf + 1] - mn);
                    rs += p0 + p1;
                    int gb = wn * 16 + nt * 8;
                    ps[rowl * PP + gb + posA]     = ftf(p0);
                    ps[rowl * PP + gb + posA + 2] = ftf(p1);
                }
                rs += __shfl_xor_sync(0xffffffffu, rs, 1);
                rs += __shfl_xor_sync(0xffffffffu, rs, 2);
                if (t4 == 0) reds[rowl * 4 + wn] = rs;
            }
        __syncthreads();

#pragma unroll
        for (int mt = 0; mt < 2; mt++)
#pragma unroll
            for (int hf = 0; hf < 2; hf++) {
                int row = wm * 32 + mt * 16 + grp + hf * 8;
                float4 rsv = *(float4*)(&reds[row * 4]);
                float ls = rsv.x + rsv.y + rsv.z + rsv.w;
                float cr = corr[mt][hf];
                lst[mt][hf] = lst[mt][hf] * cr + ls;
                mst[mt][hf] = mnew[mt][hf];
#pragma unroll
                for (int nt = 0; nt < 2; nt++) {
                    o[mt][nt][2 * hf]     *= cr;
                    o[mt][nt][2 * hf + 1] *= cr;
                }
            }

#pragma unroll
        for (int ks = 0; ks < 8; ks++) {
            int kk = ks * 8;
            uint32_t af[2][4], bf[2][2];
#pragma unroll
            for (int mt = 0; mt < 2; mt++) {
                int row = wm * 32 + mt * 16 + grp;
                float2 p0 = *(float2*)(&ps[row * PP + kk + 2 * t4]);
                float2 p1 = *(float2*)(&ps[(row + 8) * PP + kk + 2 * t4]);
                af[mt][0] = U(p0.x); af[mt][2] = U(p0.y);
                af[mt][1] = U(p1.x); af[mt][3] = U(p1.y);
            }
#pragma unroll
            for (int nt = 0; nt < 2; nt++) {
                int dcol = wn * 16 + nt * 8 + grp;
                bf[nt][0] = U(Vs[(kk + t4) * VP + dcol]);
                bf[nt][1] = U(Vs[(kk + t4 + 4) * VP + dcol]);
            }
#pragma unroll
            for (int mt = 0; mt < 2; mt++)
#pragma unroll
                for (int nt = 0; nt < 2; nt++)
                    mma_tf32(o[mt][nt], af[mt], bf[nt]);
        }
        __syncthreads();

        if (more) {
#pragma unroll
            for (int j = 0; j < 4; j++)
                *(float4*)(&Vs[(pr + j * 16) * VP + pd4]) = ftf4(vreg[j]);
#pragma unroll
            for (int j = 0; j < 4; j++)
                vreg[j] = *(const float4*)(d_V + nbase + (size_t)(pr + j * 16) * 512 + pd4);
        }
    }

#pragma unroll
    for (int mt = 0; mt < 2; mt++)
#pragma unroll
        for (int hf = 0; hf < 2; hf++) {
            int qp = qbase + wm * 32 + mt * 16 + grp + hf * 8;
            float inv = gv2[mt][hf] / lst[mt][hf];
#pragma unroll
            for (int nt = 0; nt < 2; nt++) {
                int dcol = wn * 16 + nt * 8 + 2 * t4;
                size_t ob = (size_t)(b * SEQ + qp) * 512 + hh * 64 + dcol;
                float2 cur = *(float2*)(d_O + ob);
                cur.x += o[mt][nt][2 * hf]     * inv;
                cur.y += o[mt][nt][2 * hf + 1] * inv;
                *(float2*)(d_O + ob) = cur;
            }
        }
}

// ---------------------------------------------------------------------------
extern "C" void kernel_launch(void* const* d_in, const int* in_sizes, int n_in,
                              void* d_out, int out_size)
{
    const float* x  = (const float*)d_in[0];
    const float* Wq = (const float*)d_in[1];
    const float* Wk = (const float*)d_in[2];
    const float* Wv = (const float*)d_in[3];
    const float* Wo = (const float*)d_in[4];
    const float* Wg = (const float*)d_in[5];
    float* y = (float*)d_out;

    cudaFuncSetAttribute(gemm512_tc,
                         cudaFuncAttributeMaxDynamicSharedMemorySize, 71680);
    cudaFuncSetAttribute(cmp_attn_mma,
                         cudaFuncAttributeMaxDynamicSharedMemorySize, 90368);
    cudaFuncSetAttribute(selwin_fused,
                         cudaFuncAttributeMaxDynamicSharedMemorySize, 74752);

    gemm512_tc<<<dim3(4, 64, 3), 256, 71680>>>(x, Wq, Wk, Wv, nullptr, 0);
    gate_compress<<<1024 + 512, 256>>>(x, Wg);
    cmp_attn_mma<<<dim3(64, 8, 2), 256, 90368>>>();
    selwin_fused<<<dim3(64, 8, 2), 256, 74752>>>();
    gemm512_tc<<<dim3(4, 64, 1), 256, 71680>>>(nullptr, Wo, nullptr, nullptr, y, 3);
}

// round 14
// speedup vs baseline: 1.1785x; 1.0476x over previous
#include <cuda_runtime.h>
#include <math.h>
#include <stdint.h>

#define BATCH   2
#define SEQ     4096
#define DMODEL  512
#define NH      8
#define HD      64
#define NC      128
#define NS      64
#define TOPK    16
#define NROWS   (BATCH*SEQ)

// ---------------- scratch ----------------
__device__ float d_Q[NROWS*DMODEL];
__device__ float d_K[NROWS*DMODEL];
__device__ float d_V[NROWS*DMODEL];
__device__ float d_O[NROWS*DMODEL];
__device__ float d_KC[BATCH*NH*NC*HD];
__device__ float d_VC[BATCH*NH*NC*HD];
__device__ float d_G[NROWS*3];
__device__ int   d_SEL[BATCH*NH*NS*TOPK];

// ---------------- tf32 helpers ----------------
__device__ __forceinline__ float ftf(float x) {
    uint32_t u;
    asm("cvt.rna.tf32.f32 %0, %1;" : "=r"(u) : "f"(x));
    return __uint_as_float(u);
}
__device__ __forceinline__ float4 ftf4(float4 v) {
    return make_float4(ftf(v.x), ftf(v.y), ftf(v.z), ftf(v.w));
}
__device__ __forceinline__ float ex2(float x) {
    float r;
    asm("ex2.approx.ftz.f32 %0, %1;" : "=f"(r) : "f"(x));
    return r;
}
__device__ __forceinline__ void mma_tf32(float* c, const uint32_t* a, const uint32_t* b) {
    asm volatile(
        "mma.sync.aligned.m16n8k8.row.col.f32.tf32.tf32.f32 "
        "{%0,%1,%2,%3},{%4,%5,%6,%7},{%8,%9},{%0,%1,%2,%3};\n"
        : "+f"(c[0]), "+f"(c[1]), "+f"(c[2]), "+f"(c[3])
        : "r"(a[0]), "r"(a[1]), "r"(a[2]), "r"(a[3]), "r"(b[0]), "r"(b[1]));
}
__device__ __forceinline__ void split_tf32(float x, uint32_t& hi, uint32_t& lo) {
    float h = ftf(x);
    hi = __float_as_uint(h);
    lo = __float_as_uint(ftf(x - h));
}
#define U(x) __float_as_uint(x)
#define QSCALE 0.18033688011112042f   /* 0.125 * log2(e) */

// ---------------- tf32 GEMM: 128x128 tile, k-slab 32, smem double buffer --
#define GPA 36
#define GPB 136
__global__ __launch_bounds__(256) void gemm512_tc(const float* __restrict__ Aext,
    const float* __restrict__ B0, const float* __restrict__ B1,
    const float* __restrict__ B2, float* __restrict__ Cext, int modeBase)
{
    extern __shared__ float smg[];
    float* As = smg;
    float* Bs = smg + 2 * 128 * GPA;

    int mode = modeBase + blockIdx.z;
    const float* A  = (mode == 3) ? d_O : Aext;
    const float* Bm = (mode == 1) ? B1 : (mode == 2) ? B2 : B0;
    float* C = (mode == 0) ? d_Q : (mode == 1) ? d_K : (mode == 2) ? d_V : Cext;

    int tid = threadIdx.x, lane = tid & 31, w = tid >> 5;
    int grp = lane >> 2, t4 = lane & 3;
    int wm = w & 3, wn = w >> 2;
    int m0 = blockIdx.y * 128, n0 = blockIdx.x * 128;

    int arr[4], arc[4], brr[4], brc[4];
#pragma unroll
    for (int ii = 0; ii < 4; ii++) {
        int i = tid + ii * 256;
        arr[ii] = i >> 3;  arc[ii] = (i & 7) * 4;
        brr[ii] = i >> 5;  brc[ii] = (i & 31) * 4;
    }

    float acc[2][8][4];
#pragma unroll
    for (int mt = 0; mt < 2; mt++)
#pragma unroll
        for (int nt = 0; nt < 8; nt++)
#pragma unroll
            for (int r = 0; r < 4; r++) acc[mt][nt][r] = 0.f;

    float4 areg[4], breg[4];
#pragma unroll
    for (int ii = 0; ii < 4; ii++) {
        areg[ii] = *(const float4*)(A + (size_t)(m0 + arr[ii]) * 512 + arc[ii]);
        breg[ii] = *(const float4*)(Bm + (size_t)brr[ii] * 512 + n0 + brc[ii]);
    }
#pragma unroll
    for (int ii = 0; ii < 4; ii++) {
        *(float4*)(&As[arr[ii] * GPA + arc[ii]]) = ftf4(areg[ii]);
        *(float4*)(&Bs[brr[ii] * GPB + brc[ii]]) = ftf4(breg[ii]);
    }
    __syncthreads();

    for (int s = 0; s < 16; s++) {
        float* Ab = As + (s & 1) * 128 * GPA;
        float* Bb = Bs + (s & 1) * 32 * GPB;
        if (s < 15) {
            int k0 = (s + 1) * 32;
#pragma unroll
            for (int ii = 0; ii < 4; ii++) {
                areg[ii] = *(const float4*)(A + (size_t)(m0 + arr[ii]) * 512 + k0 + arc[ii]);
                breg[ii] = *(const float4*)(Bm + (size_t)(k0 + brr[ii]) * 512 + n0 + brc[ii]);
            }
        }
#pragma unroll
        for (int ks = 0; ks < 4; ks++) {
            int kb = ks * 8;
            uint32_t af[2][4], bf[8][2];
#pragma unroll
            for (int mt = 0; mt < 2; mt++) {
                int row = wm * 32 + mt * 16 + grp;
                af[mt][0] = U(Ab[row * GPA + kb + t4]);
                af[mt][1] = U(Ab[(row + 8) * GPA + kb + t4]);
                af[mt][2] = U(Ab[row * GPA + kb + t4 + 4]);
                af[mt][3] = U(Ab[(row + 8) * GPA + kb + t4 + 4]);
            }
#pragma unroll
            for (int nt = 0; nt < 8; nt++) {
                int col = wn * 64 + nt * 8 + grp;
                bf[nt][0] = U(Bb[(kb + t4) * GPB + col]);
                bf[nt][1] = U(Bb[(kb + t4 + 4) * GPB + col]);
            }
#pragma unroll
            for (int mt = 0; mt < 2; mt++)
#pragma unroll
                for (int nt = 0; nt < 8; nt++)
                    mma_tf32(acc[mt][nt], af[mt], bf[nt]);
        }
        if (s < 15) {
            float* An = As + ((s + 1) & 1) * 128 * GPA;
            float* Bn = Bs + ((s + 1) & 1) * 32 * GPB;
#pragma unroll
            for (int ii = 0; ii < 4; ii++) {
                *(float4*)(&An[arr[ii] * GPA + arc[ii]]) = ftf4(areg[ii]);
                *(float4*)(&Bn[brr[ii] * GPB + brc[ii]]) = ftf4(breg[ii]);
            }
        }
        __syncthreads();
    }
#pragma unroll
    for (int mt = 0; mt < 2; mt++)
#pragma unroll
        for (int nt = 0; nt < 8; nt++) {
            int row = m0 + wm * 32 + mt * 16 + grp;
            int col = n0 + wn * 64 + nt * 8 + 2 * t4;
            *(float2*)(C + (size_t)row * 512 + col) =
                make_float2(acc[mt][nt][0], acc[mt][nt][1]);
            *(float2*)(C + (size_t)(row + 8) * 512 + col) =
                make_float2(acc[mt][nt][2], acc[mt][nt][3]);
        }
}

// ---------------- fused gate + compress (one launch) ----------------
__global__ __launch_bounds__(256) void gate_compress(const float* __restrict__ x,
                                                     const float* __restrict__ Wg)
{
    int blk = blockIdx.x;
    if (blk < 1024) {
        int w = threadIdx.x >> 5, lane = threadIdx.x & 31;
        int row = blk * 8 + w;
        float p0 = 0, p1 = 0, p2 = 0;
#pragma unroll
        for (int c = 0; c < 4; c++) {
            int d = c * 128 + lane * 4;
            float4 xv = *(const float4*)(x + (size_t)row * 512 + d);
            p0 += xv.x * Wg[d * 3]     + xv.y * Wg[d * 3 + 3] +
                  xv.z * Wg[d * 3 + 6] + xv.w * Wg[d * 3 + 9];
            p1 += xv.x * Wg[d * 3 + 1] + xv.y * Wg[d * 3 + 4] +
                  xv.z * Wg[d * 3 + 7] + xv.w * Wg[d * 3 + 10];
            p2 += xv.x * Wg[d * 3 + 2] + xv.y * Wg[d * 3 + 5] +
                  xv.z * Wg[d * 3 + 8] + xv.w * Wg[d * 3 + 11];
        }
#pragma unroll
        for (int o = 16; o; o >>= 1) {
            p0 += __shfl_xor_sync(0xffffffffu, p0, o);
            p1 += __shfl_xor_sync(0xffffffffu, p1, o);
            p2 += __shfl_xor_sync(0xffffffffu, p2, o);
        }
        if (lane == 0) {
            d_G[row * 3 + 0] = 1.f / (1.f + expf(-p0));
            d_G[row * 3 + 1] = 1.f / (1.f + expf(-p1));
            d_G[row * 3 + 2] = 1.f / (1.f + expf(-p2));
        }
    } else {
        int idx = (blk - 1024) * 256 + threadIdx.x;
        int d = idx & 63, n = (idx >> 6) & 127, h = (idx >> 13) & 7, b = idx >> 16;
        const float* kp = d_K + (size_t)(b * SEQ + n * 32) * 512 + h * 64 + d;
        const float* vp = d_V + (size_t)(b * SEQ + n * 32) * 512 + h * 64 + d;
        float ks = 0, vs = 0;
#pragma unroll
        for (int r = 0; r < 32; r++) { ks += kp[r * 512]; vs += vp[r * 512]; }
        d_KC[idx] = ks * (1.f / 32.f);
        d_VC[idx] = vs * (1.f / 32.f);
    }
}

// ---------------- compressed attention + top-k (R7 proven: 3xTF32 QK) -----
#define CQ 68
#define CK 72
#define CS 132
__global__ __launch_bounds__(256) void cmp_attn_mma()
{
    extern __shared__ float sm[];
    float* qs   = sm;
    float* kv   = qs + 64 * CQ;
    float* ps   = kv + 128 * CK;
    float* redm = ps + 64 * CS;
    float* reds = redm + 256;
    float* impb = reds + 256;

    int g = blockIdx.x, h = blockIdx.y, b = blockIdx.z;
    int tid = threadIdx.x, lane = tid & 31, w = tid >> 5;
    int grp = lane >> 2, t4 = lane & 3;
    int wm = w & 1, wn = w >> 1;
    int qbase = g * 64;

    for (int i = tid; i < 1024; i += 256) {
        int r = i >> 4, d4 = (i & 15) * 4;
        float4 v = *(const float4*)(d_Q + (size_t)(b * SEQ + qbase + r) * 512 + h * 64 + d4);
        *(float4*)(&qs[r * CQ + d4]) = v;
    }
    int cbase = ((b * NH + h) * NC) * HD;
    for (int i = tid; i < 2048; i += 256) {
        int r = i >> 4, d4 = (i & 15) * 4;
        float4 v = *(const float4*)(d_KC + cbase + r * 64 + d4);
        *(float4*)(&kv[r * CK + d4]) = v;
    }
    __syncthreads();

    float s[2][4][4];
#pragma unroll
    for (int mt = 0; mt < 2; mt++)
#pragma unroll
        for (int nt = 0; nt < 4; nt++)
#pragma unroll
            for (int r = 0; r < 4; r++) s[mt][nt][r] = 0.f;
#pragma unroll
    for (int ks = 0; ks < 8; ks++) {
        int kk = ks * 8;
        uint32_t ah[2][4], al[2][4], bh[4][2], bl[4][2];
#pragma unroll
        for (int mt = 0; mt < 2; mt++) {
            int row = wm * 32 + mt * 16 + grp;
            split_tf32(qs[row * CQ + kk + t4],           ah[mt][0], al[mt][0]);
            split_tf32(qs[(row + 8) * CQ + kk + t4],     ah[mt][1], al[mt][1]);
            split_tf32(qs[row * CQ + kk + t4 + 4],       ah[mt][2], al[mt][2]);
            split_tf32(qs[(row + 8) * CQ + kk + t4 + 4], ah[mt][3], al[mt][3]);
        }
#pragma unroll
        for (int nt = 0; nt < 4; nt++) {
            int key = wn * 32 + nt * 8 + grp;
            split_tf32(kv[key * CK + kk + t4],     bh[nt][0], bl[nt][0]);
            split_tf32(kv[key * CK + kk + t4 + 4], bh[nt][1], bl[nt][1]);
        }
#pragma unroll
        for (int mt = 0; mt < 2; mt++)
#pragma unroll
            for (int nt = 0; nt < 4; nt++) {
                mma_tf32(s[mt][nt], ah[mt], bl[nt]);
                mma_tf32(s[mt][nt], al[mt], bh[nt]);
                mma_tf32(s[mt][nt], ah[mt], bh[nt]);
            }
    }

    int nval[2][2];
#pragma unroll
    for (int mt = 0; mt < 2; mt++)
#pragma unroll
        for (int hf = 0; hf < 2; hf++) {
            int pos = qbase + wm * 32 + mt * 16 + grp + hf * 8;
            nval[mt][hf] = (pos >= 31) ? ((pos - 31) >> 5) + 1 : 0;
        }
#pragma unroll
    for (int mt = 0; mt < 2; mt++)
#pragma unroll
        for (int nt = 0; nt < 4; nt++)
#pragma unroll
            for (int r = 0; r < 4; r++) {
                int c = wn * 32 + nt * 8 + 2 * t4 + (r & 1);
                bool valid = c < nval[mt][r >> 1];
                s[mt][nt][r] = valid ? s[mt][nt][r] * 0.125f : -1e30f;
            }

#pragma unroll
    for (int mt = 0; mt < 2; mt++)
#pragma unroll
        for (int hf = 0; hf < 2; hf++) {
            float rm = -1e30f;
#pragma unroll
            for (int nt = 0; nt < 4; nt++)
                rm = fmaxf(rm, fmaxf(s[mt][nt][2 * hf], s[mt][nt][2 * hf + 1]));
            rm = fmaxf(rm, __shfl_xor_sync(0xffffffffu, rm, 1));
            rm = fmaxf(rm, __shfl_xor_sync(0xffffffffu, rm, 2));
            if (t4 == 0)
                redm[(wm * 32 + mt * 16 + grp + hf * 8) * 4 + wn] = rm;
        }
    __syncthreads();

    for (int i = tid; i < 2048; i += 256) {
        int r = i >> 4, d4 = (i & 15) * 4;
        float4 v = *(const float4*)(d_VC + cbase + r * 64 + d4);
        *(float4*)(&kv[r * CK + d4]) = v;
    }
#pragma unroll
    for (int mt = 0; mt < 2; mt++)
#pragma unroll
        for (int hf = 0; hf < 2; hf++) {
            int row = wm * 32 + mt * 16 + grp + hf * 8;
            float4 rmv = *(float4*)(&redm[row * 4]);
            float gmax = fmaxf(fmaxf(rmv.x, rmv.y), fmaxf(rmv.z, rmv.w));
            float rs = 0.f;
#pragma unroll
            for (int nt = 0; nt < 4; nt++) {
                float e0 = __expf(s[mt][nt][2 * hf]     - gmax);
                float e1 = __expf(s[mt][nt][2 * hf + 1] - gmax);
                s[mt][nt][2 * hf] = e0;
                s[mt][nt][2 * hf + 1] = e1;
                rs += e0 + e1;
            }
            rs += __shfl_xor_sync(0xffffffffu, rs, 1);
            rs += __shfl_xor_sync(0xffffffffu, rs, 2);
            if (t4 == 0) reds[row * 4 + wn] = rs;
        }
    __syncthreads();

#pragma unroll
    for (int mt = 0; mt < 2; mt++)
#pragma unroll
        for (int hf = 0; hf < 2; hf++) {
            int row = wm * 32 + mt * 16 + grp + hf * 8;
            float4 rsv = *(float4*)(&reds[row * 4]);
            float tot = rsv.x + rsv.y + rsv.z + rsv.w;
            float inv = (nval[mt][hf] > 0) ? 1.f / tot : 0.f;
#pragma unroll
            for (int nt = 0; nt < 4; nt++) {
                int col = wn * 32 + nt * 8 + 2 * t4;
                ps[row * CS + col]     = s[mt][nt][2 * hf]     * inv;
                ps[row * CS + col + 1] = s[mt][nt][2 * hf + 1] * inv;
            }
        }
    __syncthreads();

    float o[2][2][4];
#pragma unroll
    for (int mt = 0; mt < 2; mt++)
#pragma unroll
        for (int nt = 0; nt < 2; nt++)
#pragma unroll
            for (int r = 0; r < 4; r++) o[mt][nt][r] = 0.f;
#pragma unroll
    for (int ks = 0; ks < 16; ks++) {
        int kk = ks * 8;
        uint32_t af[2][4], bf[2][2];
#pragma unroll
        for (int mt = 0; mt < 2; mt++) {
            int row = wm * 32 + mt * 16 + grp;
            af[mt][0] = U(ftf(ps[row * CS + kk + t4]));
            af[mt][1] = U(ftf(ps[(row + 8) * CS + kk + t4]));
            af[mt][2] = U(ftf(ps[row * CS + kk + t4 + 4]));
            af[mt][3] = U(ftf(ps[(row + 8) * CS + kk + t4 + 4]));
        }
#pragma unroll
        for (int nt = 0; nt < 2; nt++) {
            int dcol = wn * 16 + nt * 8 + grp;
            bf[nt][0] = U(ftf(kv[(kk + t4) * CK + dcol]));
            bf[nt][1] = U(ftf(kv[(kk + t4 + 4) * CK + dcol]));
        }
#pragma unroll
        for (int mt = 0; mt < 2; mt++)
#pragma unroll
            for (int nt = 0; nt < 2; nt++)
                mma_tf32(o[mt][nt], af[mt], bf[nt]);
    }

#pragma unroll
    for (int mt = 0; mt < 2; mt++)
#pragma unroll
        for (int hf = 0; hf < 2; hf++) {
            int qp = qbase + wm * 32 + mt * 16 + grp + hf * 8;
            float g0 = d_G[(b * SEQ + qp) * 3 + 0];
#pragma unroll
            for (int nt = 0; nt < 2; nt++) {
                int dcol = wn * 16 + nt * 8 + 2 * t4;
                size_t ob = (size_t)(b * SEQ + qp) * 512 + h * 64 + dcol;
                *(float2*)(d_O + ob) = make_float2(o[mt][nt][2 * hf] * g0,
                                                   o[mt][nt][2 * hf + 1] * g0);
            }
        }
    __syncthreads();

    if (tid < 64) {
        float v = 0.f;
        for (int q = 0; q < 64; q++)
            v += ps[q * CS + 2 * tid] + ps[q * CS + 2 * tid + 1];
        impb[tid] = v;
    }
    __syncthreads();
    if (w == 0) {
        int j0 = lane, j1 = lane + 32;
        float v0 = (j0 <= g) ? impb[j0] + (j0 == g ? 1e9f : 0.f) : -1e30f;
        float v1 = (j1 <= g) ? impb[j1] + (j1 == g ? 1e9f : 0.f) : -1e30f;
        int selbase = ((b * NH + h) * NS + g) * TOPK;
        for (int r = 0; r < TOPK; r++) {
            float bv; int bi;
            if (v0 >= v1) { bv = v0; bi = j0; } else { bv = v1; bi = j1; }
#pragma unroll
            for (int o2 = 16; o2; o2 >>= 1) {
                float ov = __shfl_xor_sync(0xffffffffu, bv, o2);
                int   oi = __shfl_xor_sync(0xffffffffu, bi, o2);
                if (ov > bv || (ov == bv && oi < bi)) { bv = ov; bi = oi; }
            }
            if (lane == 0) d_SEL[selbase + r] = bi;
            if (bi == j0) v0 = -3e30f;
            if (bi == j1) v1 = -3e30f;
        }
    }
}

// ---------------- fused sel+win flash attention -----------------------------
// Tile list in SHARED memory (was per-thread local array -> LDL/STL traffic).
// Uniform mask-skip branch for fully-valid tiles.
#define QP 72
#define KP 68
#define VP 72
#define PP 72
__global__ void __launch_bounds__(256) selwin_fused()
{
    extern __shared__ float sm[];
    float* qs   = sm;                 // 64*72 paired (pre-scaled by QSCALE)
    float* Ks   = qs + 64 * QP;       // 64*68
    float* Vs   = Ks + 64 * KP;       // 64*72
    float* ps   = Vs + 64 * VP;       // 64*72 paired
    float* redm = ps + 64 * PP;       // 64*4
    float* reds = redm + 256;         // 64*4

    __shared__ int skb[26];
    __shared__ int sphase[2];         // [0]=nsel, [1]=ntot

    int g = blockIdx.x, hh = blockIdx.y, b = blockIdx.z;
    int tid = threadIdx.x, lane = tid & 31, w = tid >> 5;
    int grp = lane >> 2, t4 = lane & 3;
    int wm = w & 1, wn = w >> 1;
    int qbase = g * 64;

    if (tid == 0) {
        int selbase = ((b * NH + hh) * NS + g) * TOPK;
        int n = 0;
#pragma unroll
        for (int it = 0; it < TOPK; it++) {
            int kb = d_SEL[selbase + it];
            if (kb <= g) skb[n++] = kb;
        }
        sphase[0] = n;
        int st = (g > 8) ? g - 8 : 0;
        for (int kb = st; kb <= g; kb++) skb[n++] = kb;
        sphase[1] = n;
    }

#pragma unroll
    for (int ii = 0; ii < 2; ii++) {
        int i = tid + ii * 256;
        int r = i >> 3, g8 = (i & 7) * 8;
        const float* src = d_Q + (size_t)(b * SEQ + qbase + r) * 512 + hh * 64 + g8;
        float4 lo = *(const float4*)src;
        float4 hi = *(const float4*)(src + 4);
        float2* dst = (float2*)(&qs[r * QP + g8]);
        dst[0] = make_float2(ftf(lo.x * QSCALE), ftf(hi.x * QSCALE));
        dst[1] = make_float2(ftf(lo.y * QSCALE), ftf(hi.y * QSCALE));
        dst[2] = make_float2(ftf(lo.z * QSCALE), ftf(hi.z * QSCALE));
        dst[3] = make_float2(ftf(lo.w * QSCALE), ftf(hi.w * QSCALE));
    }
    __syncthreads();                  // skb/sphase + qs visible

    int nsel = sphase[0], ntot = sphase[1];

    float gv1[2][2], gv2[2][2];
#pragma unroll
    for (int mt = 0; mt < 2; mt++)
#pragma unroll
        for (int hf = 0; hf < 2; hf++) {
            int qp = qbase + wm * 32 + mt * 16 + grp + hf * 8;
            gv1[mt][hf] = d_G[(b * SEQ + qp) * 3 + 1];
            gv2[mt][hf] = d_G[(b * SEQ + qp) * 3 + 2];
        }

    float o[2][2][4];
#pragma unroll
    for (int mt = 0; mt < 2; mt++)
#pragma unroll
        for (int nt = 0; nt < 2; nt++)
#pragma unroll
            for (int r = 0; r < 4; r++) o[mt][nt][r] = 0.f;
    float mst[2][2], lst[2][2];
#pragma unroll
    for (int mt = 0; mt < 2; mt++)
#pragma unroll
        for (int hf = 0; hf < 2; hf++) { mst[mt][hf] = -1e30f; lst[mt][hf] = 0.f; }

    float4 kreg[4], vreg[4];
    int pr = tid >> 4, pd4 = (tid & 15) * 4;
    {
        size_t kbase = (size_t)(b * SEQ + skb[0] * 64) * 512 + hh * 64;
#pragma unroll
        for (int j = 0; j < 4; j++) {
            kreg[j] = *(const float4*)(d_K + kbase + (size_t)(pr + j * 16) * 512 + pd4);
            vreg[j] = *(const float4*)(d_V + kbase + (size_t)(pr + j * 16) * 512 + pd4);
        }
#pragma unroll
        for (int j = 0; j < 4; j++) {
            int r = pr + j * 16;
            *(float4*)(&Ks[r * KP + pd4]) = ftf4(kreg[j]);
            *(float4*)(&Vs[r * VP + pd4]) = ftf4(vreg[j]);
        }
        int nb = (ntot > 1) ? 1 : 0;
        size_t kbase1 = (size_t)(b * SEQ + skb[nb] * 64) * 512 + hh * 64;
#pragma unroll
        for (int j = 0; j < 4; j++) {
            kreg[j] = *(const float4*)(d_K + kbase1 + (size_t)(pr + j * 16) * 512 + pd4);
            vreg[j] = *(const float4*)(d_V + kbase1 + (size_t)(pr + j * 16) * 512 + pd4);
        }
    }
    __syncthreads();

    int posA = ((t4 & 1) << 2) + (t4 >> 1);

    for (int t = 0; t < ntot; t++) {
        if (t == nsel) {
#pragma unroll
            for (int mt = 0; mt < 2; mt++)
#pragma unroll
                for (int hf = 0; hf < 2; hf++) {
                    int qp = qbase + wm * 32 + mt * 16 + grp + hf * 8;
                    float inv = gv1[mt][hf] / lst[mt][hf];
#pragma unroll
                    for (int nt = 0; nt < 2; nt++) {
                        int dcol = wn * 16 + nt * 8 + 2 * t4;
                        size_t ob = (size_t)(b * SEQ + qp) * 512 + hh * 64 + dcol;
                        float2 cur = *(float2*)(d_O + ob);
                        cur.x += o[mt][nt][2 * hf]     * inv;
                        cur.y += o[mt][nt][2 * hf + 1] * inv;
                        *(float2*)(d_O + ob) = cur;
                        o[mt][nt][2 * hf] = 0.f; o[mt][nt][2 * hf + 1] = 0.f;
                    }
                    mst[mt][hf] = -1e30f; lst[mt][hf] = 0.f;
                }
        }
        int kb = skb[t];
        bool winph = (t >= nsel);
        bool more = (t + 1 < ntot);
        int nidx = (t + 2 < ntot) ? t + 2 : ntot - 1;
        size_t nbase = (size_t)(b * SEQ + skb[nidx] * 64) * 512 + hh * 64;

        float s[2][2][4];
#pragma unroll
        for (int mt = 0; mt < 2; mt++)
#pragma unroll
            for (int nt = 0; nt < 2; nt++)
#pragma unroll
                for (int r = 0; r < 4; r++) s[mt][nt][r] = 0.f;
#pragma unroll
        for (int ks = 0; ks < 8; ks++) {
            int kk = ks * 8;
            uint32_t af[2][4], bf[2][2];
#pragma unroll
            for (int mt = 0; mt < 2; mt++) {
                int row = wm * 32 + mt * 16 + grp;
                float2 a0 = *(float2*)(&qs[row * QP + kk + 2 * t4]);
                float2 a1 = *(float2*)(&qs[(row + 8) * QP + kk + 2 * t4]);
                af[mt][0] = U(a0.x); af[mt][2] = U(a0.y);
                af[mt][1] = U(a1.x); af[mt][3] = U(a1.y);
            }
#pragma unroll
            for (int nt = 0; nt < 2; nt++) {
                int key = wn * 16 + nt * 8 + grp;
                bf[nt][0] = U(Ks[key * KP + kk + t4]);
                bf[nt][1] = U(Ks[key * KP + kk + t4 + 4]);
            }
#pragma unroll
            for (int mt = 0; mt < 2; mt++)
#pragma unroll
                for (int nt = 0; nt < 2; nt++)
                    mma_tf32(s[mt][nt], af[mt], bf[nt]);
        }

        // mask only partially-valid tiles (uniform branch):
        // fully valid iff kb < g (all causal) and, in window phase, kb >= g-7.
        bool needmask = (kb >= g) || (winph && kb < g - 7);
        if (needmask) {
#pragma unroll
            for (int mt = 0; mt < 2; mt++)
#pragma unroll
                for (int nt = 0; nt < 2; nt++)
#pragma unroll
                    for (int r = 0; r < 4; r++) {
                        int qp = qbase + wm * 32 + mt * 16 + grp + (r >> 1) * 8;
                        int kp = kb * 64 + wn * 16 + nt * 8 + 2 * t4 + (r & 1);
                        bool valid = (kp <= qp) && (!winph || (kp + 512 > qp));
                        s[mt][nt][r] = valid ? s[mt][nt][r] : -1e30f;
                    }
        }

#pragma unroll
        for (int mt = 0; mt < 2; mt++)
#pragma unroll
            for (int hf = 0; hf < 2; hf++) {
                float rm = fmaxf(fmaxf(s[mt][0][2 * hf], s[mt][0][2 * hf + 1]),
                                 fmaxf(s[mt][1][2 * hf], s[mt][1][2 * hf + 1]));
                rm = fmaxf(rm, __shfl_xor_sync(0xffffffffu, rm, 1));
                rm = fmaxf(rm, __shfl_xor_sync(0xffffffffu, rm, 2));
                if (t4 == 0)
                    redm[(wm * 32 + mt * 16 + grp + hf * 8) * 4 + wn] = rm;
            }
        __syncthreads();

        if (more) {
#pragma unroll
            for (int j = 0; j < 4; j++)
                *(float4*)(&Ks[(pr + j * 16) * KP + pd4]) = ftf4(kreg[j]);
#pragma unroll
            for (int j = 0; j < 4; j++)
                kreg[j] = *(const float4*)(d_K + nbase + (size_t)(pr + j * 16) * 512 + pd4);
        }

        float corr[2][2], mnew[2][2];
#pragma unroll
        for (int mt = 0; mt < 2; mt++)
#pragma unroll
            for (int hf = 0; hf < 2; hf++) {
                int row = wm * 32 + mt * 16 + grp + hf * 8;
                float4 rmv = *(float4*)(&redm[row * 4]);
                float gmax = fmaxf(fmaxf(rmv.x, rmv.y), fmaxf(rmv.z, rmv.w));
                float mn = fmaxf(mst[mt][hf], gmax);
                mnew[mt][hf] = mn;
                corr[mt][hf] = ex2(mst[mt][hf] - mn);
            }

#pragma unroll
        for (int mt = 0; mt < 2; mt++)
#pragma unroll
            for (int hf = 0; hf < 2; hf++) {
                int rowl = wm * 32 + mt * 16 + grp + hf * 8;
                float mn = mnew[mt][hf];
                float rs = 0.f;
#pragma unroll
                for (int nt = 0; nt < 2; nt++) {
                    float p0 = ex2(s[mt][nt][2 * hf]     - mn);
                    float p1 = ex2(s[mt][nt][2 * hf + 1] - mn);
                    rs += p0 + p1;
                    int gb = wn * 16 + nt * 8;
                    ps[rowl * PP + gb + posA]     = ftf(p0);
                    ps[rowl * PP + gb + posA + 2] = ftf(p1);
                }
                rs += __shfl_xor_sync(0xffffffffu, rs, 1);
                rs += __shfl_xor_sync(0xffffffffu, rs, 2);
                if (t4 == 0) reds[rowl * 4 + wn] = rs;
            }
        __syncthreads();

#pragma unroll
        for (int mt = 0; mt < 2; mt++)
#pragma unroll
            for (int hf = 0; hf < 2; hf++) {
                int row = wm * 32 + mt * 16 + grp + hf * 8;
                float4 rsv = *(float4*)(&reds[row * 4]);
                float ls = rsv.x + rsv.y + rsv.z + rsv.w;
                float cr = corr[mt][hf];
                lst[mt][hf] = lst[mt][hf] * cr + ls;
                mst[mt][hf] = mnew[mt][hf];
#pragma unroll
                for (int nt = 0; nt < 2; nt++) {
                    o[mt][nt][2 * hf]     *= cr;
                    o[mt][nt][2 * hf + 1] *= cr;
                }
            }

#pragma unroll
        for (int ks = 0; ks < 8; ks++) {
            int kk = ks * 8;
            uint32_t af[2][4], bf[2][2];
#pragma unroll
            for (int mt = 0; mt < 2; mt++) {
                int row = wm * 32 + mt * 16 + grp;
                float2 p0 = *(float2*)(&ps[row * PP + kk + 2 * t4]);
                float2 p1 = *(float2*)(&ps[(row + 8) * PP + kk + 2 * t4]);
                af[mt][0] = U(p0.x); af[mt][2] = U(p0.y);
                af[mt][1] = U(p1.x); af[mt][3] = U(p1.y);
            }
#pragma unroll
            for (int nt = 0; nt < 2; nt++) {
                int dcol = wn * 16 + nt * 8 + grp;
                bf[nt][0] = U(Vs[(kk + t4) * VP + dcol]);
                bf[nt][1] = U(Vs[(kk + t4 + 4) * VP + dcol]);
            }
#pragma unroll
            for (int mt = 0; mt < 2; mt++)
#pragma unroll
                for (int nt = 0; nt < 2; nt++)
                    mma_tf32(o[mt][nt], af[mt], bf[nt]);
        }
        __syncthreads();

        if (more) {
#pragma unroll
            for (int j = 0; j < 4; j++)
                *(float4*)(&Vs[(pr + j * 16) * VP + pd4]) = ftf4(vreg[j]);
#pragma unroll
            for (int j = 0; j < 4; j++)
                vreg[j] = *(const float4*)(d_V + nbase + (size_t)(pr + j * 16) * 512 + pd4);
        }
    }

#pragma unroll
    for (int mt = 0; mt < 2; mt++)
#pragma unroll
        for (int hf = 0; hf < 2; hf++) {
            int qp = qbase + wm * 32 + mt * 16 + grp + hf * 8;
            float inv = gv2[mt][hf] / lst[mt][hf];
#pragma unroll
            for (int nt = 0; nt < 2; nt++) {
                int dcol = wn * 16 + nt * 8 + 2 * t4;
                size_t ob = (size_t)(b * SEQ + qp) * 512 + hh * 64 + dcol;
                float2 cur = *(float2*)(d_O + ob);
                cur.x += o[mt][nt][2 * hf]     * inv;
                cur.y += o[mt][nt][2 * hf + 1] * inv;
                *(float2*)(d_O + ob) = cur;
            }
        }
}

// ---------------------------------------------------------------------------
extern "C" void kernel_launch(void* const* d_in, const int* in_sizes, int n_in,
                              void* d_out, int out_size)
{
    const float* x  = (const float*)d_in[0];
    const float* Wq = (const float*)d_in[1];
    const float* Wk = (const float*)d_in[2];
    const float* Wv = (const float*)d_in[3];
    const float* Wo = (const float*)d_in[4];
    const float* Wg = (const float*)d_in[5];
    float* y = (float*)d_out;

    cudaFuncSetAttribute(gemm512_tc,
                         cudaFuncAttributeMaxDynamicSharedMemorySize, 71680);
    cudaFuncSetAttribute(cmp_attn_mma,
                         cudaFuncAttributeMaxDynamicSharedMemorySize, 90368);
    cudaFuncSetAttribute(selwin_fused,
                         cudaFuncAttributeMaxDynamicSharedMemorySize, 74752);

    gemm512_tc<<<dim3(4, 64, 3), 256, 71680>>>(x, Wq, Wk, Wv, nullptr, 0);
    gate_compress<<<1024 + 512, 256>>>(x, Wg);
    cmp_attn_mma<<<dim3(64, 8, 2), 256, 90368>>>();
    selwin_fused<<<dim3(64, 8, 2), 256, 74752>>>();
    gemm512_tc<<<dim3(4, 64, 1), 256, 71680>>>(nullptr, Wo, nullptr, nullptr, y, 3);
}

// round 15
// speedup vs baseline: 1.2125x; 1.0288x over previous
#include <cuda_runtime.h>
#include <math.h>
#include <stdint.h>

#define BATCH   2
#define SEQ     4096
#define DMODEL  512
#define NH      8
#define HD      64
#define NC      128
#define NS      64
#define TOPK    16
#define NROWS   (BATCH*SEQ)

// ---------------- scratch ----------------
__device__ float d_Q[NROWS*DMODEL];
__device__ float d_K[NROWS*DMODEL];
__device__ float d_V[NROWS*DMODEL];
__device__ float d_O[NROWS*DMODEL];
__device__ float d_KC[BATCH*NH*NC*HD];
__device__ float d_VC[BATCH*NH*NC*HD];
__device__ float d_G[NROWS*3];
__device__ int   d_SEL[BATCH*NH*NS*TOPK];

// ---------------- tf32 helpers ----------------
__device__ __forceinline__ float ftf(float x) {
    uint32_t u;
    asm("cvt.rna.tf32.f32 %0, %1;" : "=r"(u) : "f"(x));
    return __uint_as_float(u);
}
__device__ __forceinline__ float4 ftf4(float4 v) {
    return make_float4(ftf(v.x), ftf(v.y), ftf(v.z), ftf(v.w));
}
__device__ __forceinline__ float ex2(float x) {
    float r;
    asm("ex2.approx.ftz.f32 %0, %1;" : "=f"(r) : "f"(x));
    return r;
}
__device__ __forceinline__ void mma_tf32(float* c, const uint32_t* a, const uint32_t* b) {
    asm volatile(
        "mma.sync.aligned.m16n8k8.row.col.f32.tf32.tf32.f32 "
        "{%0,%1,%2,%3},{%4,%5,%6,%7},{%8,%9},{%0,%1,%2,%3};\n"
        : "+f"(c[0]), "+f"(c[1]), "+f"(c[2]), "+f"(c[3])
        : "r"(a[0]), "r"(a[1]), "r"(a[2]), "r"(a[3]), "r"(b[0]), "r"(b[1]));
}
__device__ __forceinline__ void split_tf32(float x, uint32_t& hi, uint32_t& lo) {
    float h = ftf(x);
    hi = __float_as_uint(h);
    lo = __float_as_uint(ftf(x - h));
}
__device__ __forceinline__ uint32_t sptr(const void* p) {
    return (uint32_t)__cvta_generic_to_shared(p);
}
__device__ __forceinline__ void cpa16(uint32_t dst, const float* src) {
    asm volatile("cp.async.cg.shared.global [%0], [%1], 16;" :: "r"(dst), "l"(src));
}
#define CP_COMMIT() asm volatile("cp.async.commit_group;")
#define CP_WAIT0()  asm volatile("cp.async.wait_group 0;" ::: "memory")
#define CP_WAIT1()  asm volatile("cp.async.wait_group 1;" ::: "memory")
#define U(x) __float_as_uint(x)
#define QSCALE 0.18033688011112042f   /* 0.125 * log2(e) */

// ---------------- tf32 GEMM: 128x128 tile, k-slab 32, smem double buffer --
#define GPA 36
#define GPB 136
__global__ __launch_bounds__(256) void gemm512_tc(const float* __restrict__ Aext,
    const float* __restrict__ B0, const float* __restrict__ B1,
    const float* __restrict__ B2, float* __restrict__ Cext, int modeBase)
{
    extern __shared__ float smg[];
    float* As = smg;
    float* Bs = smg + 2 * 128 * GPA;

    int mode = modeBase + blockIdx.z;
    const float* A  = (mode == 3) ? d_O : Aext;
    const float* Bm = (mode == 1) ? B1 : (mode == 2) ? B2 : B0;
    float* C = (mode == 0) ? d_Q : (mode == 1) ? d_K : (mode == 2) ? d_V : Cext;

    int tid = threadIdx.x, lane = tid & 31, w = tid >> 5;
    int grp = lane >> 2, t4 = lane & 3;
    int wm = w & 3, wn = w >> 2;
    int m0 = blockIdx.y * 128, n0 = blockIdx.x * 128;

    int arr[4], arc[4], brr[4], brc[4];
#pragma unroll
    for (int ii = 0; ii < 4; ii++) {
        int i = tid + ii * 256;
        arr[ii] = i >> 3;  arc[ii] = (i & 7) * 4;
        brr[ii] = i >> 5;  brc[ii] = (i & 31) * 4;
    }

    float acc[2][8][4];
#pragma unroll
    for (int mt = 0; mt < 2; mt++)
#pragma unroll
        for (int nt = 0; nt < 8; nt++)
#pragma unroll
            for (int r = 0; r < 4; r++) acc[mt][nt][r] = 0.f;

    float4 areg[4], breg[4];
#pragma unroll
    for (int ii = 0; ii < 4; ii++) {
        areg[ii] = *(const float4*)(A + (size_t)(m0 + arr[ii]) * 512 + arc[ii]);
        breg[ii] = *(const float4*)(Bm + (size_t)brr[ii] * 512 + n0 + brc[ii]);
    }
#pragma unroll
    for (int ii = 0; ii < 4; ii++) {
        *(float4*)(&As[arr[ii] * GPA + arc[ii]]) = ftf4(areg[ii]);
        *(float4*)(&Bs[brr[ii] * GPB + brc[ii]]) = ftf4(breg[ii]);
    }
    __syncthreads();

    for (int s = 0; s < 16; s++) {
        float* Ab = As + (s & 1) * 128 * GPA;
        float* Bb = Bs + (s & 1) * 32 * GPB;
        if (s < 15) {
            int k0 = (s + 1) * 32;
#pragma unroll
            for (int ii = 0; ii < 4; ii++) {
                areg[ii] = *(const float4*)(A + (size_t)(m0 + arr[ii]) * 512 + k0 + arc[ii]);
                breg[ii] = *(const float4*)(Bm + (size_t)(k0 + brr[ii]) * 512 + n0 + brc[ii]);
            }
        }
#pragma unroll
        for (int ks = 0; ks < 4; ks++) {
            int kb = ks * 8;
            uint32_t af[2][4], bf[8][2];
#pragma unroll
            for (int mt = 0; mt < 2; mt++) {
                int row = wm * 32 + mt * 16 + grp;
                af[mt][0] = U(Ab[row * GPA + kb + t4]);
                af[mt][1] = U(Ab[(row + 8) * GPA + kb + t4]);
                af[mt][2] = U(Ab[row * GPA + kb + t4 + 4]);
                af[mt][3] = U(Ab[(row + 8) * GPA + kb + t4 + 4]);
            }
#pragma unroll
            for (int nt = 0; nt < 8; nt++) {
                int col = wn * 64 + nt * 8 + grp;
                bf[nt][0] = U(Bb[(kb + t4) * GPB + col]);
                bf[nt][1] = U(Bb[(kb + t4 + 4) * GPB + col]);
            }
#pragma unroll
            for (int mt = 0; mt < 2; mt++)
#pragma unroll
                for (int nt = 0; nt < 8; nt++)
                    mma_tf32(acc[mt][nt], af[mt], bf[nt]);
        }
        if (s < 15) {
            float* An = As + ((s + 1) & 1) * 128 * GPA;
            float* Bn = Bs + ((s + 1) & 1) * 32 * GPB;
#pragma unroll
            for (int ii = 0; ii < 4; ii++) {
                *(float4*)(&An[arr[ii] * GPA + arc[ii]]) = ftf4(areg[ii]);
                *(float4*)(&Bn[brr[ii] * GPB + brc[ii]]) = ftf4(breg[ii]);
            }
        }
        __syncthreads();
    }
#pragma unroll
    for (int mt = 0; mt < 2; mt++)
#pragma unroll
        for (int nt = 0; nt < 8; nt++) {
            int row = m0 + wm * 32 + mt * 16 + grp;
            int col = n0 + wn * 64 + nt * 8 + 2 * t4;
            *(float2*)(C + (size_t)row * 512 + col) =
                make_float2(acc[mt][nt][0], acc[mt][nt][1]);
            *(float2*)(C + (size_t)(row + 8) * 512 + col) =
                make_float2(acc[mt][nt][2], acc[mt][nt][3]);
        }
}

// ---------------- fused gate + compress (one launch) ----------------
__global__ __launch_bounds__(256) void gate_compress(const float* __restrict__ x,
                                                     const float* __restrict__ Wg)
{
    int blk = blockIdx.x;
    if (blk < 1024) {
        int w = threadIdx.x >> 5, lane = threadIdx.x & 31;
        int row = blk * 8 + w;
        float p0 = 0, p1 = 0, p2 = 0;
#pragma unroll
        for (int c = 0; c < 4; c++) {
            int d = c * 128 + lane * 4;
            float4 xv = *(const float4*)(x + (size_t)row * 512 + d);
            p0 += xv.x * Wg[d * 3]     + xv.y * Wg[d * 3 + 3] +
                  xv.z * Wg[d * 3 + 6] + xv.w * Wg[d * 3 + 9];
            p1 += xv.x * Wg[d * 3 + 1] + xv.y * Wg[d * 3 + 4] +
                  xv.z * Wg[d * 3 + 7] + xv.w * Wg[d * 3 + 10];
            p2 += xv.x * Wg[d * 3 + 2] + xv.y * Wg[d * 3 + 5] +
                  xv.z * Wg[d * 3 + 8] + xv.w * Wg[d * 3 + 11];
        }
#pragma unroll
        for (int o = 16; o; o >>= 1) {
            p0 += __shfl_xor_sync(0xffffffffu, p0, o);
            p1 += __shfl_xor_sync(0xffffffffu, p1, o);
            p2 += __shfl_xor_sync(0xffffffffu, p2, o);
        }
        if (lane == 0) {
            d_G[row * 3 + 0] = 1.f / (1.f + expf(-p0));
            d_G[row * 3 + 1] = 1.f / (1.f + expf(-p1));
            d_G[row * 3 + 2] = 1.f / (1.f + expf(-p2));
        }
    } else {
        int idx = (blk - 1024) * 256 + threadIdx.x;
        int d = idx & 63, n = (idx >> 6) & 127, h = (idx >> 13) & 7, b = idx >> 16;
        const float* kp = d_K + (size_t)(b * SEQ + n * 32) * 512 + h * 64 + d;
        const float* vp = d_V + (size_t)(b * SEQ + n * 32) * 512 + h * 64 + d;
        float ks = 0, vs = 0;
#pragma unroll
        for (int r = 0; r < 32; r++) { ks += kp[r * 512]; vs += vp[r * 512]; }
        d_KC[idx] = ks * (1.f / 32.f);
        d_VC[idx] = vs * (1.f / 32.f);
    }
}

// ---------------- compressed attention + top-k (R7 proven: 3xTF32 QK) -----
#define CQ 68
#define CK 72
#define CS 132
__global__ __launch_bounds__(256) void cmp_attn_mma()
{
    extern __shared__ float sm[];
    float* qs   = sm;
    float* kv   = qs + 64 * CQ;
    float* ps   = kv + 128 * CK;
    float* redm = ps + 64 * CS;
    float* reds = redm + 256;
    float* impb = reds + 256;

    int g = blockIdx.x, h = blockIdx.y, b = blockIdx.z;
    int tid = threadIdx.x, lane = tid & 31, w = tid >> 5;
    int grp = lane >> 2, t4 = lane & 3;
    int wm = w & 1, wn = w >> 1;
    int qbase = g * 64;

    for (int i = tid; i < 1024; i += 256) {
        int r = i >> 4, d4 = (i & 15) * 4;
        float4 v = *(const float4*)(d_Q + (size_t)(b * SEQ + qbase + r) * 512 + h * 64 + d4);
        *(float4*)(&qs[r * CQ + d4]) = v;
    }
    int cbase = ((b * NH + h) * NC) * HD;
    for (int i = tid; i < 2048; i += 256) {
        int r = i >> 4, d4 = (i & 15) * 4;
        float4 v = *(const float4*)(d_KC + cbase + r * 64 + d4);
        *(float4*)(&kv[r * CK + d4]) = v;
    }
    __syncthreads();

    float s[2][4][4];
#pragma unroll
    for (int mt = 0; mt < 2; mt++)
#pragma unroll
        for (int nt = 0; nt < 4; nt++)
#pragma unroll
            for (int r = 0; r < 4; r++) s[mt][nt][r] = 0.f;
#pragma unroll
    for (int ks = 0; ks < 8; ks++) {
        int kk = ks * 8;
        uint32_t ah[2][4], al[2][4], bh[4][2], bl[4][2];
#pragma unroll
        for (int mt = 0; mt < 2; mt++) {
            int row = wm * 32 + mt * 16 + grp;
            split_tf32(qs[row * CQ + kk + t4],           ah[mt][0], al[mt][0]);
            split_tf32(qs[(row + 8) * CQ + kk + t4],     ah[mt][1], al[mt][1]);
            split_tf32(qs[row * CQ + kk + t4 + 4],       ah[mt][2], al[mt][2]);
            split_tf32(qs[(row + 8) * CQ + kk + t4 + 4], ah[mt][3], al[mt][3]);
        }
#pragma unroll
        for (int nt = 0; nt < 4; nt++) {
            int key = wn * 32 + nt * 8 + grp;
            split_tf32(kv[key * CK + kk + t4],     bh[nt][0], bl[nt][0]);
            split_tf32(kv[key * CK + kk + t4 + 4], bh[nt][1], bl[nt][1]);
        }
#pragma unroll
        for (int mt = 0; mt < 2; mt++)
#pragma unroll
            for (int nt = 0; nt < 4; nt++) {
                mma_tf32(s[mt][nt], ah[mt], bl[nt]);
                mma_tf32(s[mt][nt], al[mt], bh[nt]);
                mma_tf32(s[mt][nt], ah[mt], bh[nt]);
            }
    }

    int nval[2][2];
#pragma unroll
    for (int mt = 0; mt < 2; mt++)
#pragma unroll
        for (int hf = 0; hf < 2; hf++) {
            int pos = qbase + wm * 32 + mt * 16 + grp + hf * 8;
            nval[mt][hf] = (pos >= 31) ? ((pos - 31) >> 5) + 1 : 0;
        }
#pragma unroll
    for (int mt = 0; mt < 2; mt++)
#pragma unroll
        for (int nt = 0; nt < 4; nt++)
#pragma unroll
            for (int r = 0; r < 4; r++) {
                int c = wn * 32 + nt * 8 + 2 * t4 + (r & 1);
                bool valid = c < nval[mt][r >> 1];
                s[mt][nt][r] = valid ? s[mt][nt][r] * 0.125f : -1e30f;
            }

#pragma unroll
    for (int mt = 0; mt < 2; mt++)
#pragma unroll
        for (int hf = 0; hf < 2; hf++) {
            float rm = -1e30f;
#pragma unroll
            for (int nt = 0; nt < 4; nt++)
                rm = fmaxf(rm, fmaxf(s[mt][nt][2 * hf], s[mt][nt][2 * hf + 1]));
            rm = fmaxf(rm, __shfl_xor_sync(0xffffffffu, rm, 1));
            rm = fmaxf(rm, __shfl_xor_sync(0xffffffffu, rm, 2));
            if (t4 == 0)
                redm[(wm * 32 + mt * 16 + grp + hf * 8) * 4 + wn] = rm;
        }
    __syncthreads();

    for (int i = tid; i < 2048; i += 256) {
        int r = i >> 4, d4 = (i & 15) * 4;
        float4 v = *(const float4*)(d_VC + cbase + r * 64 + d4);
        *(float4*)(&kv[r * CK + d4]) = v;
    }
#pragma unroll
    for (int mt = 0; mt < 2; mt++)
#pragma unroll
        for (int hf = 0; hf < 2; hf++) {
            int row = wm * 32 + mt * 16 + grp + hf * 8;
            float4 rmv = *(float4*)(&redm[row * 4]);
            float gmax = fmaxf(fmaxf(rmv.x, rmv.y), fmaxf(rmv.z, rmv.w));
            float rs = 0.f;
#pragma unroll
            for (int nt = 0; nt < 4; nt++) {
                float e0 = __expf(s[mt][nt][2 * hf]     - gmax);
                float e1 = __expf(s[mt][nt][2 * hf + 1] - gmax);
                s[mt][nt][2 * hf] = e0;
                s[mt][nt][2 * hf + 1] = e1;
                rs += e0 + e1;
            }
            rs += __shfl_xor_sync(0xffffffffu, rs, 1);
            rs += __shfl_xor_sync(0xffffffffu, rs, 2);
            if (t4 == 0) reds[row * 4 + wn] = rs;
        }
    __syncthreads();

#pragma unroll
    for (int mt = 0; mt < 2; mt++)
#pragma unroll
        for (int hf = 0; hf < 2; hf++) {
            int row = wm * 32 + mt * 16 + grp + hf * 8;
            float4 rsv = *(float4*)(&reds[row * 4]);
            float tot = rsv.x + rsv.y + rsv.z + rsv.w;
            float inv = (nval[mt][hf] > 0) ? 1.f / tot : 0.f;
#pragma unroll
            for (int nt = 0; nt < 4; nt++) {
                int col = wn * 32 + nt * 8 + 2 * t4;
                ps[row * CS + col]     = s[mt][nt][2 * hf]     * inv;
                ps[row * CS + col + 1] = s[mt][nt][2 * hf + 1] * inv;
            }
        }
    __syncthreads();

    float o[2][2][4];
#pragma unroll
    for (int mt = 0; mt < 2; mt++)
#pragma unroll
        for (int nt = 0; nt < 2; nt++)
#pragma unroll
            for (int r = 0; r < 4; r++) o[mt][nt][r] = 0.f;
#pragma unroll
    for (int ks = 0; ks < 16; ks++) {
        int kk = ks * 8;
        uint32_t af[2][4], bf[2][2];
#pragma unroll
        for (int mt = 0; mt < 2; mt++) {
            int row = wm * 32 + mt * 16 + grp;
            af[mt][0] = U(ftf(ps[row * CS + kk + t4]));
            af[mt][1] = U(ftf(ps[(row + 8) * CS + kk + t4]));
            af[mt][2] = U(ftf(ps[row * CS + kk + t4 + 4]));
            af[mt][3] = U(ftf(ps[(row + 8) * CS + kk + t4 + 4]));
        }
#pragma unroll
        for (int nt = 0; nt < 2; nt++) {
            int dcol = wn * 16 + nt * 8 + grp;
            bf[nt][0] = U(ftf(kv[(kk + t4) * CK + dcol]));
            bf[nt][1] = U(ftf(kv[(kk + t4 + 4) * CK + dcol]));
        }
#pragma unroll
        for (int mt = 0; mt < 2; mt++)
#pragma unroll
            for (int nt = 0; nt < 2; nt++)
                mma_tf32(o[mt][nt], af[mt], bf[nt]);
    }

#pragma unroll
    for (int mt = 0; mt < 2; mt++)
#pragma unroll
        for (int hf = 0; hf < 2; hf++) {
            int qp = qbase + wm * 32 + mt * 16 + grp + hf * 8;
            float g0 = d_G[(b * SEQ + qp) * 3 + 0];
#pragma unroll
            for (int nt = 0; nt < 2; nt++) {
                int dcol = wn * 16 + nt * 8 + 2 * t4;
                size_t ob = (size_t)(b * SEQ + qp) * 512 + h * 64 + dcol;
                *(float2*)(d_O + ob) = make_float2(o[mt][nt][2 * hf] * g0,
                                                   o[mt][nt][2 * hf + 1] * g0);
            }
        }
    __syncthreads();

    if (tid < 64) {
        float v = 0.f;
        for (int q = 0; q < 64; q++)
            v += ps[q * CS + 2 * tid] + ps[q * CS + 2 * tid + 1];
        impb[tid] = v;
    }
    __syncthreads();
    if (w == 0) {
        int j0 = lane, j1 = lane + 32;
        float v0 = (j0 <= g) ? impb[j0] + (j0 == g ? 1e9f : 0.f) : -1e30f;
        float v1 = (j1 <= g) ? impb[j1] + (j1 == g ? 1e9f : 0.f) : -1e30f;
        int selbase = ((b * NH + h) * NS + g) * TOPK;
        for (int r = 0; r < TOPK; r++) {
            float bv; int bi;
            if (v0 >= v1) { bv = v0; bi = j0; } else { bv = v1; bi = j1; }
#pragma unroll
            for (int o2 = 16; o2; o2 >>= 1) {
                float ov = __shfl_xor_sync(0xffffffffu, bv, o2);
                int   oi = __shfl_xor_sync(0xffffffffu, bi, o2);
                if (ov > bv || (ov == bv && oi < bi)) { bv = ov; bi = oi; }
            }
            if (lane == 0) d_SEL[selbase + r] = bi;
            if (bi == j0) v0 = -3e30f;
            if (bi == j1) v1 = -3e30f;
        }
    }
}

// ---------------- fused sel+win flash attention -----------------------------
// cp.async K/V streaming (no cvt ALU, no prefetch registers). K double-
// buffered in smem; K/V enter mma as RZ-truncated tf32 (raw fp32 bits).
#define QP 72
#define KP 68
#define VP 72
#define PP 72
#define KSZ (64*KP)
__global__ void __launch_bounds__(256) selwin_fused()
{
    extern __shared__ float sm[];
    float* qs   = sm;                 // 64*72 paired (rna tf32, pre-scaled)
    float* Ksb  = qs + 64 * QP;       // 2 * 64*68 (raw fp32 via cp.async)
    float* Vs   = Ksb + 2 * KSZ;      // 64*72 (raw fp32 via cp.async)
    float* ps   = Vs + 64 * VP;       // 64*72 paired
    float* redm = ps + 64 * PP;       // 64*4
    float* reds = redm + 256;         // 64*4

    __shared__ int skb[26];
    __shared__ int sphase[2];

    int g = blockIdx.x, hh = blockIdx.y, b = blockIdx.z;
    int tid = threadIdx.x, lane = tid & 31, w = tid >> 5;
    int grp = lane >> 2, t4 = lane & 3;
    int wm = w & 1, wn = w >> 1;
    int qbase = g * 64;

    if (tid == 0) {
        int selbase = ((b * NH + hh) * NS + g) * TOPK;
        int n = 0;
#pragma unroll
        for (int it = 0; it < TOPK; it++) {
            int kb = d_SEL[selbase + it];
            if (kb <= g) skb[n++] = kb;
        }
        sphase[0] = n;
        int st = (g > 8) ? g - 8 : 0;
        for (int kb = st; kb <= g; kb++) skb[n++] = kb;
        sphase[1] = n;
    }

#pragma unroll
    for (int ii = 0; ii < 2; ii++) {
        int i = tid + ii * 256;
        int r = i >> 3, g8 = (i & 7) * 8;
        const float* src = d_Q + (size_t)(b * SEQ + qbase + r) * 512 + hh * 64 + g8;
        float4 lo = *(const float4*)src;
        float4 hi = *(const float4*)(src + 4);
        float2* dst = (float2*)(&qs[r * QP + g8]);
        dst[0] = make_float2(ftf(lo.x * QSCALE), ftf(hi.x * QSCALE));
        dst[1] = make_float2(ftf(lo.y * QSCALE), ftf(hi.y * QSCALE));
        dst[2] = make_float2(ftf(lo.z * QSCALE), ftf(hi.z * QSCALE));
        dst[3] = make_float2(ftf(lo.w * QSCALE), ftf(hi.w * QSCALE));
    }
    __syncthreads();                  // skb/sphase + qs visible

    int nsel = sphase[0], ntot = sphase[1];
    int pr = tid >> 4, pd4 = (tid & 15) * 4;

    // prologue: cp.async K0 -> buf0, V0 -> Vs (one group), wait, sync
    {
        size_t kbase = (size_t)(b * SEQ + skb[0] * 64) * 512 + hh * 64;
#pragma unroll
        for (int j = 0; j < 4; j++) {
            int r = pr + j * 16;
            cpa16(sptr(&Ksb[r * KP + pd4]), d_K + kbase + (size_t)r * 512 + pd4);
            cpa16(sptr(&Vs[r * VP + pd4]),  d_V + kbase + (size_t)r * 512 + pd4);
        }
        CP_COMMIT();
        CP_WAIT0();
    }
    __syncthreads();

    float gv1[2][2], gv2[2][2];
#pragma unroll
    for (int mt = 0; mt < 2; mt++)
#pragma unroll
        for (int hf = 0; hf < 2; hf++) {
            int qp = qbase + wm * 32 + mt * 16 + grp + hf * 8;
            gv1[mt][hf] = d_G[(b * SEQ + qp) * 3 + 1];
            gv2[mt][hf] = d_G[(b * SEQ + qp) * 3 + 2];
        }

    float o[2][2][4];
#pragma unroll
    for (int mt = 0; mt < 2; mt++)
#pragma unroll
        for (int nt = 0; nt < 2; nt++)
#pragma unroll
            for (int r = 0; r < 4; r++) o[mt][nt][r] = 0.f;
    float mst[2][2], lst[2][2];
#pragma unroll
    for (int mt = 0; mt < 2; mt++)
#pragma unroll
        for (int hf = 0; hf < 2; hf++) { mst[mt][hf] = -1e30f; lst[mt][hf] = 0.f; }

    int posA = ((t4 & 1) << 2) + (t4 >> 1);

    for (int t = 0; t < ntot; t++) {
        if (t == nsel) {
#pragma unroll
            for (int mt = 0; mt < 2; mt++)
#pragma unroll
                for (int hf = 0; hf < 2; hf++) {
                    int qp = qbase + wm * 32 + mt * 16 + grp + hf * 8;
                    float inv = gv1[mt][hf] / lst[mt][hf];
#pragma unroll
                    for (int nt = 0; nt < 2; nt++) {
                        int dcol = wn * 16 + nt * 8 + 2 * t4;
                        size_t ob = (size_t)(b * SEQ + qp) * 512 + hh * 64 + dcol;
                        float2 cur = *(float2*)(d_O + ob);
                        cur.x += o[mt][nt][2 * hf]     * inv;
                        cur.y += o[mt][nt][2 * hf + 1] * inv;
                        *(float2*)(d_O + ob) = cur;
                        o[mt][nt][2 * hf] = 0.f; o[mt][nt][2 * hf + 1] = 0.f;
                    }
                    mst[mt][hf] = -1e30f; lst[mt][hf] = 0.f;
                }
        }
        int kb = skb[t];
        bool winph = (t >= nsel);
        bool more = (t + 1 < ntot);
        float* Ks = Ksb + (t & 1) * KSZ;

        // issue K(t+1) into the other buffer (no dependency)
        if (more) {
            float* Kn = Ksb + ((t + 1) & 1) * KSZ;
            size_t nbase = (size_t)(b * SEQ + skb[t + 1] * 64) * 512 + hh * 64;
#pragma unroll
            for (int j = 0; j < 4; j++) {
                int r = pr + j * 16;
                cpa16(sptr(&Kn[r * KP + pd4]), d_K + nbase + (size_t)r * 512 + pd4);
            }
            CP_COMMIT();
        }

        // ---- QK^T ----
        float s[2][2][4];
#pragma unroll
        for (int mt = 0; mt < 2; mt++)
#pragma unroll
            for (int nt = 0; nt < 2; nt++)
#pragma unroll
                for (int r = 0; r < 4; r++) s[mt][nt][r] = 0.f;
#pragma unroll
        for (int ks = 0; ks < 8; ks++) {
            int kk = ks * 8;
            uint32_t af[2][4], bf[2][2];
#pragma unroll
            for (int mt = 0; mt < 2; mt++) {
                int row = wm * 32 + mt * 16 + grp;
                float2 a0 = *(float2*)(&qs[row * QP + kk + 2 * t4]);
                float2 a1 = *(float2*)(&qs[(row + 8) * QP + kk + 2 * t4]);
                af[mt][0] = U(a0.x); af[mt][2] = U(a0.y);
                af[mt][1] = U(a1.x); af[mt][3] = U(a1.y);
            }
#pragma unroll
            for (int nt = 0; nt < 2; nt++) {
                int key = wn * 16 + nt * 8 + grp;
                bf[nt][0] = U(Ks[key * KP + kk + t4]);
                bf[nt][1] = U(Ks[key * KP + kk + t4 + 4]);
            }
#pragma unroll
            for (int mt = 0; mt < 2; mt++)
#pragma unroll
                for (int nt = 0; nt < 2; nt++)
                    mma_tf32(s[mt][nt], af[mt], bf[nt]);
        }

        bool needmask = (kb >= g) || (winph && kb < g - 7);
        if (needmask) {
#pragma unroll
            for (int mt = 0; mt < 2; mt++)
#pragma unroll
                for (int nt = 0; nt < 2; nt++)
#pragma unroll
                    for (int r = 0; r < 4; r++) {
                        int qp = qbase + wm * 32 + mt * 16 + grp + (r >> 1) * 8;
                        int kp = kb * 64 + wn * 16 + nt * 8 + 2 * t4 + (r & 1);
                        bool valid = (kp <= qp) && (!winph || (kp + 512 > qp));
                        s[mt][nt][r] = valid ? s[mt][nt][r] : -1e30f;
                    }
        }

#pragma unroll
        for (int mt = 0; mt < 2; mt++)
#pragma unroll
            for (int hf = 0; hf < 2; hf++) {
                float rm = fmaxf(fmaxf(s[mt][0][2 * hf], s[mt][0][2 * hf + 1]),
                                 fmaxf(s[mt][1][2 * hf], s[mt][1][2 * hf + 1]));
                rm = fmaxf(rm, __shfl_xor_sync(0xffffffffu, rm, 1));
                rm = fmaxf(rm, __shfl_xor_sync(0xffffffffu, rm, 2));
                if (t4 == 0)
                    redm[(wm * 32 + mt * 16 + grp + hf * 8) * 4 + wn] = rm;
            }
        __syncthreads();   // S1: redm visible

        float corr[2][2], mnew[2][2];
#pragma unroll
        for (int mt = 0; mt < 2; mt++)
#pragma unroll
            for (int hf = 0; hf < 2; hf++) {
                int row = wm * 32 + mt * 16 + grp + hf * 8;
                float4 rmv = *(float4*)(&redm[row * 4]);
                float gmax = fmaxf(fmaxf(rmv.x, rmv.y), fmaxf(rmv.z, rmv.w));
                float mn = fmaxf(mst[mt][hf], gmax);
                mnew[mt][hf] = mn;
                corr[mt][hf] = ex2(mst[mt][hf] - mn);
            }

#pragma unroll
        for (int mt = 0; mt < 2; mt++)
#pragma unroll
            for (int hf = 0; hf < 2; hf++) {
                int rowl = wm * 32 + mt * 16 + grp + hf * 8;
                float mn = mnew[mt][hf];
                float rs = 0.f;
#pragma unroll
                for (int nt = 0; nt < 2; nt++) {
                    float p0 = ex2(s[mt][nt][2 * hf]     - mn);
                    float p1 = ex2(s[mt][nt][2 * hf + 1] - mn);
                    rs += p0 + p1;
                    int gb = wn * 16 + nt * 8;
                    ps[rowl * PP + gb + posA]     = ftf(p0);
                    ps[rowl * PP + gb + posA + 2] = ftf(p1);
                }
                rs += __shfl_xor_sync(0xffffffffu, rs, 1);
                rs += __shfl_xor_sync(0xffffffffu, rs, 2);
                if (t4 == 0) reds[rowl * 4 + wn] = rs;
            }

        // ensure V(t) landed (it's the oldest outstanding group)
        if (more) CP_WAIT1(); else CP_WAIT0();
        __syncthreads();   // S2: ps, reds, V(t) visible

#pragma unroll
        for (int mt = 0; mt < 2; mt++)
#pragma unroll
            for (int hf = 0; hf < 2; hf++) {
                int row = wm * 32 + mt * 16 + grp + hf * 8;
                float4 rsv = *(float4*)(&reds[row * 4]);
                float ls = rsv.x + rsv.y + rsv.z + rsv.w;
                float cr = corr[mt][hf];
                lst[mt][hf] = lst[mt][hf] * cr + ls;
                mst[mt][hf] = mnew[mt][hf];
#pragma unroll
                for (int nt = 0; nt < 2; nt++) {
                    o[mt][nt][2 * hf]     *= cr;
                    o[mt][nt][2 * hf + 1] *= cr;
                }
            }

        // ---- P*V ----
#pragma unroll
        for (int ks = 0; ks < 8; ks++) {
            int kk = ks * 8;
            uint32_t af[2][4], bf[2][2];
#pragma unroll
            for (int mt = 0; mt < 2; mt++) {
                int row = wm * 32 + mt * 16 + grp;
                float2 p0 = *(float2*)(&ps[row * PP + kk + 2 * t4]);
                float2 p1 = *(float2*)(&ps[(row + 8) * PP + kk + 2 * t4]);
                af[mt][0] = U(p0.x); af[mt][2] = U(p0.y);
                af[mt][1] = U(p1.x); af[mt][3] = U(p1.y);
            }
#pragma unroll
            for (int nt = 0; nt < 2; nt++) {
                int dcol = wn * 16 + nt * 8 + grp;
                bf[nt][0] = U(Vs[(kk + t4) * VP + dcol]);
                bf[nt][1] = U(Vs[(kk + t4 + 4) * VP + dcol]);
            }
#pragma unroll
            for (int mt = 0; mt < 2; mt++)
#pragma unroll
                for (int nt = 0; nt < 2; nt++)
                    mma_tf32(o[mt][nt], af[mt], bf[nt]);
        }

        // ensure K(t+1) landed before the barrier that frees/publishes buffers
        if (more) CP_WAIT0();
        __syncthreads();   // S3: Vs free, K(t+1) visible

        if (more) {
            size_t nbase = (size_t)(b * SEQ + skb[t + 1] * 64) * 512 + hh * 64;
#pragma unroll
            for (int j = 0; j < 4; j++) {
                int r = pr + j * 16;
                cpa16(sptr(&Vs[r * VP + pd4]), d_V + nbase + (size_t)r * 512 + pd4);
            }
            CP_COMMIT();
        }
    }

#pragma unroll
    for (int mt = 0; mt < 2; mt++)
#pragma unroll
        for (int hf = 0; hf < 2; hf++) {
            int qp = qbase + wm * 32 + mt * 16 + grp + hf * 8;
            float inv = gv2[mt][hf] / lst[mt][hf];
#pragma unroll
            for (int nt = 0; nt < 2; nt++) {
                int dcol = wn * 16 + nt * 8 + 2 * t4;
                size_t ob = (size_t)(b * SEQ + qp) * 512 + hh * 64 + dcol;
                float2 cur = *(float2*)(d_O + ob);
                cur.x += o[mt][nt][2 * hf]     * inv;
                cur.y += o[mt][nt][2 * hf + 1] * inv;
                *(float2*)(d_O + ob) = cur;
            }
        }
}

// ---------------------------------------------------------------------------
extern "C" void kernel_launch(void* const* d_in, const int* in_sizes, int n_in,
                              void* d_out, int out_size)
{
    const float* x  = (const float*)d_in[0];
    const float* Wq = (const float*)d_in[1];
    const float* Wk = (const float*)d_in[2];
    const float* Wv = (const float*)d_in[3];
    const float* Wo = (const float*)d_in[4];
    const float* Wg = (const float*)d_in[5];
    float* y = (float*)d_out;

    cudaFuncSetAttribute(gemm512_tc,
                         cudaFuncAttributeMaxDynamicSharedMemorySize, 71680);
    cudaFuncSetAttribute(cmp_attn_mma,
                         cudaFuncAttributeMaxDynamicSharedMemorySize, 90368);
    // selwin smem: (64*72 + 2*64*68 + 64*72 + 64*72 + 512) * 4 = 92160 B
    cudaFuncSetAttribute(selwin_fused,
                         cudaFuncAttributeMaxDynamicSharedMemorySize, 92160);

    gemm512_tc<<<dim3(4, 64, 3), 256, 71680>>>(x, Wq, Wk, Wv, nullptr, 0);
    gate_compress<<<1024 + 512, 256>>>(x, Wg);
    cmp_attn_mma<<<dim3(64, 8, 2), 256, 90368>>>();
    selwin_fused<<<dim3(64, 8, 2), 256, 92160>>>();
    gemm512_tc<<<dim3(4, 64, 1), 256, 71680>>>(nullptr, Wo, nullptr, nullptr, y, 3);
}

// round 16
// speedup vs baseline: 1.2205x; 1.0066x over previous
#include <cuda_runtime.h>
#include <math.h>
#include <stdint.h>

#define BATCH   2
#define SEQ     4096
#define DMODEL  512
#define NH      8
#define HD      64
#define NC      128
#define NS      64
#define TOPK    16
#define NROWS   (BATCH*SEQ)

// ---------------- scratch ----------------
__device__ float d_Q[NROWS*DMODEL];
__device__ float d_K[NROWS*DMODEL];
__device__ float d_V[NROWS*DMODEL];
__device__ float d_O[NROWS*DMODEL];
__device__ float d_KC[BATCH*NH*NC*HD];
__device__ float d_VC[BATCH*NH*NC*HD];
__device__ float d_G[NROWS*3];
__device__ int   d_SEL[BATCH*NH*NS*TOPK];

// ---------------- tf32 helpers ----------------
__device__ __forceinline__ float ftf(float x) {
    uint32_t u;
    asm("cvt.rna.tf32.f32 %0, %1;" : "=r"(u) : "f"(x));
    return __uint_as_float(u);
}
__device__ __forceinline__ float4 ftf4(float4 v) {
    return make_float4(ftf(v.x), ftf(v.y), ftf(v.z), ftf(v.w));
}
__device__ __forceinline__ float ex2(float x) {
    float r;
    asm("ex2.approx.ftz.f32 %0, %1;" : "=f"(r) : "f"(x));
    return r;
}
__device__ __forceinline__ void mma_tf32(float* c, const uint32_t* a, const uint32_t* b) {
    asm volatile(
        "mma.sync.aligned.m16n8k8.row.col.f32.tf32.tf32.f32 "
        "{%0,%1,%2,%3},{%4,%5,%6,%7},{%8,%9},{%0,%1,%2,%3};\n"
        : "+f"(c[0]), "+f"(c[1]), "+f"(c[2]), "+f"(c[3])
        : "r"(a[0]), "r"(a[1]), "r"(a[2]), "r"(a[3]), "r"(b[0]), "r"(b[1]));
}
__device__ __forceinline__ void split_tf32(float x, uint32_t& hi, uint32_t& lo) {
    float h = ftf(x);
    hi = __float_as_uint(h);
    lo = __float_as_uint(ftf(x - h));
}
__device__ __forceinline__ uint32_t sptr(const void* p) {
    return (uint32_t)__cvta_generic_to_shared(p);
}
__device__ __forceinline__ void cpa16(uint32_t dst, const float* src) {
    asm volatile("cp.async.cg.shared.global [%0], [%1], 16;" :: "r"(dst), "l"(src));
}
#define CP_COMMIT() asm volatile("cp.async.commit_group;")
#define CP_WAIT0()  asm volatile("cp.async.wait_group 0;" ::: "memory")
#define CP_WAIT1()  asm volatile("cp.async.wait_group 1;" ::: "memory")
#define U(x) __float_as_uint(x)
#define QSCALE 0.18033688011112042f   /* 0.125 * log2(e) */

// ---------------- tf32 GEMM: 128x128 tile, k-slab 32, smem double buffer --
#define GPA 36
#define GPB 136
__global__ __launch_bounds__(256) void gemm512_tc(const float* __restrict__ Aext,
    const float* __restrict__ B0, const float* __restrict__ B1,
    const float* __restrict__ B2, float* __restrict__ Cext, int modeBase)
{
    extern __shared__ float smg[];
    float* As = smg;
    float* Bs = smg + 2 * 128 * GPA;

    int mode = modeBase + blockIdx.z;
    const float* A  = (mode == 3) ? d_O : Aext;
    const float* Bm = (mode == 1) ? B1 : (mode == 2) ? B2 : B0;
    float* C = (mode == 0) ? d_Q : (mode == 1) ? d_K : (mode == 2) ? d_V : Cext;

    int tid = threadIdx.x, lane = tid & 31, w = tid >> 5;
    int grp = lane >> 2, t4 = lane & 3;
    int wm = w & 3, wn = w >> 2;
    int m0 = blockIdx.y * 128, n0 = blockIdx.x * 128;

    int arr[4], arc[4], brr[4], brc[4];
#pragma unroll
    for (int ii = 0; ii < 4; ii++) {
        int i = tid + ii * 256;
        arr[ii] = i >> 3;  arc[ii] = (i & 7) * 4;
        brr[ii] = i >> 5;  brc[ii] = (i & 31) * 4;
    }

    float acc[2][8][4];
#pragma unroll
    for (int mt = 0; mt < 2; mt++)
#pragma unroll
        for (int nt = 0; nt < 8; nt++)
#pragma unroll
            for (int r = 0; r < 4; r++) acc[mt][nt][r] = 0.f;

    float4 areg[4], breg[4];
#pragma unroll
    for (int ii = 0; ii < 4; ii++) {
        areg[ii] = *(const float4*)(A + (size_t)(m0 + arr[ii]) * 512 + arc[ii]);
        breg[ii] = *(const float4*)(Bm + (size_t)brr[ii] * 512 + n0 + brc[ii]);
    }
#pragma unroll
    for (int ii = 0; ii < 4; ii++) {
        *(float4*)(&As[arr[ii] * GPA + arc[ii]]) = ftf4(areg[ii]);
        *(float4*)(&Bs[brr[ii] * GPB + brc[ii]]) = ftf4(breg[ii]);
    }
    __syncthreads();

    for (int s = 0; s < 16; s++) {
        float* Ab = As + (s & 1) * 128 * GPA;
        float* Bb = Bs + (s & 1) * 32 * GPB;
        if (s < 15) {
            int k0 = (s + 1) * 32;
#pragma unroll
            for (int ii = 0; ii < 4; ii++) {
                areg[ii] = *(const float4*)(A + (size_t)(m0 + arr[ii]) * 512 + k0 + arc[ii]);
                breg[ii] = *(const float4*)(Bm + (size_t)(k0 + brr[ii]) * 512 + n0 + brc[ii]);
            }
        }
#pragma unroll
        for (int ks = 0; ks < 4; ks++) {
            int kb = ks * 8;
            uint32_t af[2][4], bf[8][2];
#pragma unroll
            for (int mt = 0; mt < 2; mt++) {
                int row = wm * 32 + mt * 16 + grp;
                af[mt][0] = U(Ab[row * GPA + kb + t4]);
                af[mt][1] = U(Ab[(row + 8) * GPA + kb + t4]);
                af[mt][2] = U(Ab[row * GPA + kb + t4 + 4]);
                af[mt][3] = U(Ab[(row + 8) * GPA + kb + t4 + 4]);
            }
#pragma unroll
            for (int nt = 0; nt < 8; nt++) {
                int col = wn * 64 + nt * 8 + grp;
                bf[nt][0] = U(Bb[(kb + t4) * GPB + col]);
                bf[nt][1] = U(Bb[(kb + t4 + 4) * GPB + col]);
            }
#pragma unroll
            for (int mt = 0; mt < 2; mt++)
#pragma unroll
                for (int nt = 0; nt < 8; nt++)
                    mma_tf32(acc[mt][nt], af[mt], bf[nt]);
        }
        if (s < 15) {
            float* An = As + ((s + 1) & 1) * 128 * GPA;
            float* Bn = Bs + ((s + 1) & 1) * 32 * GPB;
#pragma unroll
            for (int ii = 0; ii < 4; ii++) {
                *(float4*)(&An[arr[ii] * GPA + arc[ii]]) = ftf4(areg[ii]);
                *(float4*)(&Bn[brr[ii] * GPB + brc[ii]]) = ftf4(breg[ii]);
            }
        }
        __syncthreads();
    }
#pragma unroll
    for (int mt = 0; mt < 2; mt++)
#pragma unroll
        for (int nt = 0; nt < 8; nt++) {
            int row = m0 + wm * 32 + mt * 16 + grp;
            int col = n0 + wn * 64 + nt * 8 + 2 * t4;
            *(float2*)(C + (size_t)row * 512 + col) =
                make_float2(acc[mt][nt][0], acc[mt][nt][1]);
            *(float2*)(C + (size_t)(row + 8) * 512 + col) =
                make_float2(acc[mt][nt][2], acc[mt][nt][3]);
        }
}

// ---------------- fused gate + compress (one launch) ----------------
__global__ __launch_bounds__(256) void gate_compress(const float* __restrict__ x,
                                                     const float* __restrict__ Wg)
{
    int blk = blockIdx.x;
    if (blk < 1024) {
        int w = threadIdx.x >> 5, lane = threadIdx.x & 31;
        int row = blk * 8 + w;
        float p0 = 0, p1 = 0, p2 = 0;
#pragma unroll
        for (int c = 0; c < 4; c++) {
            int d = c * 128 + lane * 4;
            float4 xv = *(const float4*)(x + (size_t)row * 512 + d);
            p0 += xv.x * Wg[d * 3]     + xv.y * Wg[d * 3 + 3] +
                  xv.z * Wg[d * 3 + 6] + xv.w * Wg[d * 3 + 9];
            p1 += xv.x * Wg[d * 3 + 1] + xv.y * Wg[d * 3 + 4] +
                  xv.z * Wg[d * 3 + 7] + xv.w * Wg[d * 3 + 10];
            p2 += xv.x * Wg[d * 3 + 2] + xv.y * Wg[d * 3 + 5] +
                  xv.z * Wg[d * 3 + 8] + xv.w * Wg[d * 3 + 11];
        }
#pragma unroll
        for (int o = 16; o; o >>= 1) {
            p0 += __shfl_xor_sync(0xffffffffu, p0, o);
            p1 += __shfl_xor_sync(0xffffffffu, p1, o);
            p2 += __shfl_xor_sync(0xffffffffu, p2, o);
        }
        if (lane == 0) {
            d_G[row * 3 + 0] = 1.f / (1.f + expf(-p0));
            d_G[row * 3 + 1] = 1.f / (1.f + expf(-p1));
            d_G[row * 3 + 2] = 1.f / (1.f + expf(-p2));
        }
    } else {
        int idx = (blk - 1024) * 256 + threadIdx.x;
        int d = idx & 63, n = (idx >> 6) & 127, h = (idx >> 13) & 7, b = idx >> 16;
        const float* kp = d_K + (size_t)(b * SEQ + n * 32) * 512 + h * 64 + d;
        const float* vp = d_V + (size_t)(b * SEQ + n * 32) * 512 + h * 64 + d;
        float ks = 0, vs = 0;
#pragma unroll
        for (int r = 0; r < 32; r++) { ks += kp[r * 512]; vs += vp[r * 512]; }
        d_KC[idx] = ks * (1.f / 32.f);
        d_VC[idx] = vs * (1.f / 32.f);
    }
}

// ---------------- compressed attention + top-k (R7 proven: 3xTF32 QK) -----
#define CQ 68
#define CK 72
#define CS 132
__global__ __launch_bounds__(256) void cmp_attn_mma()
{
    extern __shared__ float sm[];
    float* qs   = sm;
    float* kv   = qs + 64 * CQ;
    float* ps   = kv + 128 * CK;
    float* redm = ps + 64 * CS;
    float* reds = redm + 256;
    float* impb = reds + 256;

    int g = blockIdx.x, h = blockIdx.y, b = blockIdx.z;
    int tid = threadIdx.x, lane = tid & 31, w = tid >> 5;
    int grp = lane >> 2, t4 = lane & 3;
    int wm = w & 1, wn = w >> 1;
    int qbase = g * 64;

    for (int i = tid; i < 1024; i += 256) {
        int r = i >> 4, d4 = (i & 15) * 4;
        float4 v = *(const float4*)(d_Q + (size_t)(b * SEQ + qbase + r) * 512 + h * 64 + d4);
        *(float4*)(&qs[r * CQ + d4]) = v;
    }
    int cbase = ((b * NH + h) * NC) * HD;
    for (int i = tid; i < 2048; i += 256) {
        int r = i >> 4, d4 = (i & 15) * 4;
        float4 v = *(const float4*)(d_KC + cbase + r * 64 + d4);
        *(float4*)(&kv[r * CK + d4]) = v;
    }
    __syncthreads();

    float s[2][4][4];
#pragma unroll
    for (int mt = 0; mt < 2; mt++)
#pragma unroll
        for (int nt = 0; nt < 4; nt++)
#pragma unroll
            for (int r = 0; r < 4; r++) s[mt][nt][r] = 0.f;
#pragma unroll
    for (int ks = 0; ks < 8; ks++) {
        int kk = ks * 8;
        uint32_t ah[2][4], al[2][4], bh[4][2], bl[4][2];
#pragma unroll
        for (int mt = 0; mt < 2; mt++) {
            int row = wm * 32 + mt * 16 + grp;
            split_tf32(qs[row * CQ + kk + t4],           ah[mt][0], al[mt][0]);
            split_tf32(qs[(row + 8) * CQ + kk + t4],     ah[mt][1], al[mt][1]);
            split_tf32(qs[row * CQ + kk + t4 + 4],       ah[mt][2], al[mt][2]);
            split_tf32(qs[(row + 8) * CQ + kk + t4 + 4], ah[mt][3], al[mt][3]);
        }
#pragma unroll
        for (int nt = 0; nt < 4; nt++) {
            int key = wn * 32 + nt * 8 + grp;
            split_tf32(kv[key * CK + kk + t4],     bh[nt][0], bl[nt][0]);
            split_tf32(kv[key * CK + kk + t4 + 4], bh[nt][1], bl[nt][1]);
        }
#pragma unroll
        for (int mt = 0; mt < 2; mt++)
#pragma unroll
            for (int nt = 0; nt < 4; nt++) {
                mma_tf32(s[mt][nt], ah[mt], bl[nt]);
                mma_tf32(s[mt][nt], al[mt], bh[nt]);
                mma_tf32(s[mt][nt], ah[mt], bh[nt]);
            }
    }

    int nval[2][2];
#pragma unroll
    for (int mt = 0; mt < 2; mt++)
#pragma unroll
        for (int hf = 0; hf < 2; hf++) {
            int pos = qbase + wm * 32 + mt * 16 + grp + hf * 8;
            nval[mt][hf] = (pos >= 31) ? ((pos - 31) >> 5) + 1 : 0;
        }
#pragma unroll
    for (int mt = 0; mt < 2; mt++)
#pragma unroll
        for (int nt = 0; nt < 4; nt++)
#pragma unroll
            for (int r = 0; r < 4; r++) {
                int c = wn * 32 + nt * 8 + 2 * t4 + (r & 1);
                bool valid = c < nval[mt][r >> 1];
                s[mt][nt][r] = valid ? s[mt][nt][r] * 0.125f : -1e30f;
            }

#pragma unroll
    for (int mt = 0; mt < 2; mt++)
#pragma unroll
        for (int hf = 0; hf < 2; hf++) {
            float rm = -1e30f;
#pragma unroll
            for (int nt = 0; nt < 4; nt++)
                rm = fmaxf(rm, fmaxf(s[mt][nt][2 * hf], s[mt][nt][2 * hf + 1]));
            rm = fmaxf(rm, __shfl_xor_sync(0xffffffffu, rm, 1));
            rm = fmaxf(rm, __shfl_xor_sync(0xffffffffu, rm, 2));
            if (t4 == 0)
                redm[(wm * 32 + mt * 16 + grp + hf * 8) * 4 + wn] = rm;
        }
    __syncthreads();

    for (int i = tid; i < 2048; i += 256) {
        int r = i >> 4, d4 = (i & 15) * 4;
        float4 v = *(const float4*)(d_VC + cbase + r * 64 + d4);
        *(float4*)(&kv[r * CK + d4]) = v;
    }
#pragma unroll
    for (int mt = 0; mt < 2; mt++)
#pragma unroll
        for (int hf = 0; hf < 2; hf++) {
            int row = wm * 32 + mt * 16 + grp + hf * 8;
            float4 rmv = *(float4*)(&redm[row * 4]);
            float gmax = fmaxf(fmaxf(rmv.x, rmv.y), fmaxf(rmv.z, rmv.w));
            float rs = 0.f;
#pragma unroll
            for (int nt = 0; nt < 4; nt++) {
                float e0 = __expf(s[mt][nt][2 * hf]     - gmax);
                float e1 = __expf(s[mt][nt][2 * hf + 1] - gmax);
                s[mt][nt][2 * hf] = e0;
                s[mt][nt][2 * hf + 1] = e1;
                rs += e0 + e1;
            }
            rs += __shfl_xor_sync(0xffffffffu, rs, 1);
            rs += __shfl_xor_sync(0xffffffffu, rs, 2);
            if (t4 == 0) reds[row * 4 + wn] = rs;
        }
    __syncthreads();

#pragma unroll
    for (int mt = 0; mt < 2; mt++)
#pragma unroll
        for (int hf = 0; hf < 2; hf++) {
            int row = wm * 32 + mt * 16 + grp + hf * 8;
            float4 rsv = *(float4*)(&reds[row * 4]);
            float tot = rsv.x + rsv.y + rsv.z + rsv.w;
            float inv = (nval[mt][hf] > 0) ? 1.f / tot : 0.f;
#pragma unroll
            for (int nt = 0; nt < 4; nt++) {
                int col = wn * 32 + nt * 8 + 2 * t4;
                ps[row * CS + col]     = s[mt][nt][2 * hf]     * inv;
                ps[row * CS + col + 1] = s[mt][nt][2 * hf + 1] * inv;
            }
        }
    __syncthreads();

    float o[2][2][4];
#pragma unroll
    for (int mt = 0; mt < 2; mt++)
#pragma unroll
        for (int nt = 0; nt < 2; nt++)
#pragma unroll
            for (int r = 0; r < 4; r++) o[mt][nt][r] = 0.f;
#pragma unroll
    for (int ks = 0; ks < 16; ks++) {
        int kk = ks * 8;
        uint32_t af[2][4], bf[2][2];
#pragma unroll
        for (int mt = 0; mt < 2; mt++) {
            int row = wm * 32 + mt * 16 + grp;
            af[mt][0] = U(ftf(ps[row * CS + kk + t4]));
            af[mt][1] = U(ftf(ps[(row + 8) * CS + kk + t4]));
            af[mt][2] = U(ftf(ps[row * CS + kk + t4 + 4]));
            af[mt][3] = U(ftf(ps[(row + 8) * CS + kk + t4 + 4]));
        }
#pragma unroll
        for (int nt = 0; nt < 2; nt++) {
            int dcol = wn * 16 + nt * 8 + grp;
            bf[nt][0] = U(ftf(kv[(kk + t4) * CK + dcol]));
            bf[nt][1] = U(ftf(kv[(kk + t4 + 4) * CK + dcol]));
        }
#pragma unroll
        for (int mt = 0; mt < 2; mt++)
#pragma unroll
            for (int nt = 0; nt < 2; nt++)
                mma_tf32(o[mt][nt], af[mt], bf[nt]);
    }

#pragma unroll
    for (int mt = 0; mt < 2; mt++)
#pragma unroll
        for (int hf = 0; hf < 2; hf++) {
            int qp = qbase + wm * 32 + mt * 16 + grp + hf * 8;
            float g0 = d_G[(b * SEQ + qp) * 3 + 0];
#pragma unroll
            for (int nt = 0; nt < 2; nt++) {
                int dcol = wn * 16 + nt * 8 + 2 * t4;
                size_t ob = (size_t)(b * SEQ + qp) * 512 + h * 64 + dcol;
                *(float2*)(d_O + ob) = make_float2(o[mt][nt][2 * hf] * g0,
                                                   o[mt][nt][2 * hf + 1] * g0);
            }
        }
    __syncthreads();

    if (tid < 64) {
        float v = 0.f;
        for (int q = 0; q < 64; q++)
            v += ps[q * CS + 2 * tid] + ps[q * CS + 2 * tid + 1];
        impb[tid] = v;
    }
    __syncthreads();
    if (w == 0) {
        int j0 = lane, j1 = lane + 32;
        float v0 = (j0 <= g) ? impb[j0] + (j0 == g ? 1e9f : 0.f) : -1e30f;
        float v1 = (j1 <= g) ? impb[j1] + (j1 == g ? 1e9f : 0.f) : -1e30f;
        int selbase = ((b * NH + h) * NS + g) * TOPK;
        for (int r = 0; r < TOPK; r++) {
            float bv; int bi;
            if (v0 >= v1) { bv = v0; bi = j0; } else { bv = v1; bi = j1; }
#pragma unroll
            for (int o2 = 16; o2; o2 >>= 1) {
                float ov = __shfl_xor_sync(0xffffffffu, bv, o2);
                int   oi = __shfl_xor_sync(0xffffffffu, bi, o2);
                if (ov > bv || (ov == bv && oi < bi)) { bv = ov; bi = oi; }
            }
            if (lane == 0) d_SEL[selbase + r] = bi;
            if (bi == j0) v0 = -3e30f;
            if (bi == j1) v1 = -3e30f;
        }
    }
}

// ---------------- fused sel+win flash attention -----------------------------
// cp.async K/V, SINGLE K buffer (K(t+1) streams into Ks after the S1 barrier
// proves Ks dead) -> smem 74.75KB -> 3 CTAs/SM at 80 regs.
#define QP 72
#define KP 68
#define VP 72
#define PP 72
__global__ void __launch_bounds__(256) selwin_fused()
{
    extern __shared__ float sm[];
    float* qs   = sm;                 // 64*72 paired (rna tf32, pre-scaled)
    float* Ks   = qs + 64 * QP;       // 64*68 (raw fp32 via cp.async, single)
    float* Vs   = Ks + 64 * KP;       // 64*72 (raw fp32 via cp.async)
    float* ps   = Vs + 64 * VP;       // 64*72 paired
    float* redm = ps + 64 * PP;       // 64*4
    float* reds = redm + 256;         // 64*4

    __shared__ int skb[26];
    __shared__ int sphase[2];

    int g = blockIdx.x, hh = blockIdx.y, b = blockIdx.z;
    int tid = threadIdx.x, lane = tid & 31, w = tid >> 5;
    int grp = lane >> 2, t4 = lane & 3;
    int wm = w & 1, wn = w >> 1;
    int qbase = g * 64;

    if (tid == 0) {
        int selbase = ((b * NH + hh) * NS + g) * TOPK;
        int n = 0;
#pragma unroll
        for (int it = 0; it < TOPK; it++) {
            int kb = d_SEL[selbase + it];
            if (kb <= g) skb[n++] = kb;
        }
        sphase[0] = n;
        int st = (g > 8) ? g - 8 : 0;
        for (int kb = st; kb <= g; kb++) skb[n++] = kb;
        sphase[1] = n;
    }

#pragma unroll
    for (int ii = 0; ii < 2; ii++) {
        int i = tid + ii * 256;
        int r = i >> 3, g8 = (i & 7) * 8;
        const float* src = d_Q + (size_t)(b * SEQ + qbase + r) * 512 + hh * 64 + g8;
        float4 lo = *(const float4*)src;
        float4 hi = *(const float4*)(src + 4);
        float2* dst = (float2*)(&qs[r * QP + g8]);
        dst[0] = make_float2(ftf(lo.x * QSCALE), ftf(hi.x * QSCALE));
        dst[1] = make_float2(ftf(lo.y * QSCALE), ftf(hi.y * QSCALE));
        dst[2] = make_float2(ftf(lo.z * QSCALE), ftf(hi.z * QSCALE));
        dst[3] = make_float2(ftf(lo.w * QSCALE), ftf(hi.w * QSCALE));
    }
    __syncthreads();                  // skb/sphase + qs visible

    int nsel = sphase[0], ntot = sphase[1];
    int pr = tid >> 4, pd4 = (tid & 15) * 4;

    // prologue: cp.async K0 + V0, wait, sync
    {
        size_t kbase = (size_t)(b * SEQ + skb[0] * 64) * 512 + hh * 64;
#pragma unroll
        for (int j = 0; j < 4; j++) {
            int r = pr + j * 16;
            cpa16(sptr(&Ks[r * KP + pd4]), d_K + kbase + (size_t)r * 512 + pd4);
            cpa16(sptr(&Vs[r * VP + pd4]), d_V + kbase + (size_t)r * 512 + pd4);
        }
        CP_COMMIT();
        CP_WAIT0();
    }
    __syncthreads();

    float gv1[2][2], gv2[2][2];
#pragma unroll
    for (int mt = 0; mt < 2; mt++)
#pragma unroll
        for (int hf = 0; hf < 2; hf++) {
            int qp = qbase + wm * 32 + mt * 16 + grp + hf * 8;
            gv1[mt][hf] = d_G[(b * SEQ + qp) * 3 + 1];
            gv2[mt][hf] = d_G[(b * SEQ + qp) * 3 + 2];
        }

    float o[2][2][4];
#pragma unroll
    for (int mt = 0; mt < 2; mt++)
#pragma unroll
        for (int nt = 0; nt < 2; nt++)
#pragma unroll
            for (int r = 0; r < 4; r++) o[mt][nt][r] = 0.f;
    float mst[2][2], lst[2][2];
#pragma unroll
    for (int mt = 0; mt < 2; mt++)
#pragma unroll
        for (int hf = 0; hf < 2; hf++) { mst[mt][hf] = -1e30f; lst[mt][hf] = 0.f; }

    int posA = ((t4 & 1) << 2) + (t4 >> 1);

    for (int t = 0; t < ntot; t++) {
        if (t == nsel) {
#pragma unroll
            for (int mt = 0; mt < 2; mt++)
#pragma unroll
                for (int hf = 0; hf < 2; hf++) {
                    int qp = qbase + wm * 32 + mt * 16 + grp + hf * 8;
                    float inv = gv1[mt][hf] / lst[mt][hf];
#pragma unroll
                    for (int nt = 0; nt < 2; nt++) {
                        int dcol = wn * 16 + nt * 8 + 2 * t4;
                        size_t ob = (size_t)(b * SEQ + qp) * 512 + hh * 64 + dcol;
                        float2 cur = *(float2*)(d_O + ob);
                        cur.x += o[mt][nt][2 * hf]     * inv;
                        cur.y += o[mt][nt][2 * hf + 1] * inv;
                        *(float2*)(d_O + ob) = cur;
                        o[mt][nt][2 * hf] = 0.f; o[mt][nt][2 * hf + 1] = 0.f;
                    }
                    mst[mt][hf] = -1e30f; lst[mt][hf] = 0.f;
                }
        }
        int kb = skb[t];
        bool winph = (t >= nsel);
        bool more = (t + 1 < ntot);

        // ---- QK^T (Ks = K(t), valid) ----
        float s[2][2][4];
#pragma unroll
        for (int mt = 0; mt < 2; mt++)
#pragma unroll
            for (int nt = 0; nt < 2; nt++)
#pragma unroll
                for (int r = 0; r < 4; r++) s[mt][nt][r] = 0.f;
#pragma unroll
        for (int ks = 0; ks < 8; ks++) {
            int kk = ks * 8;
            uint32_t af[2][4], bf[2][2];
#pragma unroll
            for (int mt = 0; mt < 2; mt++) {
                int row = wm * 32 + mt * 16 + grp;
                float2 a0 = *(float2*)(&qs[row * QP + kk + 2 * t4]);
                float2 a1 = *(float2*)(&qs[(row + 8) * QP + kk + 2 * t4]);
                af[mt][0] = U(a0.x); af[mt][2] = U(a0.y);
                af[mt][1] = U(a1.x); af[mt][3] = U(a1.y);
            }
#pragma unroll
            for (int nt = 0; nt < 2; nt++) {
                int key = wn * 16 + nt * 8 + grp;
                bf[nt][0] = U(Ks[key * KP + kk + t4]);
                bf[nt][1] = U(Ks[key * KP + kk + t4 + 4]);
            }
#pragma unroll
            for (int mt = 0; mt < 2; mt++)
#pragma unroll
                for (int nt = 0; nt < 2; nt++)
                    mma_tf32(s[mt][nt], af[mt], bf[nt]);
        }

        bool needmask = (kb >= g) || (winph && kb < g - 7);
        if (needmask) {
#pragma unroll
            for (int mt = 0; mt < 2; mt++)
#pragma unroll
                for (int nt = 0; nt < 2; nt++)
#pragma unroll
                    for (int r = 0; r < 4; r++) {
                        int qp = qbase + wm * 32 + mt * 16 + grp + (r >> 1) * 8;
                        int kp = kb * 64 + wn * 16 + nt * 8 + 2 * t4 + (r & 1);
                        bool valid = (kp <= qp) && (!winph || (kp + 512 > qp));
                        s[mt][nt][r] = valid ? s[mt][nt][r] : -1e30f;
                    }
        }

#pragma unroll
        for (int mt = 0; mt < 2; mt++)
#pragma unroll
            for (int hf = 0; hf < 2; hf++) {
                float rm = fmaxf(fmaxf(s[mt][0][2 * hf], s[mt][0][2 * hf + 1]),
                                 fmaxf(s[mt][1][2 * hf], s[mt][1][2 * hf + 1]));
                rm = fmaxf(rm, __shfl_xor_sync(0xffffffffu, rm, 1));
                rm = fmaxf(rm, __shfl_xor_sync(0xffffffffu, rm, 2));
                if (t4 == 0)
                    redm[(wm * 32 + mt * 16 + grp + hf * 8) * 4 + wn] = rm;
            }
        __syncthreads();   // S1: redm visible, Ks fully consumed

        // stream K(t+1) into the SAME Ks buffer (dead after S1)
        if (more) {
            size_t nbase = (size_t)(b * SEQ + skb[t + 1] * 64) * 512 + hh * 64;
#pragma unroll
            for (int j = 0; j < 4; j++) {
                int r = pr + j * 16;
                cpa16(sptr(&Ks[r * KP + pd4]), d_K + nbase + (size_t)r * 512 + pd4);
            }
            CP_COMMIT();
        }

        float corr[2][2], mnew[2][2];
#pragma unroll
        for (int mt = 0; mt < 2; mt++)
#pragma unroll
            for (int hf = 0; hf < 2; hf++) {
                int row = wm * 32 + mt * 16 + grp + hf * 8;
                float4 rmv = *(float4*)(&redm[row * 4]);
                float gmax = fmaxf(fmaxf(rmv.x, rmv.y), fmaxf(rmv.z, rmv.w));
                float mn = fmaxf(mst[mt][hf], gmax);
                mnew[mt][hf] = mn;
                corr[mt][hf] = ex2(mst[mt][hf] - mn);
            }

#pragma unroll
        for (int mt = 0; mt < 2; mt++)
#pragma unroll
            for (int hf = 0; hf < 2; hf++) {
                int rowl = wm * 32 + mt * 16 + grp + hf * 8;
                float mn = mnew[mt][hf];
                float rs = 0.f;
#pragma unroll
                for (int nt = 0; nt < 2; nt++) {
                    float p0 = ex2(s[mt][nt][2 * hf]     - mn);
                    float p1 = ex2(s[mt][nt][2 * hf + 1] - mn);
                    rs += p0 + p1;
                    int gb = wn * 16 + nt * 8;
                    ps[rowl * PP + gb + posA]     = ftf(p0);
                    ps[rowl * PP + gb + posA + 2] = ftf(p1);
                }
                rs += __shfl_xor_sync(0xffffffffu, rs, 1);
                rs += __shfl_xor_sync(0xffffffffu, rs, 2);
                if (t4 == 0) reds[rowl * 4 + wn] = rs;
            }

        // V(t) must have landed (oldest outstanding group)
        if (more) CP_WAIT1(); else CP_WAIT0();
        __syncthreads();   // S2: ps, reds, V(t) visible

#pragma unroll
        for (int mt = 0; mt < 2; mt++)
#pragma unroll
            for (int hf = 0; hf < 2; hf++) {
                int row = wm * 32 + mt * 16 + grp + hf * 8;
                float4 rsv = *(float4*)(&reds[row * 4]);
                float ls = rsv.x + rsv.y + rsv.z + rsv.w;
                float cr = corr[mt][hf];
                lst[mt][hf] = lst[mt][hf] * cr + ls;
                mst[mt][hf] = mnew[mt][hf];
#pragma unroll
                for (int nt = 0; nt < 2; nt++) {
                    o[mt][nt][2 * hf]     *= cr;
                    o[mt][nt][2 * hf + 1] *= cr;
                }
            }

        // ---- P*V ----
#pragma unroll
        for (int ks = 0; ks < 8; ks++) {
            int kk = ks * 8;
            uint32_t af[2][4], bf[2][2];
#pragma unroll
            for (int mt = 0; mt < 2; mt++) {
                int row = wm * 32 + mt * 16 + grp;
                float2 p0 = *(float2*)(&ps[row * PP + kk + 2 * t4]);
                float2 p1 = *(float2*)(&ps[(row + 8) * PP + kk + 2 * t4]);
                af[mt][0] = U(p0.x); af[mt][2] = U(p0.y);
                af[mt][1] = U(p1.x); af[mt][3] = U(p1.y);
            }
#pragma unroll
            for (int nt = 0; nt < 2; nt++) {
                int dcol = wn * 16 + nt * 8 + grp;
                bf[nt][0] = U(Vs[(kk + t4) * VP + dcol]);
                bf[nt][1] = U(Vs[(kk + t4 + 4) * VP + dcol]);
            }
#pragma unroll
            for (int mt = 0; mt < 2; mt++)
#pragma unroll
                for (int nt = 0; nt < 2; nt++)
                    mma_tf32(o[mt][nt], af[mt], bf[nt]);
        }

        // K(t+1) must have landed before next QK; barrier publishes it
        if (more) CP_WAIT0();
        __syncthreads();   // S3: Vs dead, K(t+1) visible

        if (more) {
            size_t nbase = (size_t)(b * SEQ + skb[t + 1] * 64) * 512 + hh * 64;
#pragma unroll
            for (int j = 0; j < 4; j++) {
                int r = pr + j * 16;
                cpa16(sptr(&Vs[r * VP + pd4]), d_V + nbase + (size_t)r * 512 + pd4);
            }
            CP_COMMIT();
        }
    }

#pragma unroll
    for (int mt = 0; mt < 2; mt++)
#pragma unroll
        for (int hf = 0; hf < 2; hf++) {
            int qp = qbase + wm * 32 + mt * 16 + grp + hf * 8;
            float inv = gv2[mt][hf] / lst[mt][hf];
#pragma unroll
            for (int nt = 0; nt < 2; nt++) {
                int dcol = wn * 16 + nt * 8 + 2 * t4;
                size_t ob = (size_t)(b * SEQ + qp) * 512 + hh * 64 + dcol;
                float2 cur = *(float2*)(d_O + ob);
                cur.x += o[mt][nt][2 * hf]     * inv;
                cur.y += o[mt][nt][2 * hf + 1] * inv;
                *(float2*)(d_O + ob) = cur;
            }
        }
}

// ---------------------------------------------------------------------------
extern "C" void kernel_launch(void* const* d_in, const int* in_sizes, int n_in,
                              void* d_out, int out_size)
{
    const float* x  = (const float*)d_in[0];
    const float* Wq = (const float*)d_in[1];
    const float* Wk = (const float*)d_in[2];
    const float* Wv = (const float*)d_in[3];
    const float* Wo = (const float*)d_in[4];
    const float* Wg = (const float*)d_in[5];
    float* y = (float*)d_out;

    cudaFuncSetAttribute(gemm512_tc,
                         cudaFuncAttributeMaxDynamicSharedMemorySize, 71680);
    cudaFuncSetAttribute(cmp_attn_mma,
                         cudaFuncAttributeMaxDynamicSharedMemorySize, 90368);
    // selwin dynamic smem: (64*(72+68+72+72) + 512) * 4 = 74752 B -> 3 CTAs/SM
    cudaFuncSetAttribute(selwin_fused,
                         cudaFuncAttributeMaxDynamicSharedMemorySize, 74752);

    gemm512_tc<<<dim3(4, 64, 3), 256, 71680>>>(x, Wq, Wk, Wv, nullptr, 0);
    gate_compress<<<1024 + 512, 256>>>(x, Wg);
    cmp_attn_mma<<<dim3(64, 8, 2), 256, 90368>>>();
    selwin_fused<<<dim3(64, 8, 2), 256, 74752>>>();
    gemm512_tc<<<dim3(4, 64, 1), 256, 71680>>>(nullptr, Wo, nullptr, nullptr, y, 3);
}

// round 17
// speedup vs baseline: 1.3547x; 1.1100x over previous
#include <cuda_runtime.h>
#include <cuda_fp16.h>
#include <math.h>
#include <stdint.h>

#define BATCH   2
#define SEQ     4096
#define DMODEL  512
#define NH      8
#define HD      64
#define NC      128
#define NS      64
#define TOPK    16
#define NROWS   (BATCH*SEQ)

// ---------------- scratch ----------------
__device__ float d_Q[NROWS*DMODEL];
__device__ float d_K[NROWS*DMODEL];
__device__ float d_V[NROWS*DMODEL];
__device__ float d_O[NROWS*DMODEL];
__device__ __half d_Kh[NROWS*DMODEL];
__device__ float d_KC[BATCH*NH*NC*HD];
__device__ float d_VC[BATCH*NH*NC*HD];
__device__ float d_G[NROWS*3];
__device__ int   d_SEL[BATCH*NH*NS*TOPK];

// ---------------- helpers ----------------
__device__ __forceinline__ float ftf(float x) {
    uint32_t u;
    asm("cvt.rna.tf32.f32 %0, %1;" : "=r"(u) : "f"(x));
    return __uint_as_float(u);
}
__device__ __forceinline__ float4 ftf4(float4 v) {
    return make_float4(ftf(v.x), ftf(v.y), ftf(v.z), ftf(v.w));
}
__device__ __forceinline__ float ex2(float x) {
    float r;
    asm("ex2.approx.ftz.f32 %0, %1;" : "=f"(r) : "f"(x));
    return r;
}
__device__ __forceinline__ void mma_tf32(float* c, const uint32_t* a, const uint32_t* b) {
    asm volatile(
        "mma.sync.aligned.m16n8k8.row.col.f32.tf32.tf32.f32 "
        "{%0,%1,%2,%3},{%4,%5,%6,%7},{%8,%9},{%0,%1,%2,%3};\n"
        : "+f"(c[0]), "+f"(c[1]), "+f"(c[2]), "+f"(c[3])
        : "r"(a[0]), "r"(a[1]), "r"(a[2]), "r"(a[3]), "r"(b[0]), "r"(b[1]));
}
__device__ __forceinline__ void mma_f16(float* c, const uint32_t* a, const uint32_t* b) {
    asm volatile(
        "mma.sync.aligned.m16n8k16.row.col.f32.f16.f16.f32 "
        "{%0,%1,%2,%3},{%4,%5,%6,%7},{%8,%9},{%0,%1,%2,%3};\n"
        : "+f"(c[0]), "+f"(c[1]), "+f"(c[2]), "+f"(c[3])
        : "r"(a[0]), "r"(a[1]), "r"(a[2]), "r"(a[3]), "r"(b[0]), "r"(b[1]));
}
__device__ __forceinline__ void split_tf32(float x, uint32_t& hi, uint32_t& lo) {
    float h = ftf(x);
    hi = __float_as_uint(h);
    lo = __float_as_uint(ftf(x - h));
}
__device__ __forceinline__ uint32_t sptr(const void* p) {
    return (uint32_t)__cvta_generic_to_shared(p);
}
__device__ __forceinline__ void cpa16(uint32_t dst, const void* src) {
    asm volatile("cp.async.cg.shared.global [%0], [%1], 16;" :: "r"(dst), "l"(src));
}
#define CP_COMMIT() asm volatile("cp.async.commit_group;")
#define CP_WAIT0()  asm volatile("cp.async.wait_group 0;" ::: "memory")
#define CP_WAIT1()  asm volatile("cp.async.wait_group 1;" ::: "memory")
#define U(x) __float_as_uint(x)
#define QSCALE 0.18033688011112042f   /* 0.125 * log2(e) */

// ---------------- tf32 GEMM: 128x128 tile, k-slab 32, smem double buffer --
// mode 1 (K) additionally emits d_Kh (half) for the fp16 QK in selwin.
#define GPA 36
#define GPB 136
__global__ __launch_bounds__(256) void gemm512_tc(const float* __restrict__ Aext,
    const float* __restrict__ B0, const float* __restrict__ B1,
    const float* __restrict__ B2, float* __restrict__ Cext, int modeBase)
{
    extern __shared__ float smg[];
    float* As = smg;
    float* Bs = smg + 2 * 128 * GPA;

    int mode = modeBase + blockIdx.z;
    const float* A  = (mode == 3) ? d_O : Aext;
    const float* Bm = (mode == 1) ? B1 : (mode == 2) ? B2 : B0;
    float* C = (mode == 0) ? d_Q : (mode == 1) ? d_K : (mode == 2) ? d_V : Cext;

    int tid = threadIdx.x, lane = tid & 31, w = tid >> 5;
    int grp = lane >> 2, t4 = lane & 3;
    int wm = w & 3, wn = w >> 2;
    int m0 = blockIdx.y * 128, n0 = blockIdx.x * 128;

    int arr[4], arc[4], brr[4], brc[4];
#pragma unroll
    for (int ii = 0; ii < 4; ii++) {
        int i = tid + ii * 256;
        arr[ii] = i >> 3;  arc[ii] = (i & 7) * 4;
        brr[ii] = i >> 5;  brc[ii] = (i & 31) * 4;
    }

    float acc[2][8][4];
#pragma unroll
    for (int mt = 0; mt < 2; mt++)
#pragma unroll
        for (int nt = 0; nt < 8; nt++)
#pragma unroll
            for (int r = 0; r < 4; r++) acc[mt][nt][r] = 0.f;

    float4 areg[4], breg[4];
#pragma unroll
    for (int ii = 0; ii < 4; ii++) {
        areg[ii] = *(const float4*)(A + (size_t)(m0 + arr[ii]) * 512 + arc[ii]);
        breg[ii] = *(const float4*)(Bm + (size_t)brr[ii] * 512 + n0 + brc[ii]);
    }
#pragma unroll
    for (int ii = 0; ii < 4; ii++) {
        *(float4*)(&As[arr[ii] * GPA + arc[ii]]) = ftf4(areg[ii]);
        *(float4*)(&Bs[brr[ii] * GPB + brc[ii]]) = ftf4(breg[ii]);
    }
    __syncthreads();

    for (int s = 0; s < 16; s++) {
        float* Ab = As + (s & 1) * 128 * GPA;
        float* Bb = Bs + (s & 1) * 32 * GPB;
        if (s < 15) {
            int k0 = (s + 1) * 32;
#pragma unroll
            for (int ii = 0; ii < 4; ii++) {
                areg[ii] = *(const float4*)(A + (size_t)(m0 + arr[ii]) * 512 + k0 + arc[ii]);
                breg[ii] = *(const float4*)(Bm + (size_t)(k0 + brr[ii]) * 512 + n0 + brc[ii]);
            }
        }
#pragma unroll
        for (int ks = 0; ks < 4; ks++) {
            int kb = ks * 8;
            uint32_t af[2][4], bf[8][2];
#pragma unroll
            for (int mt = 0; mt < 2; mt++) {
                int row = wm * 32 + mt * 16 + grp;
                af[mt][0] = U(Ab[row * GPA + kb + t4]);
                af[mt][1] = U(Ab[(row + 8) * GPA + kb + t4]);
                af[mt][2] = U(Ab[row * GPA + kb + t4 + 4]);
                af[mt][3] = U(Ab[(row + 8) * GPA + kb + t4 + 4]);
            }
#pragma unroll
            for (int nt = 0; nt < 8; nt++) {
                int col = wn * 64 + nt * 8 + grp;
                bf[nt][0] = U(Bb[(kb + t4) * GPB + col]);
                bf[nt][1] = U(Bb[(kb + t4 + 4) * GPB + col]);
            }
#pragma unroll
            for (int mt = 0; mt < 2; mt++)
#pragma unroll
                for (int nt = 0; nt < 8; nt++)
                    mma_tf32(acc[mt][nt], af[mt], bf[nt]);
        }
        if (s < 15) {
            float* An = As + ((s + 1) & 1) * 128 * GPA;
            float* Bn = Bs + ((s + 1) & 1) * 32 * GPB;
#pragma unroll
            for (int ii = 0; ii < 4; ii++) {
                *(float4*)(&An[arr[ii] * GPA + arc[ii]]) = ftf4(areg[ii]);
                *(float4*)(&Bn[brr[ii] * GPB + brc[ii]]) = ftf4(breg[ii]);
            }
        }
        __syncthreads();
    }
#pragma unroll
    for (int mt = 0; mt < 2; mt++)
#pragma unroll
        for (int nt = 0; nt < 8; nt++) {
            int row = m0 + wm * 32 + mt * 16 + grp;
            int col = n0 + wn * 64 + nt * 8 + 2 * t4;
            *(float2*)(C + (size_t)row * 512 + col) =
                make_float2(acc[mt][nt][0], acc[mt][nt][1]);
            *(float2*)(C + (size_t)(row + 8) * 512 + col) =
                make_float2(acc[mt][nt][2], acc[mt][nt][3]);
        }
    if (mode == 1) {
#pragma unroll
        for (int mt = 0; mt < 2; mt++)
#pragma unroll
            for (int nt = 0; nt < 8; nt++) {
                int row = m0 + wm * 32 + mt * 16 + grp;
                int col = n0 + wn * 64 + nt * 8 + 2 * t4;
                *(__half2*)(&d_Kh[(size_t)row * 512 + col]) =
                    __floats2half2_rn(acc[mt][nt][0], acc[mt][nt][1]);
                *(__half2*)(&d_Kh[(size_t)(row + 8) * 512 + col]) =
                    __floats2half2_rn(acc[mt][nt][2], acc[mt][nt][3]);
            }
    }
}

// ---------------- fused gate + compress (one launch) ----------------
__global__ __launch_bounds__(256) void gate_compress(const float* __restrict__ x,
                                                     const float* __restrict__ Wg)
{
    int blk = blockIdx.x;
    if (blk < 1024) {
        int w = threadIdx.x >> 5, lane = threadIdx.x & 31;
        int row = blk * 8 + w;
        float p0 = 0, p1 = 0, p2 = 0;
#pragma unroll
        for (int c = 0; c < 4; c++) {
            int d = c * 128 + lane * 4;
            float4 xv = *(const float4*)(x + (size_t)row * 512 + d);
            p0 += xv.x * Wg[d * 3]     + xv.y * Wg[d * 3 + 3] +
                  xv.z * Wg[d * 3 + 6] + xv.w * Wg[d * 3 + 9];
            p1 += xv.x * Wg[d * 3 + 1] + xv.y * Wg[d * 3 + 4] +
                  xv.z * Wg[d * 3 + 7] + xv.w * Wg[d * 3 + 10];
            p2 += xv.x * Wg[d * 3 + 2] + xv.y * Wg[d * 3 + 5] +
                  xv.z * Wg[d * 3 + 8] + xv.w * Wg[d * 3 + 11];
        }
#pragma unroll
        for (int o = 16; o; o >>= 1) {
            p0 += __shfl_xor_sync(0xffffffffu, p0, o);
            p1 += __shfl_xor_sync(0xffffffffu, p1, o);
            p2 += __shfl_xor_sync(0xffffffffu, p2, o);
        }
        if (lane == 0) {
            d_G[row * 3 + 0] = 1.f / (1.f + expf(-p0));
            d_G[row * 3 + 1] = 1.f / (1.f + expf(-p1));
            d_G[row * 3 + 2] = 1.f / (1.f + expf(-p2));
        }
    } else {
        int idx = (blk - 1024) * 256 + threadIdx.x;
        int d = idx & 63, n = (idx >> 6) & 127, h = (idx >> 13) & 7, b = idx >> 16;
        const float* kp = d_K + (size_t)(b * SEQ + n * 32) * 512 + h * 64 + d;
        const float* vp = d_V + (size_t)(b * SEQ + n * 32) * 512 + h * 64 + d;
        float ks = 0, vs = 0;
#pragma unroll
        for (int r = 0; r < 32; r++) { ks += kp[r * 512]; vs += vp[r * 512]; }
        d_KC[idx] = ks * (1.f / 32.f);
        d_VC[idx] = vs * (1.f / 32.f);
    }
}

// ---------------- compressed attention + top-k (3xTF32 QK, unchanged) -----
#define CQ 68
#define CK 72
#define CS 132
__global__ __launch_bounds__(256) void cmp_attn_mma()
{
    extern __shared__ float sm[];
    float* qs   = sm;
    float* kv   = qs + 64 * CQ;
    float* ps   = kv + 128 * CK;
    float* redm = ps + 64 * CS;
    float* reds = redm + 256;
    float* impb = reds + 256;

    int g = blockIdx.x, h = blockIdx.y, b = blockIdx.z;
    int tid = threadIdx.x, lane = tid & 31, w = tid >> 5;
    int grp = lane >> 2, t4 = lane & 3;
    int wm = w & 1, wn = w >> 1;
    int qbase = g * 64;

    for (int i = tid; i < 1024; i += 256) {
        int r = i >> 4, d4 = (i & 15) * 4;
        float4 v = *(const float4*)(d_Q + (size_t)(b * SEQ + qbase + r) * 512 + h * 64 + d4);
        *(float4*)(&qs[r * CQ + d4]) = v;
    }
    int cbase = ((b * NH + h) * NC) * HD;
    for (int i = tid; i < 2048; i += 256) {
        int r = i >> 4, d4 = (i & 15) * 4;
        float4 v = *(const float4*)(d_KC + cbase + r * 64 + d4);
        *(float4*)(&kv[r * CK + d4]) = v;
    }
    __syncthreads();

    float s[2][4][4];
#pragma unroll
    for (int mt = 0; mt < 2; mt++)
#pragma unroll
        for (int nt = 0; nt < 4; nt++)
#pragma unroll
            for (int r = 0; r < 4; r++) s[mt][nt][r] = 0.f;
#pragma unroll
    for (int ks = 0; ks < 8; ks++) {
        int kk = ks * 8;
        uint32_t ah[2][4], al[2][4], bh[4][2], bl[4][2];
#pragma unroll
        for (int mt = 0; mt < 2; mt++) {
            int row = wm * 32 + mt * 16 + grp;
            split_tf32(qs[row * CQ + kk + t4],           ah[mt][0], al[mt][0]);
            split_tf32(qs[(row + 8) * CQ + kk + t4],     ah[mt][1], al[mt][1]);
            split_tf32(qs[row * CQ + kk + t4 + 4],       ah[mt][2], al[mt][2]);
            split_tf32(qs[(row + 8) * CQ + kk + t4 + 4], ah[mt][3], al[mt][3]);
        }
#pragma unroll
        for (int nt = 0; nt < 4; nt++) {
            int key = wn * 32 + nt * 8 + grp;
            split_tf32(kv[key * CK + kk + t4],     bh[nt][0], bl[nt][0]);
            split_tf32(kv[key * CK + kk + t4 + 4], bh[nt][1], bl[nt][1]);
        }
#pragma unroll
        for (int mt = 0; mt < 2; mt++)
#pragma unroll
            for (int nt = 0; nt < 4; nt++) {
                mma_tf32(s[mt][nt], ah[mt], bl[nt]);
                mma_tf32(s[mt][nt], al[mt], bh[nt]);
                mma_tf32(s[mt][nt], ah[mt], bh[nt]);
            }
    }

    int nval[2][2];
#pragma unroll
    for (int mt = 0; mt < 2; mt++)
#pragma unroll
        for (int hf = 0; hf < 2; hf++) {
            int pos = qbase + wm * 32 + mt * 16 + grp + hf * 8;
            nval[mt][hf] = (pos >= 31) ? ((pos - 31) >> 5) + 1 : 0;
        }
#pragma unroll
    for (int mt = 0; mt < 2; mt++)
#pragma unroll
        for (int nt = 0; nt < 4; nt++)
#pragma unroll
            for (int r = 0; r < 4; r++) {
                int c = wn * 32 + nt * 8 + 2 * t4 + (r & 1);
                bool valid = c < nval[mt][r >> 1];
                s[mt][nt][r] = valid ? s[mt][nt][r] * 0.125f : -1e30f;
            }

#pragma unroll
    for (int mt = 0; mt < 2; mt++)
#pragma unroll
        for (int hf = 0; hf < 2; hf++) {
            float rm = -1e30f;
#pragma unroll
            for (int nt = 0; nt < 4; nt++)
                rm = fmaxf(rm, fmaxf(s[mt][nt][2 * hf], s[mt][nt][2 * hf + 1]));
            rm = fmaxf(rm, __shfl_xor_sync(0xffffffffu, rm, 1));
            rm = fmaxf(rm, __shfl_xor_sync(0xffffffffu, rm, 2));
            if (t4 == 0)
                redm[(wm * 32 + mt * 16 + grp + hf * 8) * 4 + wn] = rm;
        }
    __syncthreads();

    for (int i = tid; i < 2048; i += 256) {
        int r = i >> 4, d4 = (i & 15) * 4;
        float4 v = *(const float4*)(d_VC + cbase + r * 64 + d4);
        *(float4*)(&kv[r * CK + d4]) = v;
    }
#pragma unroll
    for (int mt = 0; mt < 2; mt++)
#pragma unroll
        for (int hf = 0; hf < 2; hf++) {
            int row = wm * 32 + mt * 16 + grp + hf * 8;
            float4 rmv = *(float4*)(&redm[row * 4]);
            float gmax = fmaxf(fmaxf(rmv.x, rmv.y), fmaxf(rmv.z, rmv.w));
            float rs = 0.f;
#pragma unroll
            for (int nt = 0; nt < 4; nt++) {
                float e0 = __expf(s[mt][nt][2 * hf]     - gmax);
                float e1 = __expf(s[mt][nt][2 * hf + 1] - gmax);
                s[mt][nt][2 * hf] = e0;
                s[mt][nt][2 * hf + 1] = e1;
                rs += e0 + e1;
            }
            rs += __shfl_xor_sync(0xffffffffu, rs, 1);
            rs += __shfl_xor_sync(0xffffffffu, rs, 2);
            if (t4 == 0) reds[row * 4 + wn] = rs;
        }
    __syncthreads();

#pragma unroll
    for (int mt = 0; mt < 2; mt++)
#pragma unroll
        for (int hf = 0; hf < 2; hf++) {
            int row = wm * 32 + mt * 16 + grp + hf * 8;
            float4 rsv = *(float4*)(&reds[row * 4]);
            float tot = rsv.x + rsv.y + rsv.z + rsv.w;
            float inv = (nval[mt][hf] > 0) ? 1.f / tot : 0.f;
#pragma unroll
            for (int nt = 0; nt < 4; nt++) {
                int col = wn * 32 + nt * 8 + 2 * t4;
                ps[row * CS + col]     = s[mt][nt][2 * hf]     * inv;
                ps[row * CS + col + 1] = s[mt][nt][2 * hf + 1] * inv;
            }
        }
    __syncthreads();

    float o[2][2][4];
#pragma unroll
    for (int mt = 0; mt < 2; mt++)
#pragma unroll
        for (int nt = 0; nt < 2; nt++)
#pragma unroll
            for (int r = 0; r < 4; r++) o[mt][nt][r] = 0.f;
#pragma unroll
    for (int ks = 0; ks < 16; ks++) {
        int kk = ks * 8;
        uint32_t af[2][4], bf[2][2];
#pragma unroll
        for (int mt = 0; mt < 2; mt++) {
            int row = wm * 32 + mt * 16 + grp;
            af[mt][0] = U(ftf(ps[row * CS + kk + t4]));
            af[mt][1] = U(ftf(ps[(row + 8) * CS + kk + t4]));
            af[mt][2] = U(ftf(ps[row * CS + kk + t4 + 4]));
            af[mt][3] = U(ftf(ps[(row + 8) * CS + kk + t4 + 4]));
        }
#pragma unroll
        for (int nt = 0; nt < 2; nt++) {
            int dcol = wn * 16 + nt * 8 + grp;
            bf[nt][0] = U(ftf(kv[(kk + t4) * CK + dcol]));
            bf[nt][1] = U(ftf(kv[(kk + t4 + 4) * CK + dcol]));
        }
#pragma unroll
        for (int mt = 0; mt < 2; mt++)
#pragma unroll
            for (int nt = 0; nt < 2; nt++)
                mma_tf32(o[mt][nt], af[mt], bf[nt]);
    }

#pragma unroll
    for (int mt = 0; mt < 2; mt++)
#pragma unroll
        for (int hf = 0; hf < 2; hf++) {
            int qp = qbase + wm * 32 + mt * 16 + grp + hf * 8;
            float g0 = d_G[(b * SEQ + qp) * 3 + 0];
#pragma unroll
            for (int nt = 0; nt < 2; nt++) {
                int dcol = wn * 16 + nt * 8 + 2 * t4;
                size_t ob = (size_t)(b * SEQ + qp) * 512 + h * 64 + dcol;
                *(float2*)(d_O + ob) = make_float2(o[mt][nt][2 * hf] * g0,
                                                   o[mt][nt][2 * hf + 1] * g0);
            }
        }
    __syncthreads();

    if (tid < 64) {
        float v = 0.f;
        for (int q = 0; q < 64; q++)
            v += ps[q * CS + 2 * tid] + ps[q * CS + 2 * tid + 1];
        impb[tid] = v;
    }
    __syncthreads();
    if (w == 0) {
        int j0 = lane, j1 = lane + 32;
        float v0 = (j0 <= g) ? impb[j0] + (j0 == g ? 1e9f : 0.f) : -1e30f;
        float v1 = (j1 <= g) ? impb[j1] + (j1 == g ? 1e9f : 0.f) : -1e30f;
        int selbase = ((b * NH + h) * NS + g) * TOPK;
        for (int r = 0; r < TOPK; r++) {
            float bv; int bi;
            if (v0 >= v1) { bv = v0; bi = j0; } else { bv = v1; bi = j1; }
#pragma unroll
            for (int o2 = 16; o2; o2 >>= 1) {
                float ov = __shfl_xor_sync(0xffffffffu, bv, o2);
                int   oi = __shfl_xor_sync(0xffffffffu, bi, o2);
                if (ov > bv || (ov == bv && oi < bi)) { bv = ov; bi = oi; }
            }
            if (lane == 0) d_SEL[selbase + r] = bi;
            if (bi == j0) v0 = -3e30f;
            if (bi == j1) v1 = -3e30f;
        }
    }
}

// ---------------- fused sel+win flash attention -----------------------------
// QK in fp16 m16n8k16 (Q half in smem, K half via cp.async from d_Kh):
// halves QK mma count and fragment LDS. PV stays tf32. smem 57.3KB.
#define QPH 72   // halfs
#define KPH 72   // halfs
#define VP 72
#define PP 72
__global__ void __launch_bounds__(256) selwin_fused()
{
    extern __shared__ float sm[];
    __half* qs_h = (__half*)sm;                    // 64*72 halfs (2304 f)
    __half* Ks_h = (__half*)(sm + 2304);           // 64*72 halfs (2304 f)
    float*  Vs   = sm + 4608;                      // 64*72 f
    float*  ps   = Vs + 64 * VP;                   // 64*72 f
    float*  redm = ps + 64 * PP;                   // 256
    float*  reds = redm + 256;                     // 256

    __shared__ int skb[26];
    __shared__ int sphase[2];

    int g = blockIdx.x, hh = blockIdx.y, b = blockIdx.z;
    int tid = threadIdx.x, lane = tid & 31, w = tid >> 5;
    int grp = lane >> 2, t4 = lane & 3;
    int wm = w & 1, wn = w >> 1;
    int qbase = g * 64;

    if (tid == 0) {
        int selbase = ((b * NH + hh) * NS + g) * TOPK;
        int n = 0;
#pragma unroll
        for (int it = 0; it < TOPK; it++) {
            int kb = d_SEL[selbase + it];
            if (kb <= g) skb[n++] = kb;
        }
        sphase[0] = n;
        int st = (g > 8) ? g - 8 : 0;
        for (int kb = st; kb <= g; kb++) skb[n++] = kb;
        sphase[1] = n;
    }

    // Q load: scale + convert to half, natural layout
#pragma unroll
    for (int ii = 0; ii < 2; ii++) {
        int i = tid + ii * 256;
        int r = i >> 3, g8 = (i & 7) * 8;
        const float* src = d_Q + (size_t)(b * SEQ + qbase + r) * 512 + hh * 64 + g8;
        float4 lo = *(const float4*)src;
        float4 hi = *(const float4*)(src + 4);
        __half2 h0 = __floats2half2_rn(lo.x * QSCALE, lo.y * QSCALE);
        __half2 h1 = __floats2half2_rn(lo.z * QSCALE, lo.w * QSCALE);
        __half2 h2 = __floats2half2_rn(hi.x * QSCALE, hi.y * QSCALE);
        __half2 h3 = __floats2half2_rn(hi.z * QSCALE, hi.w * QSCALE);
        __half2* dst = (__half2*)(&qs_h[r * QPH + g8]);
        dst[0] = h0; dst[1] = h1; dst[2] = h2; dst[3] = h3;
    }
    __syncthreads();                  // skb/sphase + qs visible

    int nsel = sphase[0], ntot = sphase[1];
    int pr = tid >> 4, pd4 = (tid & 15) * 4;   // V copy indices
    int kr = tid >> 2, ko8 = (tid & 3) * 16;   // K copy: 64 rows x 4 chunks(16B=8h)... (use below)

    // prologue: cp.async K0 (half) + V0 (fp32)
    {
        size_t kb64 = (size_t)(b * SEQ + skb[0] * 64) * 512 + hh * 64;
        // K half: 64 rows x 128B = 512 chunks of 16B -> 2 per thread
#pragma unroll
        for (int c = 0; c < 2; c++) {
            int ch = tid + c * 256;
            int r = ch >> 3, o8 = (ch & 7) * 8;
            cpa16(sptr(&Ks_h[r * KPH + o8]), d_Kh + kb64 + (size_t)r * 512 + o8);
        }
#pragma unroll
        for (int j = 0; j < 4; j++) {
            int r = pr + j * 16;
            cpa16(sptr(&Vs[r * VP + pd4]), d_V + kb64 + (size_t)r * 512 + pd4);
        }
        CP_COMMIT();
        CP_WAIT0();
    }
    __syncthreads();

    float gv1[2][2], gv2[2][2];
#pragma unroll
    for (int mt = 0; mt < 2; mt++)
#pragma unroll
        for (int hf = 0; hf < 2; hf++) {
            int qp = qbase + wm * 32 + mt * 16 + grp + hf * 8;
            gv1[mt][hf] = d_G[(b * SEQ + qp) * 3 + 1];
            gv2[mt][hf] = d_G[(b * SEQ + qp) * 3 + 2];
        }

    float o[2][2][4];
#pragma unroll
    for (int mt = 0; mt < 2; mt++)
#pragma unroll
        for (int nt = 0; nt < 2; nt++)
#pragma unroll
            for (int r = 0; r < 4; r++) o[mt][nt][r] = 0.f;
    float mst[2][2], lst[2][2];
#pragma unroll
    for (int mt = 0; mt < 2; mt++)
#pragma unroll
        for (int hf = 0; hf < 2; hf++) { mst[mt][hf] = -1e30f; lst[mt][hf] = 0.f; }

    int posA = ((t4 & 1) << 2) + (t4 >> 1);
    (void)kr; (void)ko8;

    for (int t = 0; t < ntot; t++) {
        if (t == nsel) {
#pragma unroll
            for (int mt = 0; mt < 2; mt++)
#pragma unroll
                for (int hf = 0; hf < 2; hf++) {
                    int qp = qbase + wm * 32 + mt * 16 + grp + hf * 8;
                    float inv = gv1[mt][hf] / lst[mt][hf];
#pragma unroll
                    for (int nt = 0; nt < 2; nt++) {
                        int dcol = wn * 16 + nt * 8 + 2 * t4;
                        size_t ob = (size_t)(b * SEQ + qp) * 512 + hh * 64 + dcol;
                        float2 cur = *(float2*)(d_O + ob);
                        cur.x += o[mt][nt][2 * hf]     * inv;
                        cur.y += o[mt][nt][2 * hf + 1] * inv;
                        *(float2*)(d_O + ob) = cur;
                        o[mt][nt][2 * hf] = 0.f; o[mt][nt][2 * hf + 1] = 0.f;
                    }
                    mst[mt][hf] = -1e30f; lst[mt][hf] = 0.f;
                }
        }
        int kb = skb[t];
        bool winph = (t >= nsel);
        bool more = (t + 1 < ntot);

        // ---- QK^T via fp16 m16n8k16: 4 ksteps x 4 mma ----
        float s[2][2][4];
#pragma unroll
        for (int mt = 0; mt < 2; mt++)
#pragma unroll
            for (int nt = 0; nt < 2; nt++)
#pragma unroll
                for (int r = 0; r < 4; r++) s[mt][nt][r] = 0.f;
#pragma unroll
        for (int ks = 0; ks < 4; ks++) {
            int kk = ks * 16;
            uint32_t af[2][4], bf[2][2];
#pragma unroll
            for (int mt = 0; mt < 2; mt++) {
                int row = wm * 32 + mt * 16 + grp;
                af[mt][0] = *(uint32_t*)(&qs_h[row * QPH + kk + 2 * t4]);
                af[mt][1] = *(uint32_t*)(&qs_h[(row + 8) * QPH + kk + 2 * t4]);
                af[mt][2] = *(uint32_t*)(&qs_h[row * QPH + kk + 2 * t4 + 8]);
                af[mt][3] = *(uint32_t*)(&qs_h[(row + 8) * QPH + kk + 2 * t4 + 8]);
            }
#pragma unroll
            for (int nt = 0; nt < 2; nt++) {
                int key = wn * 16 + nt * 8 + grp;
                bf[nt][0] = *(uint32_t*)(&Ks_h[key * KPH + kk + 2 * t4]);
                bf[nt][1] = *(uint32_t*)(&Ks_h[key * KPH + kk + 2 * t4 + 8]);
            }
#pragma unroll
            for (int mt = 0; mt < 2; mt++)
#pragma unroll
                for (int nt = 0; nt < 2; nt++)
                    mma_f16(s[mt][nt], af[mt], bf[nt]);
        }

        bool needmask = (kb >= g) || (winph && kb < g - 7);
        if (needmask) {
#pragma unroll
            for (int mt = 0; mt < 2; mt++)
#pragma unroll
                for (int nt = 0; nt < 2; nt++)
#pragma unroll
                    for (int r = 0; r < 4; r++) {
                        int qp = qbase + wm * 32 + mt * 16 + grp + (r >> 1) * 8;
                        int kp = kb * 64 + wn * 16 + nt * 8 + 2 * t4 + (r & 1);
                        bool valid = (kp <= qp) && (!winph || (kp + 512 > qp));
                        s[mt][nt][r] = valid ? s[mt][nt][r] : -1e30f;
                    }
        }

#pragma unroll
        for (int mt = 0; mt < 2; mt++)
#pragma unroll
            for (int hf = 0; hf < 2; hf++) {
                float rm = fmaxf(fmaxf(s[mt][0][2 * hf], s[mt][0][2 * hf + 1]),
                                 fmaxf(s[mt][1][2 * hf], s[mt][1][2 * hf + 1]));
                rm = fmaxf(rm, __shfl_xor_sync(0xffffffffu, rm, 1));
                rm = fmaxf(rm, __shfl_xor_sync(0xffffffffu, rm, 2));
                if (t4 == 0)
                    redm[(wm * 32 + mt * 16 + grp + hf * 8) * 4 + wn] = rm;
            }
        __syncthreads();   // S1: redm visible, Ks fully consumed

        // stream K(t+1) into Ks (dead after S1)
        if (more) {
            size_t nb64 = (size_t)(b * SEQ + skb[t + 1] * 64) * 512 + hh * 64;
#pragma unroll
            for (int c = 0; c < 2; c++) {
                int ch = tid + c * 256;
                int r = ch >> 3, o8 = (ch & 7) * 8;
                cpa16(sptr(&Ks_h[r * KPH + o8]), d_Kh + nb64 + (size_t)r * 512 + o8);
            }
            CP_COMMIT();
        }

        float corr[2][2], mnew[2][2];
#pragma unroll
        for (int mt = 0; mt < 2; mt++)
#pragma unroll
            for (int hf = 0; hf < 2; hf++) {
                int row = wm * 32 + mt * 16 + grp + hf * 8;
                float4 rmv = *(float4*)(&redm[row * 4]);
                float gmax = fmaxf(fmaxf(rmv.x, rmv.y), fmaxf(rmv.z, rmv.w));
                float mn = fmaxf(mst[mt][hf], gmax);
                mnew[mt][hf] = mn;
                corr[mt][hf] = ex2(mst[mt][hf] - mn);
            }

#pragma unroll
        for (int mt = 0; mt < 2; mt++)
#pragma unroll
            for (int hf = 0; hf < 2; hf++) {
                int rowl = wm * 32 + mt * 16 + grp + hf * 8;
                float mn = mnew[mt][hf];
                float rs = 0.f;
#pragma unroll
                for (int nt = 0; nt < 2; nt++) {
                    float p0 = ex2(s[mt][nt][2 * hf]     - mn);
                    float p1 = ex2(s[mt][nt][2 * hf + 1] - mn);
                    rs += p0 + p1;
                    int gb = wn * 16 + nt * 8;
                    ps[rowl * PP + gb + posA]     = ftf(p0);
                    ps[rowl * PP + gb + posA + 2] = ftf(p1);
                }
                rs += __shfl_xor_sync(0xffffffffu, rs, 1);
                rs += __shfl_xor_sync(0xffffffffu, rs, 2);
                if (t4 == 0) reds[rowl * 4 + wn] = rs;
            }

        // V(t) must have landed (oldest outstanding group)
        if (more) CP_WAIT1(); else CP_WAIT0();
        __syncthreads();   // S2: ps, reds, V(t) visible

#pragma unroll
        for (int mt = 0; mt < 2; mt++)
#pragma unroll
            for (int hf = 0; hf < 2; hf++) {
                int row = wm * 32 + mt * 16 + grp + hf * 8;
                float4 rsv = *(float4*)(&reds[row * 4]);
                float ls = rsv.x + rsv.y + rsv.z + rsv.w;
                float cr = corr[mt][hf];
                lst[mt][hf] = lst[mt][hf] * cr + ls;
                mst[mt][hf] = mnew[mt][hf];
#pragma unroll
                for (int nt = 0; nt < 2; nt++) {
                    o[mt][nt][2 * hf]     *= cr;
                    o[mt][nt][2 * hf + 1] *= cr;
                }
            }

        // ---- P*V (tf32) ----
#pragma unroll
        for (int ks = 0; ks < 8; ks++) {
            int kk = ks * 8;
            uint32_t af[2][4], bf[2][2];
#pragma unroll
            for (int mt = 0; mt < 2; mt++) {
                int row = wm * 32 + mt * 16 + grp;
                float2 p0 = *(float2*)(&ps[row * PP + kk + 2 * t4]);
                float2 p1 = *(float2*)(&ps[(row + 8) * PP + kk + 2 * t4]);
                af[mt][0] = U(p0.x); af[mt][2] = U(p0.y);
                af[mt][1] = U(p1.x); af[mt][3] = U(p1.y);
            }
#pragma unroll
            for (int nt = 0; nt < 2; nt++) {
                int dcol = wn * 16 + nt * 8 + grp;
                bf[nt][0] = U(Vs[(kk + t4) * VP + dcol]);
                bf[nt][1] = U(Vs[(kk + t4 + 4) * VP + dcol]);
            }
#pragma unroll
            for (int mt = 0; mt < 2; mt++)
#pragma unroll
                for (int nt = 0; nt < 2; nt++)
                    mma_tf32(o[mt][nt], af[mt], bf[nt]);
        }

        // K(t+1) landed before barrier publishes buffers
        if (more) CP_WAIT0();
        __syncthreads();   // S3: Vs dead, K(t+1) visible

        if (more) {
            size_t nb64 = (size_t)(b * SEQ + skb[t + 1] * 64) * 512 + hh * 64;
#pragma unroll
            for (int j = 0; j < 4; j++) {
                int r = pr + j * 16;
                cpa16(sptr(&Vs[r * VP + pd4]), d_V + nb64 + (size_t)r * 512 + pd4);
            }
            CP_COMMIT();
        }
    }

#pragma unroll
    for (int mt = 0; mt < 2; mt++)
#pragma unroll
        for (int hf = 0; hf < 2; hf++) {
            int qp = qbase + wm * 32 + mt * 16 + grp + hf * 8;
            float inv = gv2[mt][hf] / lst[mt][hf];
#pragma unroll
            for (int nt = 0; nt < 2; nt++) {
                int dcol = wn * 16 + nt * 8 + 2 * t4;
                size_t ob = (size_t)(b * SEQ + qp) * 512 + hh * 64 + dcol;
                float2 cur = *(float2*)(d_O + ob);
                cur.x += o[mt][nt][2 * hf]     * inv;
                cur.y += o[mt][nt][2 * hf + 1] * inv;
                *(float2*)(d_O + ob) = cur;
            }
        }
}

// ---------------------------------------------------------------------------
extern "C" void kernel_launch(void* const* d_in, const int* in_sizes, int n_in,
                              void* d_out, int out_size)
{
    const float* x  = (const float*)d_in[0];
    const float* Wq = (const float*)d_in[1];
    const float* Wk = (const float*)d_in[2];
    const float* Wv = (const float*)d_in[3];
    const float* Wo = (const float*)d_in[4];
    const float* Wg = (const float*)d_in[5];
    float* y = (float*)d_out;

    cudaFuncSetAttribute(gemm512_tc,
                         cudaFuncAttributeMaxDynamicSharedMemorySize, 71680);
    cudaFuncSetAttribute(cmp_attn_mma,
                         cudaFuncAttributeMaxDynamicSharedMemorySize, 90368);
    // selwin dynamic smem: (2304+2304+4608+4608+512) floats = 14336 f = 57344 B
    cudaFuncSetAttribute(selwin_fused,
                         cudaFuncAttributeMaxDynamicSharedMemorySize, 57344);

    gemm512_tc<<<dim3(4, 64, 3), 256, 71680>>>(x, Wq, Wk, Wv, nullptr, 0);
    gate_compress<<<1024 + 512, 256>>>(x, Wg);
    cmp_attn_mma<<<dim3(64, 8, 2), 256, 90368>>>();
    selwin_fused<<<dim3(64, 8, 2), 256, 57344>>>();
    gemm512_tc<<<dim3(4, 64, 1), 256, 71680>>>(nullptr, Wo, nullptr, nullptr, y, 3);
}